// round 10
// baseline (speedup 1.0000x reference)
#include <cuda_runtime.h>
#include <cuda_fp16.h>
#include <math.h>
#include <stdint.h>

// Problem constants
#define B_   2
#define S_   2048
#define HID_ 2048
#define H_   16
#define KV_  8
#define D_   128
#define MTOK (B_*S_)   // 4096 tokens
#define NQKV 4096

// ---------------- scratch (device globals) ----------------------------------
__device__ float g_qkv[MTOK * NQKV];   // fused QKV projection output

__device__ __half g_hid_h[MTOK*HID_], g_hid_l[MTOK*HID_];  // hidden fp16 hi/lo
__device__ __half g_w16 [NQKV*HID_];                        // q|k|v weights fp16
__device__ __half g_ow16[HID_*H_*D_];                       // o_w fp16

// roped/normed operands for flash (fp16), [B,H|KV,S,D]
__device__ __half g_qh[B_*H_*S_*D_], g_ql[B_*H_*S_*D_];
__device__ __half g_k16[B_*KV_*S_*D_];
__device__ __half g_v16[B_*KV_*S_*D_];
// attention output (fp16 hi/lo), [B*S, H*D]
__device__ __half g_at_h[MTOK*H_*D_], g_at_l[MTOK*H_*D_];

// ======================= PTX helpers (sm_80-era) ===========================
__device__ __forceinline__ uint32_t smem_u32(const void* p) {
    return (uint32_t)__cvta_generic_to_shared(p);
}
__device__ __forceinline__ void cpasync16(uint32_t dst, const void* src) {
    asm volatile("cp.async.cg.shared.global [%0], [%1], 16;" :: "r"(dst), "l"(src));
}
#define CP_COMMIT() asm volatile("cp.async.commit_group;" ::: "memory")
#define CP_WAIT1()  asm volatile("cp.async.wait_group 1;" ::: "memory")
#define CP_WAIT0()  asm volatile("cp.async.wait_group 0;" ::: "memory")

__device__ __forceinline__ void ldmx4(uint32_t* r, uint32_t addr) {
    asm volatile("ldmatrix.sync.aligned.m8n8.x4.shared.b16 {%0,%1,%2,%3}, [%4];"
                 : "=r"(r[0]), "=r"(r[1]), "=r"(r[2]), "=r"(r[3]) : "r"(addr));
}
__device__ __forceinline__ void ldmx4t(uint32_t* r, uint32_t addr) {
    asm volatile("ldmatrix.sync.aligned.m8n8.x4.trans.shared.b16 {%0,%1,%2,%3}, [%4];"
                 : "=r"(r[0]), "=r"(r[1]), "=r"(r[2]), "=r"(r[3]) : "r"(addr));
}
__device__ __forceinline__ void mma16816h(float* d, const uint32_t* a, const uint32_t* b) {
    asm volatile("mma.sync.aligned.m16n8k16.row.col.f32.f16.f16.f32 "
                 "{%0,%1,%2,%3}, {%4,%5,%6,%7}, {%8,%9}, {%0,%1,%2,%3};"
                 : "+f"(d[0]), "+f"(d[1]), "+f"(d[2]), "+f"(d[3])
                 : "r"(a[0]), "r"(a[1]), "r"(a[2]), "r"(a[3]), "r"(b[0]), "r"(b[1]));
}
__device__ __forceinline__ uint32_t packh(float x, float y) {
    __half2 t; t.x = __float2half_rn(x); t.y = __float2half_rn(y);
    return *(uint32_t*)&t;
}
__device__ __forceinline__ float fexp(float x) {
    return __expf(fmaxf(x, -80.0f));
}

// ======================= fp32 -> fp16 hi/lo split ==========================
__global__ __launch_bounds__(256)
void split_fp16_kernel(const float* __restrict__ src,
                       __half* __restrict__ hi, __half* __restrict__ lo, int n4)
{
    int i = blockIdx.x * blockDim.x + threadIdx.x;
    if (i >= n4) return;
    float4 x = ((const float4*)src)[i];
    float xs[4] = {x.x, x.y, x.z, x.w};
    __half h[4], l[4];
#pragma unroll
    for (int j = 0; j < 4; j++) {
        h[j] = __float2half_rn(xs[j]);
        l[j] = __float2half_rn(xs[j] - __half2float(h[j]));
    }
    __half2 h0; h0.x = h[0]; h0.y = h[1];
    __half2 h1; h1.x = h[2]; h1.y = h[3];
    __half2 l0; l0.x = l[0]; l0.y = l[1];
    __half2 l1; l1.x = l[2]; l1.y = l[3];
    ((__half2*)hi)[i*2 + 0] = h0;
    ((__half2*)hi)[i*2 + 1] = h1;
    ((__half2*)lo)[i*2 + 0] = l0;
    ((__half2*)lo)[i*2 + 1] = l1;
}

// ======================= fp32 -> fp16 single convert =======================
__global__ __launch_bounds__(256)
void conv_fp16_kernel(const float* __restrict__ src, __half* __restrict__ dst, int n4)
{
    int i = blockIdx.x * blockDim.x + threadIdx.x;
    if (i >= n4) return;
    float4 x = ((const float4*)src)[i];
    __half2 a; a.x = __float2half_rn(x.x); a.y = __float2half_rn(x.y);
    __half2 b; b.x = __float2half_rn(x.z); b.y = __float2half_rn(x.w);
    ((__half2*)dst)[i*2 + 0] = a;
    ((__half2*)dst)[i*2 + 1] = b;
}

// ======================= fp16 asym GEMM (A hi/lo x B single, NT) ===========
// C[M,N] = A[M,K]*B[N,K]^T, fp32 acc, 2 MMAs per operand pair.
#define LDT   40
#define TILE_B (128*LDT*2)
#define STG_B3 (3*TILE_B)
#define NSTG  3
#define GEMM_SMEM3 (NSTG*STG_B3)

__device__ __forceinline__ void load_stage3(
    uint32_t sbase, int stg,
    const __half* __restrict__ Ah, const __half* __restrict__ Al,
    const __half* __restrict__ Bs,
    int m0, int n0, int K, int k0, int tid)
{
    uint32_t sd = sbase + stg * STG_B3;
#pragma unroll
    for (int i = 0; i < 6; i++) {
        int chunk = i * 256 + tid;
        int tile  = chunk >> 9;         // 0..2
        int idx   = chunk & 511;
        int row   = idx >> 2;
        int cseg  = idx & 3;
        const __half* g = (tile == 0) ? Ah : (tile == 1) ? Al : Bs;
        int grow = ((tile < 2) ? m0 : n0) + row;
        const char* src = (const char*)(g + (size_t)grow * K + k0) + cseg * 16;
        cpasync16(sd + tile * TILE_B + row * 80 + cseg * 16, src);
    }
}

__global__ __launch_bounds__(256, 1)
void gemm_asym(const __half* __restrict__ Ah, const __half* __restrict__ Al,
               const __half* __restrict__ Bs,
               float* __restrict__ C, int N, int K)
{
    extern __shared__ char dsm[];
    const uint32_t sb = smem_u32(dsm);
    const int tid = threadIdx.x;
    const int w = tid >> 5;
    const int l = tid & 31;
    const int wm = (w >> 2) * 64;
    const int wn = (w & 3) * 32;
    const int m0 = blockIdx.y * 128;
    const int n0 = blockIdx.x * 128;
    const int kiters = K / 32;

    load_stage3(sb, 0, Ah, Al, Bs, m0, n0, K, 0, tid);  CP_COMMIT();
    load_stage3(sb, 1, Ah, Al, Bs, m0, n0, K, 32, tid); CP_COMMIT();

    float acc[16][4];
#pragma unroll
    for (int i = 0; i < 16; i++)
#pragma unroll
        for (int j = 0; j < 4; j++) acc[i][j] = 0.f;

    const int a_row = (l & 15);
    const int a_kof = (l >> 4) * 8;
    const int b_row = (l & 7) + ((l >> 4) & 1) * 8;
    const int b_kof = ((l >> 3) & 1) * 8;

    for (int kt = 0; kt < kiters; kt++) {
        CP_WAIT1();
        __syncthreads();
        const uint32_t st = sb + (kt % 3) * STG_B3;
        const uint32_t sAh = st;
        const uint32_t sAl = st + TILE_B;
        const uint32_t sBs = st + 2 * TILE_B;

#pragma unroll
        for (int ks = 0; ks < 2; ks++) {
            const int kbase = ks * 16;
            uint32_t ah[4][4], al[4][4], bh[2][4];
#pragma unroll
            for (int mi = 0; mi < 4; mi++) {
                uint32_t off = (uint32_t)((wm + mi * 16 + a_row) * 80 + (kbase + a_kof) * 2);
                ldmx4(ah[mi], sAh + off);
                ldmx4(al[mi], sAl + off);
            }
#pragma unroll
            for (int ni2 = 0; ni2 < 2; ni2++) {
                uint32_t off = (uint32_t)((wn + ni2 * 16 + b_row) * 80 + (kbase + b_kof) * 2);
                ldmx4(bh[ni2], sBs + off);
            }
#pragma unroll
            for (int mi = 0; mi < 4; mi++) {
#pragma unroll
                for (int ni = 0; ni < 4; ni++) {
                    const uint32_t* bhp = &bh[ni >> 1][(ni & 1) * 2];
                    mma16816h(acc[mi * 4 + ni], ah[mi], bhp);
                    mma16816h(acc[mi * 4 + ni], al[mi], bhp);
                }
            }
        }
        __syncthreads();
        if (kt + 2 < kiters)
            load_stage3(sb, (kt + 2) % 3, Ah, Al, Bs, m0, n0, K, (kt + 2) * 32, tid);
        CP_COMMIT();
    }

#pragma unroll
    for (int mi = 0; mi < 4; mi++) {
#pragma unroll
        for (int ni = 0; ni < 4; ni++) {
            int row = m0 + wm + mi * 16 + (l >> 2);
            int col = n0 + wn + ni * 8 + (l & 3) * 2;
            float* c = C + (size_t)row * N + col;
            float2 v0; v0.x = acc[mi * 4 + ni][0]; v0.y = acc[mi * 4 + ni][1];
            float2 v1; v1.x = acc[mi * 4 + ni][2]; v1.y = acc[mi * 4 + ni][3];
            *(float2*)c = v0;
            *(float2*)(c + 8 * (size_t)N) = v1;
        }
    }
}

// ---------------- RMSNorm + mrope -> fp16 operands --------------------------
__device__ __forceinline__ int mrope_axis(int d) {
    return d < 21 ? 0 : d < 42 ? 1 : d < 64 ? 2 : d < 85 ? 0 : d < 106 ? 1 : 2;
}

__global__ __launch_bounds__(256)
void norm_rope_kernel(const float* __restrict__ cosb, const float* __restrict__ sinb,
                      const float* __restrict__ qw,   const float* __restrict__ kw)
{
    const int m = blockIdx.x;
    const int b = m >> 11;
    const int s = m & (S_ - 1);
    const int warp = threadIdx.x >> 5;
    const int lane = threadIdx.x & 31;
    const float SC = 0.08838834764831845f;
    const float* tok = g_qkv + (size_t)m * NQKV;

#pragma unroll
    for (int it = 0; it < 4; it++) {
        int slot = warp + (it << 3);
        const float* src; const float* w; bool rope; float scale;
        __half *dh = nullptr, *dl = nullptr;
        if (slot < 16) {
            src = tok + slot * D_;
            size_t o = ((size_t)(b * H_ + slot) * S_ + s) * D_;
            dh = g_qh + o; dl = g_ql + o;
            w = qw; rope = true; scale = SC;
        } else if (slot < 24) {
            int hh = slot - 16;
            src = tok + 2048 + hh * D_;
            size_t o = ((size_t)(b * KV_ + hh) * S_ + s) * D_;
            dh = g_k16 + o;
            w = kw; rope = true; scale = 1.f;
        } else {
            int hh = slot - 24;
            src = tok + 3072 + hh * D_;
            size_t o = ((size_t)(b * KV_ + hh) * S_ + s) * D_;
            dh = g_v16 + o;
            w = nullptr; rope = false; scale = 1.f;
        }
        float4 x4 = *(const float4*)(src + lane * 4);
        float out[4] = {x4.x, x4.y, x4.z, x4.w};
        if (rope) {
            float x[4] = {out[0], out[1], out[2], out[3]};
            float ssum = x[0]*x[0] + x[1]*x[1] + x[2]*x[2] + x[3]*x[3];
#pragma unroll
            for (int o2 = 16; o2 > 0; o2 >>= 1)
                ssum += __shfl_xor_sync(0xffffffffu, ssum, o2);
            float r = rsqrtf(ssum * (1.0f / 128.0f) + 1e-6f);
            float4 w4 = *(const float4*)(w + lane * 4);
            float xn[4];
            xn[0] = x[0] * r * w4.x; xn[1] = x[1] * r * w4.y;
            xn[2] = x[2] * r * w4.z; xn[3] = x[3] * r * w4.w;
            float oth[4];
#pragma unroll
            for (int j = 0; j < 4; j++)
                oth[j] = __shfl_xor_sync(0xffffffffu, xn[j], 16);
            float sgn = (lane < 16) ? -1.f : 1.f;
            int dbase = lane * 4;
#pragma unroll
            for (int j = 0; j < 4; j++) {
                int d = dbase + j;
                int ax = mrope_axis(d);
                size_t ci = ((size_t)(ax * B_ + b) * S_ + s) * D_ + d;
                out[j] = (xn[j] * cosb[ci] + sgn * oth[j] * sinb[ci]) * scale;
            }
        }
        if (dl) {
            __half h[4], lo[4];
#pragma unroll
            for (int j = 0; j < 4; j++) {
                h[j]  = __float2half_rn(out[j]);
                lo[j] = __float2half_rn(out[j] - __half2float(h[j]));
            }
            __half2* ph = (__half2*)(dh + lane * 4);
            __half2* pl = (__half2*)(dl + lane * 4);
            __half2 t;
            t.x = h[0];  t.y = h[1];  ph[0] = t;
            t.x = h[2];  t.y = h[3];  ph[1] = t;
            t.x = lo[0]; t.y = lo[1]; pl[0] = t;
            t.x = lo[2]; t.y = lo[3]; pl[1] = t;
        } else {
            __half2* ph = (__half2*)(dh + lane * 4);
            __half2 t;
            t.x = __float2half_rn(out[0]); t.y = __float2half_rn(out[1]); ph[0] = t;
            t.x = __float2half_rn(out[2]); t.y = __float2half_rn(out[3]); ph[1] = t;
        }
    }
}

// ---------------- causal GQA flash attention (fp16, reduced mma) ------------
#define FSTR 136
#define QTILE_E (128*FSTR)
#define KTILE_E (64*FSTR)
#define FLASH_SMEM ((2*QTILE_E + 4*KTILE_E)*2)   // 139264 bytes
#define MASKV (-30000.0f)

__device__ __forceinline__ void load_kv_stage(
    __half* fsb, int st, int k0,
    const __half* Kp, const __half* Vp, int tid)
{
    __half* kd = fsb + 2*QTILE_E + st * 2 * KTILE_E;
    __half* vd = kd + KTILE_E;
#pragma unroll
    for (int i = 0; i < 4; i++) {
        int c = tid + i * 256;
        int r = c >> 4, cs = c & 15;
        size_t go = (size_t)(k0 + r) * D_ + cs * 8;
        uint32_t so = (uint32_t)(r * FSTR + cs * 8);
        cpasync16(smem_u32(kd + so), Kp + go);
        cpasync16(smem_u32(vd + so), Vp + go);
    }
}

__global__ __launch_bounds__(256, 1)
void flash_mma(__half* __restrict__ Oh, __half* __restrict__ Ol)
{
    extern __shared__ __half fsh[];
    __half* sQh = fsh;
    __half* sQl = fsh + QTILE_E;

    const int qt = (int)gridDim.x - 1 - (int)blockIdx.x;  // longest-first
    const int h = blockIdx.y, b = blockIdx.z;
    const int tid = threadIdx.x;
    const int w = tid >> 5;
    const int l = tid & 31;
    const int q0 = qt * 128;

    const __half* Qbh = g_qh + ((size_t)(b * H_ + h) * S_ + q0) * D_;
    const __half* Qbl = g_ql + ((size_t)(b * H_ + h) * S_ + q0) * D_;
    const __half* Kb  = g_k16 + (size_t)(b * KV_ + (h >> 1)) * S_ * D_;
    const __half* Vb  = g_v16 + (size_t)(b * KV_ + (h >> 1)) * S_ * D_;

#pragma unroll
    for (int i = 0; i < 8; i++) {
        int c = tid + i * 256;
        int r = c >> 4, cs = c & 15;
        size_t go = (size_t)r * D_ + cs * 8;
        uint32_t so = (uint32_t)(r * FSTR + cs * 8);
        cpasync16(smem_u32(sQh + so), Qbh + go);
        cpasync16(smem_u32(sQl + so), Qbl + go);
    }
    load_kv_stage(fsh, 0, 0, Kb, Vb, tid);
    CP_COMMIT();

    float o[16][4];
#pragma unroll
    for (int i = 0; i < 16; i++)
#pragma unroll
        for (int j = 0; j < 4; j++) o[i][j] = 0.f;
    float mrow[2] = {MASKV, MASKV};
    float lrow[2] = {0.f, 0.f};

    const int r0 = l >> 2;
    const int a_row = (l & 15);
    const int a_kof = (l >> 4) * 8;
    const int b_row = (l & 7) + ((l >> 4) & 1) * 8;
    const int b_kof = ((l >> 3) & 1) * 8;
    const int v_row = (l & 15);
    const int v_cof = (l >> 4) * 8;
    const int wrow_lo = q0 + 16 * w;
    const int ntiles = 2 * qt + 2;

    for (int t = 0; t < ntiles; t++) {
        const int k0 = t * 64;
        const int st = t & 1;
        if (t + 1 < ntiles) {
            load_kv_stage(fsh, st ^ 1, (t + 1) * 64, Kb, Vb, tid);
            CP_COMMIT();
            CP_WAIT1();
        } else {
            CP_WAIT0();
        }
        __syncthreads();

        if (k0 <= wrow_lo + 15) {
            __half* sK = fsh + 2*QTILE_E + st * 2 * KTILE_E;
            __half* sV = sK + KTILE_E;

            float s[8][4];
#pragma unroll
            for (int i = 0; i < 8; i++)
#pragma unroll
                for (int j = 0; j < 4; j++) s[i][j] = 0.f;

#pragma unroll
            for (int ks = 0; ks < 8; ks++) {
                uint32_t aoff = (uint32_t)((16 * w + a_row) * FSTR + ks * 16 + a_kof) * 2;
                uint32_t qh[4], ql[4];
                ldmx4(qh, smem_u32(sQh) + aoff);
                ldmx4(ql, smem_u32(sQl) + aoff);
#pragma unroll
                for (int ng = 0; ng < 4; ng++) {
                    uint32_t boff = (uint32_t)((16 * ng + b_row) * FSTR + ks * 16 + b_kof) * 2;
                    uint32_t kf[4];
                    ldmx4(kf, smem_u32(sK) + boff);
                    mma16816h(s[2*ng],   qh, &kf[0]);
                    mma16816h(s[2*ng],   ql, &kf[0]);
                    mma16816h(s[2*ng+1], qh, &kf[2]);
                    mma16816h(s[2*ng+1], ql, &kf[2]);
                }
            }

            if (k0 + 63 > wrow_lo) {
                int grow0 = wrow_lo + r0;
                int grow1 = grow0 + 8;
#pragma unroll
                for (int nt = 0; nt < 8; nt++) {
                    int col = k0 + nt * 8 + (l & 3) * 2;
                    if (col > grow0)     s[nt][0] = MASKV;
                    if (col + 1 > grow0) s[nt][1] = MASKV;
                    if (col > grow1)     s[nt][2] = MASKV;
                    if (col + 1 > grow1) s[nt][3] = MASKV;
                }
            }

            float rm0 = MASKV, rm1 = MASKV;
#pragma unroll
            for (int nt = 0; nt < 8; nt++) {
                rm0 = fmaxf(rm0, fmaxf(s[nt][0], s[nt][1]));
                rm1 = fmaxf(rm1, fmaxf(s[nt][2], s[nt][3]));
            }
            rm0 = fmaxf(rm0, __shfl_xor_sync(0xffffffffu, rm0, 1));
            rm0 = fmaxf(rm0, __shfl_xor_sync(0xffffffffu, rm0, 2));
            rm1 = fmaxf(rm1, __shfl_xor_sync(0xffffffffu, rm1, 1));
            rm1 = fmaxf(rm1, __shfl_xor_sync(0xffffffffu, rm1, 2));

            float mn0 = fmaxf(mrow[0], rm0);
            float mn1 = fmaxf(mrow[1], rm1);
            float alpha0 = fexp(mrow[0] - mn0);
            float alpha1 = fexp(mrow[1] - mn1);
            mrow[0] = mn0; mrow[1] = mn1;

            float rs0 = 0.f, rs1 = 0.f;
#pragma unroll
            for (int nt = 0; nt < 8; nt++) {
                s[nt][0] = fexp(s[nt][0] - mn0);
                s[nt][1] = fexp(s[nt][1] - mn0);
                s[nt][2] = fexp(s[nt][2] - mn1);
                s[nt][3] = fexp(s[nt][3] - mn1);
                rs0 += s[nt][0] + s[nt][1];
                rs1 += s[nt][2] + s[nt][3];
            }
            rs0 += __shfl_xor_sync(0xffffffffu, rs0, 1);
            rs0 += __shfl_xor_sync(0xffffffffu, rs0, 2);
            rs1 += __shfl_xor_sync(0xffffffffu, rs1, 1);
            rs1 += __shfl_xor_sync(0xffffffffu, rs1, 2);
            lrow[0] = lrow[0] * alpha0 + rs0;
            lrow[1] = lrow[1] * alpha1 + rs1;

#pragma unroll
            for (int nt = 0; nt < 16; nt++) {
                o[nt][0] *= alpha0; o[nt][1] *= alpha0;
                o[nt][2] *= alpha1; o[nt][3] *= alpha1;
            }

#pragma unroll
            for (int ks = 0; ks < 4; ks++) {
                uint32_t pa[4];
                pa[0] = packh(s[2*ks][0],   s[2*ks][1]);
                pa[1] = packh(s[2*ks][2],   s[2*ks][3]);
                pa[2] = packh(s[2*ks+1][0], s[2*ks+1][1]);
                pa[3] = packh(s[2*ks+1][2], s[2*ks+1][3]);
#pragma unroll
                for (int dg = 0; dg < 8; dg++) {
                    uint32_t voff = (uint32_t)((ks * 16 + v_row) * FSTR + dg * 16 + v_cof) * 2;
                    uint32_t vf[4];
                    ldmx4t(vf, smem_u32(sV) + voff);
                    mma16816h(o[2*dg],   pa, &vf[0]);
                    mma16816h(o[2*dg+1], pa, &vf[2]);
                }
            }
        }
        __syncthreads();
    }

    float inv0 = 1.f / lrow[0];
    float inv1 = 1.f / lrow[1];
    size_t row0 = (size_t)b * S_ + q0 + 16 * w + r0;
    size_t row1 = row0 + 8;
    int colb = h * D_ + (l & 3) * 2;
#pragma unroll
    for (int nt = 0; nt < 16; nt++) {
        int col = colb + nt * 8;
        float v0 = o[nt][0] * inv0, v1 = o[nt][1] * inv0;
        float v2 = o[nt][2] * inv1, v3 = o[nt][3] * inv1;
        uint32_t h0 = packh(v0, v1);
        __half2 th = *(__half2*)&h0;
        uint32_t lo0 = packh(v0 - __half2float(th.x), v1 - __half2float(th.y));
        *(uint32_t*)(Oh + row0 * (H_*D_) + col) = h0;
        *(uint32_t*)(Ol + row0 * (H_*D_) + col) = lo0;
        uint32_t h1 = packh(v2, v3);
        __half2 th1 = *(__half2*)&h1;
        uint32_t lo1 = packh(v2 - __half2float(th1.x), v3 - __half2float(th1.y));
        *(uint32_t*)(Oh + row1 * (H_*D_) + col) = h1;
        *(uint32_t*)(Ol + row1 * (H_*D_) + col) = lo1;
    }
}

// ---------------- launcher ---------------------------------------------------
extern "C" void kernel_launch(void* const* d_in, const int* in_sizes, int n_in,
                              void* d_out, int out_size)
{
    const float* hidden   = (const float*)d_in[0];
    const float* cosb     = (const float*)d_in[1];
    const float* sinb     = (const float*)d_in[2];
    const float* q_w      = (const float*)d_in[3];
    const float* k_w      = (const float*)d_in[4];
    const float* v_w      = (const float*)d_in[5];
    const float* o_w      = (const float*)d_in[6];
    const float* q_norm_w = (const float*)d_in[7];
    const float* k_norm_w = (const float*)d_in[8];
    float* out = (float*)d_out;

    float* pqkv;
    cudaGetSymbolAddress((void**)&pqkv, g_qkv);

    __half *hidh, *hidl, *w16, *ow16, *ath, *atl;
    cudaGetSymbolAddress((void**)&hidh, g_hid_h);
    cudaGetSymbolAddress((void**)&hidl, g_hid_l);
    cudaGetSymbolAddress((void**)&w16,  g_w16);
    cudaGetSymbolAddress((void**)&ow16, g_ow16);
    cudaGetSymbolAddress((void**)&ath,  g_at_h);
    cudaGetSymbolAddress((void**)&atl,  g_at_l);

    cudaFuncSetAttribute(gemm_asym, cudaFuncAttributeMaxDynamicSharedMemorySize, GEMM_SMEM3);
    cudaFuncSetAttribute(flash_mma, cudaFuncAttributeMaxDynamicSharedMemorySize, FLASH_SMEM);

    // 1) converts: hidden -> fp16 hi/lo; weights -> single fp16
    {
        int n4 = MTOK * HID_ / 4;
        split_fp16_kernel<<<(n4 + 255) / 256, 256>>>(hidden, hidh, hidl, n4);
    }
    conv_fp16_kernel<<<(H_*D_*HID_/4 + 255)/256, 256>>>(q_w, w16,                     H_*D_*HID_/4);
    conv_fp16_kernel<<<(KV_*D_*HID_/4 + 255)/256, 256>>>(k_w, w16 + (size_t)2048*HID_, KV_*D_*HID_/4);
    conv_fp16_kernel<<<(KV_*D_*HID_/4 + 255)/256, 256>>>(v_w, w16 + (size_t)3072*HID_, KV_*D_*HID_/4);
    conv_fp16_kernel<<<(HID_*H_*D_/4 + 255)/256, 256>>>(o_w, ow16, HID_*H_*D_/4);

    // 2) fused QKV projection (fp16 asym: hidden hi/lo x weights single, 2-mma)
    gemm_asym<<<dim3(NQKV/128, MTOK/128), 256, GEMM_SMEM3>>>(hidh, hidl, w16, pqkv, NQKV, HID_);

    // 3) RMSNorm + mrope -> fp16 operands
    norm_rope_kernel<<<MTOK, 256>>>(cosb, sinb, q_norm_w, k_norm_w);

    // 4) flash attention: QK 2-mma, PV 1-mma
    flash_mma<<<dim3(S_ / 128, H_, B_), 256, FLASH_SMEM>>>(ath, atl);

    // 5) O-projection (fp16 asym, 2-mma) -> d_out
    gemm_asym<<<dim3(HID_/128, MTOK/128), 256, GEMM_SMEM3>>>(ath, atl, ow16, out, HID_, H_*D_);
}

// round 11
// speedup vs baseline: 1.5162x; 1.5162x over previous
#include <cuda_runtime.h>
#include <cuda_bf16.h>
#include <cuda_fp16.h>
#include <math.h>
#include <stdint.h>

// Problem constants
#define B_   2
#define S_   2048
#define HID_ 2048
#define H_   16
#define KV_  8
#define D_   128
#define MTOK (B_*S_)   // 4096 tokens
#define NQKV 4096

// ---------------- scratch (device globals) ----------------------------------
__device__ float g_qkv[MTOK * NQKV];   // fused QKV projection output

__device__ __nv_bfloat16 g_hid_h[MTOK*HID_],  g_hid_l[MTOK*HID_];
__device__ __nv_bfloat16 g_w_h [NQKV*HID_],   g_w_l [NQKV*HID_];   // q|k|v weights concat
__device__ __half        g_ow16[HID_*H_*D_];                        // o_w fp16

// roped/normed operands for flash (single fp16), [B,H|KV,S,D]
__device__ __half g_q16[B_*H_*S_*D_];
__device__ __half g_k16[B_*KV_*S_*D_];
__device__ __half g_v16[B_*KV_*S_*D_];
// attention output (single fp16), [B*S, H*D]
__device__ __half g_at16[MTOK*H_*D_];

// ======================= PTX helpers (sm_80-era) ===========================
__device__ __forceinline__ uint32_t smem_u32(const void* p) {
    return (uint32_t)__cvta_generic_to_shared(p);
}
__device__ __forceinline__ void cpasync16(uint32_t dst, const void* src) {
    asm volatile("cp.async.cg.shared.global [%0], [%1], 16;" :: "r"(dst), "l"(src));
}
#define CP_COMMIT() asm volatile("cp.async.commit_group;" ::: "memory")
#define CP_WAIT1()  asm volatile("cp.async.wait_group 1;" ::: "memory")
#define CP_WAIT0()  asm volatile("cp.async.wait_group 0;" ::: "memory")

__device__ __forceinline__ void ldmx4(uint32_t* r, uint32_t addr) {
    asm volatile("ldmatrix.sync.aligned.m8n8.x4.shared.b16 {%0,%1,%2,%3}, [%4];"
                 : "=r"(r[0]), "=r"(r[1]), "=r"(r[2]), "=r"(r[3]) : "r"(addr));
}
__device__ __forceinline__ void ldmx4t(uint32_t* r, uint32_t addr) {
    asm volatile("ldmatrix.sync.aligned.m8n8.x4.trans.shared.b16 {%0,%1,%2,%3}, [%4];"
                 : "=r"(r[0]), "=r"(r[1]), "=r"(r[2]), "=r"(r[3]) : "r"(addr));
}
// bf16 mma
__device__ __forceinline__ void mma16816(float* d, const uint32_t* a, const uint32_t* b) {
    asm volatile("mma.sync.aligned.m16n8k16.row.col.f32.bf16.bf16.f32 "
                 "{%0,%1,%2,%3}, {%4,%5,%6,%7}, {%8,%9}, {%0,%1,%2,%3};"
                 : "+f"(d[0]), "+f"(d[1]), "+f"(d[2]), "+f"(d[3])
                 : "r"(a[0]), "r"(a[1]), "r"(a[2]), "r"(a[3]), "r"(b[0]), "r"(b[1]));
}
// fp16 mma
__device__ __forceinline__ void mma16816h(float* d, const uint32_t* a, const uint32_t* b) {
    asm volatile("mma.sync.aligned.m16n8k16.row.col.f32.f16.f16.f32 "
                 "{%0,%1,%2,%3}, {%4,%5,%6,%7}, {%8,%9}, {%0,%1,%2,%3};"
                 : "+f"(d[0]), "+f"(d[1]), "+f"(d[2]), "+f"(d[3])
                 : "r"(a[0]), "r"(a[1]), "r"(a[2]), "r"(a[3]), "r"(b[0]), "r"(b[1]));
}
__device__ __forceinline__ uint32_t packh(float x, float y) {
    __half2 t; t.x = __float2half_rn(x); t.y = __float2half_rn(y);
    return *(uint32_t*)&t;
}
__device__ __forceinline__ float fexp(float x) {
    return __expf(fmaxf(x, -80.0f));
}

// ======================= fp32 -> bf16 hi/lo split ==========================
__global__ __launch_bounds__(256)
void split_bf16_kernel(const float* __restrict__ src,
                       __nv_bfloat16* __restrict__ hi,
                       __nv_bfloat16* __restrict__ lo, int n4)
{
    int i = blockIdx.x * blockDim.x + threadIdx.x;
    if (i >= n4) return;
    float4 x = ((const float4*)src)[i];
    float xs[4] = {x.x, x.y, x.z, x.w};
    __nv_bfloat16 h[4], l[4];
#pragma unroll
    for (int j = 0; j < 4; j++) {
        h[j] = __float2bfloat16_rn(xs[j]);
        l[j] = __float2bfloat16_rn(xs[j] - __bfloat162float(h[j]));
    }
    __nv_bfloat162 h0; h0.x = h[0]; h0.y = h[1];
    __nv_bfloat162 h1; h1.x = h[2]; h1.y = h[3];
    __nv_bfloat162 l0; l0.x = l[0]; l0.y = l[1];
    __nv_bfloat162 l1; l1.x = l[2]; l1.y = l[3];
    ((__nv_bfloat162*)hi)[i*2 + 0] = h0;
    ((__nv_bfloat162*)hi)[i*2 + 1] = h1;
    ((__nv_bfloat162*)lo)[i*2 + 0] = l0;
    ((__nv_bfloat162*)lo)[i*2 + 1] = l1;
}

// ======================= fp32 -> fp16 single convert =======================
__global__ __launch_bounds__(256)
void conv_fp16_kernel(const float* __restrict__ src, __half* __restrict__ dst, int n4)
{
    int i = blockIdx.x * blockDim.x + threadIdx.x;
    if (i >= n4) return;
    float4 x = ((const float4*)src)[i];
    __half2 a; a.x = __float2half_rn(x.x); a.y = __float2half_rn(x.y);
    __half2 b; b.x = __float2half_rn(x.z); b.y = __float2half_rn(x.w);
    ((__half2*)dst)[i*2 + 0] = a;
    ((__half2*)dst)[i*2 + 1] = b;
}

// ======================= mma.sync bf16x3 GEMM (NT) — QKV (proven) ==========
#define LDT   40
#define TILE_B (128*LDT*2)
#define STG_B  (4*TILE_B)
#define NSTG  3
#define GEMM_SMEM (NSTG*STG_B)

__device__ __forceinline__ void load_stage(
    uint32_t sbase, int stg,
    const __nv_bfloat16* __restrict__ Ah, const __nv_bfloat16* __restrict__ Al,
    const __nv_bfloat16* __restrict__ Bh, const __nv_bfloat16* __restrict__ Bl,
    int m0, int n0, int K, int k0, int tid)
{
    uint32_t sd = sbase + stg * STG_B;
#pragma unroll
    for (int i = 0; i < 8; i++) {
        int chunk = i * 256 + tid;
        int tile  = chunk >> 9;
        int idx   = chunk & 511;
        int row   = idx >> 2;
        int cseg  = idx & 3;
        const __nv_bfloat16* g = (tile == 0) ? Ah : (tile == 1) ? Al : (tile == 2) ? Bh : Bl;
        int grow = ((tile < 2) ? m0 : n0) + row;
        const char* src = (const char*)(g + (size_t)grow * K + k0) + cseg * 16;
        cpasync16(sd + tile * TILE_B + row * 80 + cseg * 16, src);
    }
}

__global__ __launch_bounds__(256, 1)
void gemm_mma(const __nv_bfloat16* __restrict__ Ah, const __nv_bfloat16* __restrict__ Al,
              const __nv_bfloat16* __restrict__ Bh, const __nv_bfloat16* __restrict__ Bl,
              float* __restrict__ C, int N, int K)
{
    extern __shared__ char dsm[];
    const uint32_t sb = smem_u32(dsm);
    const int tid = threadIdx.x;
    const int w = tid >> 5;
    const int l = tid & 31;
    const int wm = (w >> 2) * 64;
    const int wn = (w & 3) * 32;
    const int m0 = blockIdx.y * 128;
    const int n0 = blockIdx.x * 128;
    const int kiters = K / 32;

    load_stage(sb, 0, Ah, Al, Bh, Bl, m0, n0, K, 0, tid);  CP_COMMIT();
    load_stage(sb, 1, Ah, Al, Bh, Bl, m0, n0, K, 32, tid); CP_COMMIT();

    float acc[16][4];
#pragma unroll
    for (int i = 0; i < 16; i++)
#pragma unroll
        for (int j = 0; j < 4; j++) acc[i][j] = 0.f;

    const int a_row = (l & 15);
    const int a_kof = (l >> 4) * 8;
    const int b_row = (l & 7) + ((l >> 4) & 1) * 8;
    const int b_kof = ((l >> 3) & 1) * 8;

    for (int kt = 0; kt < kiters; kt++) {
        CP_WAIT1();
        __syncthreads();
        const uint32_t st = sb + (kt % 3) * STG_B;
        const uint32_t sAh = st;
        const uint32_t sAl = st + TILE_B;
        const uint32_t sBh = st + 2 * TILE_B;
        const uint32_t sBl = st + 3 * TILE_B;

#pragma unroll
        for (int ks = 0; ks < 2; ks++) {
            const int kbase = ks * 16;
            uint32_t ah[4][4], al[4][4], bh[2][4], bl[2][4];
#pragma unroll
            for (int mi = 0; mi < 4; mi++) {
                uint32_t off = (uint32_t)((wm + mi * 16 + a_row) * 80 + (kbase + a_kof) * 2);
                ldmx4(ah[mi], sAh + off);
                ldmx4(al[mi], sAl + off);
            }
#pragma unroll
            for (int ni2 = 0; ni2 < 2; ni2++) {
                uint32_t off = (uint32_t)((wn + ni2 * 16 + b_row) * 80 + (kbase + b_kof) * 2);
                ldmx4(bh[ni2], sBh + off);
                ldmx4(bl[ni2], sBl + off);
            }
#pragma unroll
            for (int mi = 0; mi < 4; mi++) {
#pragma unroll
                for (int ni = 0; ni < 4; ni++) {
                    const uint32_t* bhp = &bh[ni >> 1][(ni & 1) * 2];
                    const uint32_t* blp = &bl[ni >> 1][(ni & 1) * 2];
                    mma16816(acc[mi * 4 + ni], ah[mi], bhp);
                    mma16816(acc[mi * 4 + ni], al[mi], bhp);
                    mma16816(acc[mi * 4 + ni], ah[mi], blp);
                }
            }
        }
        __syncthreads();
        if (kt + 2 < kiters)
            load_stage(sb, (kt + 2) % 3, Ah, Al, Bh, Bl, m0, n0, K, (kt + 2) * 32, tid);
        CP_COMMIT();
    }

#pragma unroll
    for (int mi = 0; mi < 4; mi++) {
#pragma unroll
        for (int ni = 0; ni < 4; ni++) {
            int row = m0 + wm + mi * 16 + (l >> 2);
            int col = n0 + wn + ni * 8 + (l & 3) * 2;
            float* c = C + (size_t)row * N + col;
            float2 v0; v0.x = acc[mi * 4 + ni][0]; v0.y = acc[mi * 4 + ni][1];
            float2 v1; v1.x = acc[mi * 4 + ni][2]; v1.y = acc[mi * 4 + ni][3];
            *(float2*)c = v0;
            *(float2*)(c + 8 * (size_t)N) = v1;
        }
    }
}

// ======================= plain fp16 GEMM (single x single) — O-proj ========
#define STG_B2 (2*TILE_B)
#define GEMM_SMEM2 (NSTG*STG_B2)

__device__ __forceinline__ void load_stage2(
    uint32_t sbase, int stg,
    const __half* __restrict__ As, const __half* __restrict__ Bs,
    int m0, int n0, int K, int k0, int tid)
{
    uint32_t sd = sbase + stg * STG_B2;
#pragma unroll
    for (int i = 0; i < 4; i++) {
        int chunk = i * 256 + tid;
        int tile  = chunk >> 9;         // 0..1
        int idx   = chunk & 511;
        int row   = idx >> 2;
        int cseg  = idx & 3;
        const __half* g = (tile == 0) ? As : Bs;
        int grow = ((tile == 0) ? m0 : n0) + row;
        const char* src = (const char*)(g + (size_t)grow * K + k0) + cseg * 16;
        cpasync16(sd + tile * TILE_B + row * 80 + cseg * 16, src);
    }
}

__global__ __launch_bounds__(256, 2)
void gemm_ff(const __half* __restrict__ As, const __half* __restrict__ Bs,
             float* __restrict__ C, int N, int K)
{
    extern __shared__ char dsm[];
    const uint32_t sb = smem_u32(dsm);
    const int tid = threadIdx.x;
    const int w = tid >> 5;
    const int l = tid & 31;
    const int wm = (w >> 2) * 64;
    const int wn = (w & 3) * 32;
    const int m0 = blockIdx.y * 128;
    const int n0 = blockIdx.x * 128;
    const int kiters = K / 32;

    load_stage2(sb, 0, As, Bs, m0, n0, K, 0, tid);  CP_COMMIT();
    load_stage2(sb, 1, As, Bs, m0, n0, K, 32, tid); CP_COMMIT();

    float acc[16][4];
#pragma unroll
    for (int i = 0; i < 16; i++)
#pragma unroll
        for (int j = 0; j < 4; j++) acc[i][j] = 0.f;

    const int a_row = (l & 15);
    const int a_kof = (l >> 4) * 8;
    const int b_row = (l & 7) + ((l >> 4) & 1) * 8;
    const int b_kof = ((l >> 3) & 1) * 8;

    for (int kt = 0; kt < kiters; kt++) {
        CP_WAIT1();
        __syncthreads();
        const uint32_t st = sb + (kt % 3) * STG_B2;
        const uint32_t sA = st;
        const uint32_t sB = st + TILE_B;

#pragma unroll
        for (int ks = 0; ks < 2; ks++) {
            const int kbase = ks * 16;
            uint32_t af[4][4], bf[2][4];
#pragma unroll
            for (int mi = 0; mi < 4; mi++) {
                uint32_t off = (uint32_t)((wm + mi * 16 + a_row) * 80 + (kbase + a_kof) * 2);
                ldmx4(af[mi], sA + off);
            }
#pragma unroll
            for (int ni2 = 0; ni2 < 2; ni2++) {
                uint32_t off = (uint32_t)((wn + ni2 * 16 + b_row) * 80 + (kbase + b_kof) * 2);
                ldmx4(bf[ni2], sB + off);
            }
#pragma unroll
            for (int mi = 0; mi < 4; mi++) {
#pragma unroll
                for (int ni = 0; ni < 4; ni++) {
                    const uint32_t* bp = &bf[ni >> 1][(ni & 1) * 2];
                    mma16816h(acc[mi * 4 + ni], af[mi], bp);
                }
            }
        }
        __syncthreads();
        if (kt + 2 < kiters)
            load_stage2(sb, (kt + 2) % 3, As, Bs, m0, n0, K, (kt + 2) * 32, tid);
        CP_COMMIT();
    }

#pragma unroll
    for (int mi = 0; mi < 4; mi++) {
#pragma unroll
        for (int ni = 0; ni < 4; ni++) {
            int row = m0 + wm + mi * 16 + (l >> 2);
            int col = n0 + wn + ni * 8 + (l & 3) * 2;
            float* c = C + (size_t)row * N + col;
            float2 v0; v0.x = acc[mi * 4 + ni][0]; v0.y = acc[mi * 4 + ni][1];
            float2 v1; v1.x = acc[mi * 4 + ni][2]; v1.y = acc[mi * 4 + ni][3];
            *(float2*)c = v0;
            *(float2*)(c + 8 * (size_t)N) = v1;
        }
    }
}

// ---------------- RMSNorm + mrope -> single fp16 operands -------------------
__device__ __forceinline__ int mrope_axis(int d) {
    return d < 21 ? 0 : d < 42 ? 1 : d < 64 ? 2 : d < 85 ? 0 : d < 106 ? 1 : 2;
}

__global__ __launch_bounds__(256)
void norm_rope_kernel(const float* __restrict__ cosb, const float* __restrict__ sinb,
                      const float* __restrict__ qw,   const float* __restrict__ kw)
{
    const int m = blockIdx.x;
    const int b = m >> 11;
    const int s = m & (S_ - 1);
    const int warp = threadIdx.x >> 5;
    const int lane = threadIdx.x & 31;
    const float SC = 0.08838834764831845f;
    const float* tok = g_qkv + (size_t)m * NQKV;

#pragma unroll
    for (int it = 0; it < 4; it++) {
        int slot = warp + (it << 3);
        const float* src; const float* w; bool rope; float scale;
        __half* dh;
        if (slot < 16) {
            src = tok + slot * D_;
            dh = g_q16 + ((size_t)(b * H_ + slot) * S_ + s) * D_;
            w = qw; rope = true; scale = SC;
        } else if (slot < 24) {
            int hh = slot - 16;
            src = tok + 2048 + hh * D_;
            dh = g_k16 + ((size_t)(b * KV_ + hh) * S_ + s) * D_;
            w = kw; rope = true; scale = 1.f;
        } else {
            int hh = slot - 24;
            src = tok + 3072 + hh * D_;
            dh = g_v16 + ((size_t)(b * KV_ + hh) * S_ + s) * D_;
            w = nullptr; rope = false; scale = 1.f;
        }
        float4 x4 = *(const float4*)(src + lane * 4);
        float out[4] = {x4.x, x4.y, x4.z, x4.w};
        if (rope) {
            float x[4] = {out[0], out[1], out[2], out[3]};
            float ssum = x[0]*x[0] + x[1]*x[1] + x[2]*x[2] + x[3]*x[3];
#pragma unroll
            for (int o2 = 16; o2 > 0; o2 >>= 1)
                ssum += __shfl_xor_sync(0xffffffffu, ssum, o2);
            float r = rsqrtf(ssum * (1.0f / 128.0f) + 1e-6f);
            float4 w4 = *(const float4*)(w + lane * 4);
            float xn[4];
            xn[0] = x[0] * r * w4.x; xn[1] = x[1] * r * w4.y;
            xn[2] = x[2] * r * w4.z; xn[3] = x[3] * r * w4.w;
            float oth[4];
#pragma unroll
            for (int j = 0; j < 4; j++)
                oth[j] = __shfl_xor_sync(0xffffffffu, xn[j], 16);
            float sgn = (lane < 16) ? -1.f : 1.f;
            int dbase = lane * 4;
#pragma unroll
            for (int j = 0; j < 4; j++) {
                int d = dbase + j;
                int ax = mrope_axis(d);
                size_t ci = ((size_t)(ax * B_ + b) * S_ + s) * D_ + d;
                out[j] = (xn[j] * cosb[ci] + sgn * oth[j] * sinb[ci]) * scale;
            }
        }
        __half2* ph = (__half2*)(dh + lane * 4);
        __half2 t;
        t.x = __float2half_rn(out[0]); t.y = __float2half_rn(out[1]); ph[0] = t;
        t.x = __float2half_rn(out[2]); t.y = __float2half_rn(out[3]); ph[1] = t;
    }
}

// ---------------- causal GQA flash attention (fp16 single, 1-mma) -----------
// CTA: 128 q rows, 256 threads. K-tile 64, double-buffered. 2 CTAs/SM.
#define FSTR 136
#define QTILE_E (128*FSTR)
#define KTILE_E (64*FSTR)
#define FLASH_SMEM ((QTILE_E + 4*KTILE_E)*2)   // 104448 bytes
#define MASKV (-30000.0f)

__device__ __forceinline__ void load_kv_stage(
    __half* fsb, int st, int k0,
    const __half* Kp, const __half* Vp, int tid)
{
    __half* kd = fsb + QTILE_E + st * 2 * KTILE_E;
    __half* vd = kd + KTILE_E;
#pragma unroll
    for (int i = 0; i < 4; i++) {
        int c = tid + i * 256;
        int r = c >> 4, cs = c & 15;
        size_t go = (size_t)(k0 + r) * D_ + cs * 8;
        uint32_t so = (uint32_t)(r * FSTR + cs * 8);
        cpasync16(smem_u32(kd + so), Kp + go);
        cpasync16(smem_u32(vd + so), Vp + go);
    }
}

__global__ __launch_bounds__(256, 2)
void flash_mma(__half* __restrict__ O16)
{
    extern __shared__ __half fsh[];
    __half* sQ = fsh;

    const int qt = (int)gridDim.x - 1 - (int)blockIdx.x;  // longest-first
    const int h = blockIdx.y, b = blockIdx.z;
    const int tid = threadIdx.x;
    const int w = tid >> 5;
    const int l = tid & 31;
    const int q0 = qt * 128;

    const __half* Qb = g_q16 + ((size_t)(b * H_ + h) * S_ + q0) * D_;
    const __half* Kb = g_k16 + (size_t)(b * KV_ + (h >> 1)) * S_ * D_;
    const __half* Vb = g_v16 + (size_t)(b * KV_ + (h >> 1)) * S_ * D_;

    // prologue: Q (128 rows x 16 segs = 2048 chunks) + KV(tile 0)
#pragma unroll
    for (int i = 0; i < 8; i++) {
        int c = tid + i * 256;
        int r = c >> 4, cs = c & 15;
        cpasync16(smem_u32(sQ + (uint32_t)(r * FSTR + cs * 8)), Qb + (size_t)r * D_ + cs * 8);
    }
    load_kv_stage(fsh, 0, 0, Kb, Vb, tid);
    CP_COMMIT();

    float o[16][4];
#pragma unroll
    for (int i = 0; i < 16; i++)
#pragma unroll
        for (int j = 0; j < 4; j++) o[i][j] = 0.f;
    float mrow[2] = {MASKV, MASKV};
    float lrow[2] = {0.f, 0.f};

    const int r0 = l >> 2;
    const int a_row = (l & 15);
    const int a_kof = (l >> 4) * 8;
    const int b_row = (l & 7) + ((l >> 4) & 1) * 8;
    const int b_kof = ((l >> 3) & 1) * 8;
    const int v_row = (l & 15);
    const int v_cof = (l >> 4) * 8;
    const int wrow_lo = q0 + 16 * w;
    const int ntiles = 2 * qt + 2;

    for (int t = 0; t < ntiles; t++) {
        const int k0 = t * 64;
        const int st = t & 1;
        if (t + 1 < ntiles) {
            load_kv_stage(fsh, st ^ 1, (t + 1) * 64, Kb, Vb, tid);
            CP_COMMIT();
            CP_WAIT1();
        } else {
            CP_WAIT0();
        }
        __syncthreads();

        if (k0 <= wrow_lo + 15) {
            __half* sK = fsh + QTILE_E + st * 2 * KTILE_E;
            __half* sV = sK + KTILE_E;

            // ---- S = Q K^T (1 mma per pair) ----
            float s[8][4];
#pragma unroll
            for (int i = 0; i < 8; i++)
#pragma unroll
                for (int j = 0; j < 4; j++) s[i][j] = 0.f;

#pragma unroll
            for (int ks = 0; ks < 8; ks++) {
                uint32_t aoff = (uint32_t)((16 * w + a_row) * FSTR + ks * 16 + a_kof) * 2;
                uint32_t qf[4];
                ldmx4(qf, smem_u32(sQ) + aoff);
#pragma unroll
                for (int ng = 0; ng < 4; ng++) {
                    uint32_t boff = (uint32_t)((16 * ng + b_row) * FSTR + ks * 16 + b_kof) * 2;
                    uint32_t kf[4];
                    ldmx4(kf, smem_u32(sK) + boff);
                    mma16816h(s[2*ng],   qf, &kf[0]);
                    mma16816h(s[2*ng+1], qf, &kf[2]);
                }
            }

            // ---- causal mask (boundary tiles only) ----
            if (k0 + 63 > wrow_lo) {
                int grow0 = wrow_lo + r0;
                int grow1 = grow0 + 8;
#pragma unroll
                for (int nt = 0; nt < 8; nt++) {
                    int col = k0 + nt * 8 + (l & 3) * 2;
                    if (col > grow0)     s[nt][0] = MASKV;
                    if (col + 1 > grow0) s[nt][1] = MASKV;
                    if (col > grow1)     s[nt][2] = MASKV;
                    if (col + 1 > grow1) s[nt][3] = MASKV;
                }
            }

            // ---- online softmax ----
            float rm0 = MASKV, rm1 = MASKV;
#pragma unroll
            for (int nt = 0; nt < 8; nt++) {
                rm0 = fmaxf(rm0, fmaxf(s[nt][0], s[nt][1]));
                rm1 = fmaxf(rm1, fmaxf(s[nt][2], s[nt][3]));
            }
            rm0 = fmaxf(rm0, __shfl_xor_sync(0xffffffffu, rm0, 1));
            rm0 = fmaxf(rm0, __shfl_xor_sync(0xffffffffu, rm0, 2));
            rm1 = fmaxf(rm1, __shfl_xor_sync(0xffffffffu, rm1, 1));
            rm1 = fmaxf(rm1, __shfl_xor_sync(0xffffffffu, rm1, 2));

            float mn0 = fmaxf(mrow[0], rm0);
            float mn1 = fmaxf(mrow[1], rm1);
            float alpha0 = fexp(mrow[0] - mn0);
            float alpha1 = fexp(mrow[1] - mn1);
            mrow[0] = mn0; mrow[1] = mn1;

            float rs0 = 0.f, rs1 = 0.f;
#pragma unroll
            for (int nt = 0; nt < 8; nt++) {
                s[nt][0] = fexp(s[nt][0] - mn0);
                s[nt][1] = fexp(s[nt][1] - mn0);
                s[nt][2] = fexp(s[nt][2] - mn1);
                s[nt][3] = fexp(s[nt][3] - mn1);
                rs0 += s[nt][0] + s[nt][1];
                rs1 += s[nt][2] + s[nt][3];
            }
            rs0 += __shfl_xor_sync(0xffffffffu, rs0, 1);
            rs0 += __shfl_xor_sync(0xffffffffu, rs0, 2);
            rs1 += __shfl_xor_sync(0xffffffffu, rs1, 1);
            rs1 += __shfl_xor_sync(0xffffffffu, rs1, 2);
            lrow[0] = lrow[0] * alpha0 + rs0;
            lrow[1] = lrow[1] * alpha1 + rs1;

#pragma unroll
            for (int nt = 0; nt < 16; nt++) {
                o[nt][0] *= alpha0; o[nt][1] *= alpha0;
                o[nt][2] *= alpha1; o[nt][3] *= alpha1;
            }

            // ---- O += P V (P single fp16 in regs) ----
#pragma unroll
            for (int ks = 0; ks < 4; ks++) {
                uint32_t pa[4];
                pa[0] = packh(s[2*ks][0],   s[2*ks][1]);
                pa[1] = packh(s[2*ks][2],   s[2*ks][3]);
                pa[2] = packh(s[2*ks+1][0], s[2*ks+1][1]);
                pa[3] = packh(s[2*ks+1][2], s[2*ks+1][3]);
#pragma unroll
                for (int dg = 0; dg < 8; dg++) {
                    uint32_t voff = (uint32_t)((ks * 16 + v_row) * FSTR + dg * 16 + v_cof) * 2;
                    uint32_t vf[4];
                    ldmx4t(vf, smem_u32(sV) + voff);
                    mma16816h(o[2*dg],   pa, &vf[0]);
                    mma16816h(o[2*dg+1], pa, &vf[2]);
                }
            }
        }
        __syncthreads();
    }

    // ---- epilogue: normalize, single fp16 out ----
    float inv0 = 1.f / lrow[0];
    float inv1 = 1.f / lrow[1];
    size_t row0 = (size_t)b * S_ + q0 + 16 * w + r0;
    size_t row1 = row0 + 8;
    int colb = h * D_ + (l & 3) * 2;
#pragma unroll
    for (int nt = 0; nt < 16; nt++) {
        int col = colb + nt * 8;
        *(uint32_t*)(O16 + row0 * (H_*D_) + col) = packh(o[nt][0] * inv0, o[nt][1] * inv0);
        *(uint32_t*)(O16 + row1 * (H_*D_) + col) = packh(o[nt][2] * inv1, o[nt][3] * inv1);
    }
}

// ---------------- launcher ---------------------------------------------------
static void launch_split(const float* src, __nv_bfloat16* hi, __nv_bfloat16* lo, int n)
{
    int n4 = n / 4;
    split_bf16_kernel<<<(n4 + 255) / 256, 256>>>(src, hi, lo, n4);
}

extern "C" void kernel_launch(void* const* d_in, const int* in_sizes, int n_in,
                              void* d_out, int out_size)
{
    const float* hidden   = (const float*)d_in[0];
    const float* cosb     = (const float*)d_in[1];
    const float* sinb     = (const float*)d_in[2];
    const float* q_w      = (const float*)d_in[3];
    const float* k_w      = (const float*)d_in[4];
    const float* v_w      = (const float*)d_in[5];
    const float* o_w      = (const float*)d_in[6];
    const float* q_norm_w = (const float*)d_in[7];
    const float* k_norm_w = (const float*)d_in[8];
    float* out = (float*)d_out;

    float* pqkv;
    cudaGetSymbolAddress((void**)&pqkv, g_qkv);

    __nv_bfloat16 *hidh, *hidl, *wh, *wl;
    __half *ow16, *at16;
    cudaGetSymbolAddress((void**)&hidh, g_hid_h); cudaGetSymbolAddress((void**)&hidl, g_hid_l);
    cudaGetSymbolAddress((void**)&wh,   g_w_h);   cudaGetSymbolAddress((void**)&wl,   g_w_l);
    cudaGetSymbolAddress((void**)&ow16, g_ow16);
    cudaGetSymbolAddress((void**)&at16, g_at16);

    cudaFuncSetAttribute(gemm_mma,  cudaFuncAttributeMaxDynamicSharedMemorySize, GEMM_SMEM);
    cudaFuncSetAttribute(gemm_ff,   cudaFuncAttributeMaxDynamicSharedMemorySize, GEMM_SMEM2);
    cudaFuncSetAttribute(flash_mma, cudaFuncAttributeMaxDynamicSharedMemorySize, FLASH_SMEM);

    // 1) converts
    launch_split(hidden, hidh, hidl, MTOK * HID_);
    launch_split(q_w, wh,                     wl,                     H_*D_*HID_);
    launch_split(k_w, wh + (size_t)2048*HID_, wl + (size_t)2048*HID_, KV_*D_*HID_);
    launch_split(v_w, wh + (size_t)3072*HID_, wl + (size_t)3072*HID_, KV_*D_*HID_);
    conv_fp16_kernel<<<(HID_*H_*D_/4 + 255)/256, 256>>>(o_w, ow16, HID_*H_*D_/4);

    // 2) fused QKV projection (bf16x3 — proven path)
    gemm_mma<<<dim3(NQKV/128, MTOK/128), 256, GEMM_SMEM>>>(hidh, hidl, wh, wl, pqkv, NQKV, HID_);

    // 3) RMSNorm + mrope -> single fp16 Q/K/V (Q pre-scaled by 1/sqrt(D))
    norm_rope_kernel<<<MTOK, 256>>>(cosb, sinb, q_norm_w, k_norm_w);

    // 4) flash attention: QK 1-mma, PV 1-mma, 2 CTAs/SM
    flash_mma<<<dim3(S_ / 128, H_, B_), 256, FLASH_SMEM>>>(at16);

    // 5) O-projection (plain fp16, 1-mma) -> d_out
    gemm_ff<<<dim3(HID_/128, MTOK/128), 256, GEMM_SMEM2>>>(at16, ow16, out, HID_, H_*D_);
}

// round 12
// speedup vs baseline: 1.6822x; 1.1095x over previous
#include <cuda_runtime.h>
#include <cuda_bf16.h>
#include <cuda_fp16.h>
#include <math.h>
#include <stdint.h>

// Problem constants
#define B_   2
#define S_   2048
#define HID_ 2048
#define H_   16
#define KV_  8
#define D_   128
#define MTOK (B_*S_)   // 4096 tokens
#define NQKV 4096

// ---------------- scratch (device globals) ----------------------------------
__device__ float g_qkv[MTOK * NQKV];   // fused QKV projection output

__device__ __nv_bfloat16 g_hid_h[MTOK*HID_],  g_hid_l[MTOK*HID_];
__device__ __nv_bfloat16 g_w_h [NQKV*HID_],   g_w_l [NQKV*HID_];   // q|k|v weights concat
__device__ __half        g_ow16[HID_*H_*D_];                        // o_w fp16

// roped/normed operands for flash (single fp16), [B,H|KV,S,D]
__device__ __half g_q16[B_*H_*S_*D_];
__device__ __half g_k16[B_*KV_*S_*D_];
__device__ __half g_v16[B_*KV_*S_*D_];
// attention output (single fp16), [B*S, H*D]
__device__ __half g_at16[MTOK*H_*D_];

// ======================= PTX helpers (sm_80-era) ===========================
__device__ __forceinline__ uint32_t smem_u32(const void* p) {
    return (uint32_t)__cvta_generic_to_shared(p);
}
__device__ __forceinline__ void cpasync16(uint32_t dst, const void* src) {
    asm volatile("cp.async.cg.shared.global [%0], [%1], 16;" :: "r"(dst), "l"(src));
}
#define CP_COMMIT() asm volatile("cp.async.commit_group;" ::: "memory")
#define CP_WAIT1()  asm volatile("cp.async.wait_group 1;" ::: "memory")
#define CP_WAIT0()  asm volatile("cp.async.wait_group 0;" ::: "memory")

__device__ __forceinline__ void ldmx4(uint32_t* r, uint32_t addr) {
    asm volatile("ldmatrix.sync.aligned.m8n8.x4.shared.b16 {%0,%1,%2,%3}, [%4];"
                 : "=r"(r[0]), "=r"(r[1]), "=r"(r[2]), "=r"(r[3]) : "r"(addr));
}
__device__ __forceinline__ void ldmx4t(uint32_t* r, uint32_t addr) {
    asm volatile("ldmatrix.sync.aligned.m8n8.x4.trans.shared.b16 {%0,%1,%2,%3}, [%4];"
                 : "=r"(r[0]), "=r"(r[1]), "=r"(r[2]), "=r"(r[3]) : "r"(addr));
}
// bf16 mma
__device__ __forceinline__ void mma16816(float* d, const uint32_t* a, const uint32_t* b) {
    asm volatile("mma.sync.aligned.m16n8k16.row.col.f32.bf16.bf16.f32 "
                 "{%0,%1,%2,%3}, {%4,%5,%6,%7}, {%8,%9}, {%0,%1,%2,%3};"
                 : "+f"(d[0]), "+f"(d[1]), "+f"(d[2]), "+f"(d[3])
                 : "r"(a[0]), "r"(a[1]), "r"(a[2]), "r"(a[3]), "r"(b[0]), "r"(b[1]));
}
// fp16 mma
__device__ __forceinline__ void mma16816h(float* d, const uint32_t* a, const uint32_t* b) {
    asm volatile("mma.sync.aligned.m16n8k16.row.col.f32.f16.f16.f32 "
                 "{%0,%1,%2,%3}, {%4,%5,%6,%7}, {%8,%9}, {%0,%1,%2,%3};"
                 : "+f"(d[0]), "+f"(d[1]), "+f"(d[2]), "+f"(d[3])
                 : "r"(a[0]), "r"(a[1]), "r"(a[2]), "r"(a[3]), "r"(b[0]), "r"(b[1]));
}
__device__ __forceinline__ uint32_t packh(float x, float y) {
    __half2 t; t.x = __float2half_rn(x); t.y = __float2half_rn(y);
    return *(uint32_t*)&t;
}
__device__ __forceinline__ float fexp(float x) {
    return __expf(fmaxf(x, -80.0f));
}

// ======================= fp32 -> bf16 hi/lo split ==========================
__global__ __launch_bounds__(256)
void split_bf16_kernel(const float* __restrict__ src,
                       __nv_bfloat16* __restrict__ hi,
                       __nv_bfloat16* __restrict__ lo, int n4)
{
    int i = blockIdx.x * blockDim.x + threadIdx.x;
    if (i >= n4) return;
    float4 x = ((const float4*)src)[i];
    float xs[4] = {x.x, x.y, x.z, x.w};
    __nv_bfloat16 h[4], l[4];
#pragma unroll
    for (int j = 0; j < 4; j++) {
        h[j] = __float2bfloat16_rn(xs[j]);
        l[j] = __float2bfloat16_rn(xs[j] - __bfloat162float(h[j]));
    }
    __nv_bfloat162 h0; h0.x = h[0]; h0.y = h[1];
    __nv_bfloat162 h1; h1.x = h[2]; h1.y = h[3];
    __nv_bfloat162 l0; l0.x = l[0]; l0.y = l[1];
    __nv_bfloat162 l1; l1.x = l[2]; l1.y = l[3];
    ((__nv_bfloat162*)hi)[i*2 + 0] = h0;
    ((__nv_bfloat162*)hi)[i*2 + 1] = h1;
    ((__nv_bfloat162*)lo)[i*2 + 0] = l0;
    ((__nv_bfloat162*)lo)[i*2 + 1] = l1;
}

// ======================= fp32 -> fp16 single convert =======================
__global__ __launch_bounds__(256)
void conv_fp16_kernel(const float* __restrict__ src, __half* __restrict__ dst, int n4)
{
    int i = blockIdx.x * blockDim.x + threadIdx.x;
    if (i >= n4) return;
    float4 x = ((const float4*)src)[i];
    __half2 a; a.x = __float2half_rn(x.x); a.y = __float2half_rn(x.y);
    __half2 b; b.x = __float2half_rn(x.z); b.y = __float2half_rn(x.w);
    ((__half2*)dst)[i*2 + 0] = a;
    ((__half2*)dst)[i*2 + 1] = b;
}

// ======================= mma.sync bf16x3 GEMM (NT) — QKV ===================
// 2-stage double buffer, 2 CTAs/SM.
#define LDT   40
#define TILE_B (128*LDT*2)
#define STG_B  (4*TILE_B)
#define GEMM_SMEM (2*STG_B)   // 81920

__device__ __forceinline__ void load_stage(
    uint32_t sbase, int stg,
    const __nv_bfloat16* __restrict__ Ah, const __nv_bfloat16* __restrict__ Al,
    const __nv_bfloat16* __restrict__ Bh, const __nv_bfloat16* __restrict__ Bl,
    int m0, int n0, int K, int k0, int tid)
{
    uint32_t sd = sbase + stg * STG_B;
#pragma unroll
    for (int i = 0; i < 8; i++) {
        int chunk = i * 256 + tid;
        int tile  = chunk >> 9;
        int idx   = chunk & 511;
        int row   = idx >> 2;
        int cseg  = idx & 3;
        const __nv_bfloat16* g = (tile == 0) ? Ah : (tile == 1) ? Al : (tile == 2) ? Bh : Bl;
        int grow = ((tile < 2) ? m0 : n0) + row;
        const char* src = (const char*)(g + (size_t)grow * K + k0) + cseg * 16;
        cpasync16(sd + tile * TILE_B + row * 80 + cseg * 16, src);
    }
}

__global__ __launch_bounds__(256, 2)
void gemm_mma(const __nv_bfloat16* __restrict__ Ah, const __nv_bfloat16* __restrict__ Al,
              const __nv_bfloat16* __restrict__ Bh, const __nv_bfloat16* __restrict__ Bl,
              float* __restrict__ C, int N, int K)
{
    extern __shared__ char dsm[];
    const uint32_t sb = smem_u32(dsm);
    const int tid = threadIdx.x;
    const int w = tid >> 5;
    const int l = tid & 31;
    const int wm = (w >> 2) * 64;
    const int wn = (w & 3) * 32;
    const int m0 = blockIdx.y * 128;
    const int n0 = blockIdx.x * 128;
    const int kiters = K / 32;

    load_stage(sb, 0, Ah, Al, Bh, Bl, m0, n0, K, 0, tid);  CP_COMMIT();
    load_stage(sb, 1, Ah, Al, Bh, Bl, m0, n0, K, 32, tid); CP_COMMIT();

    float acc[16][4];
#pragma unroll
    for (int i = 0; i < 16; i++)
#pragma unroll
        for (int j = 0; j < 4; j++) acc[i][j] = 0.f;

    const int a_row = (l & 15);
    const int a_kof = (l >> 4) * 8;
    const int b_row = (l & 7) + ((l >> 4) & 1) * 8;
    const int b_kof = ((l >> 3) & 1) * 8;

    for (int kt = 0; kt < kiters; kt++) {
        CP_WAIT1();
        __syncthreads();
        const uint32_t st = sb + (kt & 1) * STG_B;
        const uint32_t sAh = st;
        const uint32_t sAl = st + TILE_B;
        const uint32_t sBh = st + 2 * TILE_B;
        const uint32_t sBl = st + 3 * TILE_B;

#pragma unroll
        for (int ks = 0; ks < 2; ks++) {
            const int kbase = ks * 16;
            uint32_t ah[4][4], al[4][4], bh[2][4], bl[2][4];
#pragma unroll
            for (int mi = 0; mi < 4; mi++) {
                uint32_t off = (uint32_t)((wm + mi * 16 + a_row) * 80 + (kbase + a_kof) * 2);
                ldmx4(ah[mi], sAh + off);
                ldmx4(al[mi], sAl + off);
            }
#pragma unroll
            for (int ni2 = 0; ni2 < 2; ni2++) {
                uint32_t off = (uint32_t)((wn + ni2 * 16 + b_row) * 80 + (kbase + b_kof) * 2);
                ldmx4(bh[ni2], sBh + off);
                ldmx4(bl[ni2], sBl + off);
            }
#pragma unroll
            for (int mi = 0; mi < 4; mi++) {
#pragma unroll
                for (int ni = 0; ni < 4; ni++) {
                    const uint32_t* bhp = &bh[ni >> 1][(ni & 1) * 2];
                    const uint32_t* blp = &bl[ni >> 1][(ni & 1) * 2];
                    mma16816(acc[mi * 4 + ni], ah[mi], bhp);
                    mma16816(acc[mi * 4 + ni], al[mi], bhp);
                    mma16816(acc[mi * 4 + ni], ah[mi], blp);
                }
            }
        }
        __syncthreads();
        if (kt + 2 < kiters)
            load_stage(sb, kt & 1, Ah, Al, Bh, Bl, m0, n0, K, (kt + 2) * 32, tid);
        CP_COMMIT();
    }

#pragma unroll
    for (int mi = 0; mi < 4; mi++) {
#pragma unroll
        for (int ni = 0; ni < 4; ni++) {
            int row = m0 + wm + mi * 16 + (l >> 2);
            int col = n0 + wn + ni * 8 + (l & 3) * 2;
            float* c = C + (size_t)row * N + col;
            float2 v0; v0.x = acc[mi * 4 + ni][0]; v0.y = acc[mi * 4 + ni][1];
            float2 v1; v1.x = acc[mi * 4 + ni][2]; v1.y = acc[mi * 4 + ni][3];
            *(float2*)c = v0;
            *(float2*)(c + 8 * (size_t)N) = v1;
        }
    }
}

// ======================= plain fp16 GEMM (single x single) — O-proj ========
#define STG_B2 (2*TILE_B)
#define GEMM_SMEM2 (3*STG_B2)

__device__ __forceinline__ void load_stage2(
    uint32_t sbase, int stg,
    const __half* __restrict__ As, const __half* __restrict__ Bs,
    int m0, int n0, int K, int k0, int tid)
{
    uint32_t sd = sbase + stg * STG_B2;
#pragma unroll
    for (int i = 0; i < 4; i++) {
        int chunk = i * 256 + tid;
        int tile  = chunk >> 9;
        int idx   = chunk & 511;
        int row   = idx >> 2;
        int cseg  = idx & 3;
        const __half* g = (tile == 0) ? As : Bs;
        int grow = ((tile == 0) ? m0 : n0) + row;
        const char* src = (const char*)(g + (size_t)grow * K + k0) + cseg * 16;
        cpasync16(sd + tile * TILE_B + row * 80 + cseg * 16, src);
    }
}

__global__ __launch_bounds__(256, 2)
void gemm_ff(const __half* __restrict__ As, const __half* __restrict__ Bs,
             float* __restrict__ C, int N, int K)
{
    extern __shared__ char dsm[];
    const uint32_t sb = smem_u32(dsm);
    const int tid = threadIdx.x;
    const int w = tid >> 5;
    const int l = tid & 31;
    const int wm = (w >> 2) * 64;
    const int wn = (w & 3) * 32;
    const int m0 = blockIdx.y * 128;
    const int n0 = blockIdx.x * 128;
    const int kiters = K / 32;

    load_stage2(sb, 0, As, Bs, m0, n0, K, 0, tid);  CP_COMMIT();
    load_stage2(sb, 1, As, Bs, m0, n0, K, 32, tid); CP_COMMIT();

    float acc[16][4];
#pragma unroll
    for (int i = 0; i < 16; i++)
#pragma unroll
        for (int j = 0; j < 4; j++) acc[i][j] = 0.f;

    const int a_row = (l & 15);
    const int a_kof = (l >> 4) * 8;
    const int b_row = (l & 7) + ((l >> 4) & 1) * 8;
    const int b_kof = ((l >> 3) & 1) * 8;

    for (int kt = 0; kt < kiters; kt++) {
        CP_WAIT1();
        __syncthreads();
        const uint32_t st = sb + (kt % 3) * STG_B2;
        const uint32_t sA = st;
        const uint32_t sB = st + TILE_B;

#pragma unroll
        for (int ks = 0; ks < 2; ks++) {
            const int kbase = ks * 16;
            uint32_t af[4][4], bf[2][4];
#pragma unroll
            for (int mi = 0; mi < 4; mi++) {
                uint32_t off = (uint32_t)((wm + mi * 16 + a_row) * 80 + (kbase + a_kof) * 2);
                ldmx4(af[mi], sA + off);
            }
#pragma unroll
            for (int ni2 = 0; ni2 < 2; ni2++) {
                uint32_t off = (uint32_t)((wn + ni2 * 16 + b_row) * 80 + (kbase + b_kof) * 2);
                ldmx4(bf[ni2], sB + off);
            }
#pragma unroll
            for (int mi = 0; mi < 4; mi++) {
#pragma unroll
                for (int ni = 0; ni < 4; ni++) {
                    const uint32_t* bp = &bf[ni >> 1][(ni & 1) * 2];
                    mma16816h(acc[mi * 4 + ni], af[mi], bp);
                }
            }
        }
        __syncthreads();
        if (kt + 2 < kiters)
            load_stage2(sb, (kt + 2) % 3, As, Bs, m0, n0, K, (kt + 2) * 32, tid);
        CP_COMMIT();
    }

#pragma unroll
    for (int mi = 0; mi < 4; mi++) {
#pragma unroll
        for (int ni = 0; ni < 4; ni++) {
            int row = m0 + wm + mi * 16 + (l >> 2);
            int col = n0 + wn + ni * 8 + (l & 3) * 2;
            float* c = C + (size_t)row * N + col;
            float2 v0; v0.x = acc[mi * 4 + ni][0]; v0.y = acc[mi * 4 + ni][1];
            float2 v1; v1.x = acc[mi * 4 + ni][2]; v1.y = acc[mi * 4 + ni][3];
            *(float2*)c = v0;
            *(float2*)(c + 8 * (size_t)N) = v1;
        }
    }
}

// ---------------- RMSNorm + mrope -> single fp16 operands -------------------
__device__ __forceinline__ int mrope_axis(int d) {
    return d < 21 ? 0 : d < 42 ? 1 : d < 64 ? 2 : d < 85 ? 0 : d < 106 ? 1 : 2;
}

__global__ __launch_bounds__(256)
void norm_rope_kernel(const float* __restrict__ cosb, const float* __restrict__ sinb,
                      const float* __restrict__ qw,   const float* __restrict__ kw)
{
    const int m = blockIdx.x;
    const int b = m >> 11;
    const int s = m & (S_ - 1);
    const int warp = threadIdx.x >> 5;
    const int lane = threadIdx.x & 31;
    const float SC = 0.08838834764831845f;
    const float* tok = g_qkv + (size_t)m * NQKV;

#pragma unroll
    for (int it = 0; it < 4; it++) {
        int slot = warp + (it << 3);
        const float* src; const float* w; bool rope; float scale;
        __half* dh;
        if (slot < 16) {
            src = tok + slot * D_;
            dh = g_q16 + ((size_t)(b * H_ + slot) * S_ + s) * D_;
            w = qw; rope = true; scale = SC;
        } else if (slot < 24) {
            int hh = slot - 16;
            src = tok + 2048 + hh * D_;
            dh = g_k16 + ((size_t)(b * KV_ + hh) * S_ + s) * D_;
            w = kw; rope = true; scale = 1.f;
        } else {
            int hh = slot - 24;
            src = tok + 3072 + hh * D_;
            dh = g_v16 + ((size_t)(b * KV_ + hh) * S_ + s) * D_;
            w = nullptr; rope = false; scale = 1.f;
        }
        float4 x4 = *(const float4*)(src + lane * 4);
        float out[4] = {x4.x, x4.y, x4.z, x4.w};
        if (rope) {
            float x[4] = {out[0], out[1], out[2], out[3]};
            float ssum = x[0]*x[0] + x[1]*x[1] + x[2]*x[2] + x[3]*x[3];
#pragma unroll
            for (int o2 = 16; o2 > 0; o2 >>= 1)
                ssum += __shfl_xor_sync(0xffffffffu, ssum, o2);
            float r = rsqrtf(ssum * (1.0f / 128.0f) + 1e-6f);
            float4 w4 = *(const float4*)(w + lane * 4);
            float xn[4];
            xn[0] = x[0] * r * w4.x; xn[1] = x[1] * r * w4.y;
            xn[2] = x[2] * r * w4.z; xn[3] = x[3] * r * w4.w;
            float oth[4];
#pragma unroll
            for (int j = 0; j < 4; j++)
                oth[j] = __shfl_xor_sync(0xffffffffu, xn[j], 16);
            float sgn = (lane < 16) ? -1.f : 1.f;
            int dbase = lane * 4;
#pragma unroll
            for (int j = 0; j < 4; j++) {
                int d = dbase + j;
                int ax = mrope_axis(d);
                size_t ci = ((size_t)(ax * B_ + b) * S_ + s) * D_ + d;
                out[j] = (xn[j] * cosb[ci] + sgn * oth[j] * sinb[ci]) * scale;
            }
        }
        __half2* ph = (__half2*)(dh + lane * 4);
        __half2 t;
        t.x = __float2half_rn(out[0]); t.y = __float2half_rn(out[1]); ph[0] = t;
        t.x = __float2half_rn(out[2]); t.y = __float2half_rn(out[3]); ph[1] = t;
    }
}

// ---------------- causal GQA flash attention (fp16 single, 1-mma) -----------
#define FSTR 136
#define QTILE_E (128*FSTR)
#define KTILE_E (64*FSTR)
#define FLASH_SMEM ((QTILE_E + 4*KTILE_E)*2)   // 104448 bytes
#define MASKV (-30000.0f)

__device__ __forceinline__ void load_kv_stage(
    __half* fsb, int st, int k0,
    const __half* Kp, const __half* Vp, int tid)
{
    __half* kd = fsb + QTILE_E + st * 2 * KTILE_E;
    __half* vd = kd + KTILE_E;
#pragma unroll
    for (int i = 0; i < 4; i++) {
        int c = tid + i * 256;
        int r = c >> 4, cs = c & 15;
        size_t go = (size_t)(k0 + r) * D_ + cs * 8;
        uint32_t so = (uint32_t)(r * FSTR + cs * 8);
        cpasync16(smem_u32(kd + so), Kp + go);
        cpasync16(smem_u32(vd + so), Vp + go);
    }
}

__global__ __launch_bounds__(256, 2)
void flash_mma(__half* __restrict__ O16)
{
    extern __shared__ __half fsh[];
    __half* sQ = fsh;

    const int qt = (int)gridDim.x - 1 - (int)blockIdx.x;  // longest-first
    const int h = blockIdx.y, b = blockIdx.z;
    const int tid = threadIdx.x;
    const int w = tid >> 5;
    const int l = tid & 31;
    const int q0 = qt * 128;

    const __half* Qb = g_q16 + ((size_t)(b * H_ + h) * S_ + q0) * D_;
    const __half* Kb = g_k16 + (size_t)(b * KV_ + (h >> 1)) * S_ * D_;
    const __half* Vb = g_v16 + (size_t)(b * KV_ + (h >> 1)) * S_ * D_;

#pragma unroll
    for (int i = 0; i < 8; i++) {
        int c = tid + i * 256;
        int r = c >> 4, cs = c & 15;
        cpasync16(smem_u32(sQ + (uint32_t)(r * FSTR + cs * 8)), Qb + (size_t)r * D_ + cs * 8);
    }
    load_kv_stage(fsh, 0, 0, Kb, Vb, tid);
    CP_COMMIT();

    float o[16][4];
#pragma unroll
    for (int i = 0; i < 16; i++)
#pragma unroll
        for (int j = 0; j < 4; j++) o[i][j] = 0.f;
    float mrow[2] = {MASKV, MASKV};
    float lrow[2] = {0.f, 0.f};

    const int r0 = l >> 2;
    const int a_row = (l & 15);
    const int a_kof = (l >> 4) * 8;
    const int b_row = (l & 7) + ((l >> 4) & 1) * 8;
    const int b_kof = ((l >> 3) & 1) * 8;
    const int v_row = (l & 15);
    const int v_cof = (l >> 4) * 8;
    const int wrow_lo = q0 + 16 * w;
    const int ntiles = 2 * qt + 2;

    for (int t = 0; t < ntiles; t++) {
        const int k0 = t * 64;
        const int st = t & 1;
        if (t + 1 < ntiles) {
            load_kv_stage(fsh, st ^ 1, (t + 1) * 64, Kb, Vb, tid);
            CP_COMMIT();
            CP_WAIT1();
        } else {
            CP_WAIT0();
        }
        __syncthreads();

        if (k0 <= wrow_lo + 15) {
            __half* sK = fsh + QTILE_E + st * 2 * KTILE_E;
            __half* sV = sK + KTILE_E;

            float s[8][4];
#pragma unroll
            for (int i = 0; i < 8; i++)
#pragma unroll
                for (int j = 0; j < 4; j++) s[i][j] = 0.f;

#pragma unroll
            for (int ks = 0; ks < 8; ks++) {
                uint32_t aoff = (uint32_t)((16 * w + a_row) * FSTR + ks * 16 + a_kof) * 2;
                uint32_t qf[4];
                ldmx4(qf, smem_u32(sQ) + aoff);
#pragma unroll
                for (int ng = 0; ng < 4; ng++) {
                    uint32_t boff = (uint32_t)((16 * ng + b_row) * FSTR + ks * 16 + b_kof) * 2;
                    uint32_t kf[4];
                    ldmx4(kf, smem_u32(sK) + boff);
                    mma16816h(s[2*ng],   qf, &kf[0]);
                    mma16816h(s[2*ng+1], qf, &kf[2]);
                }
            }

            if (k0 + 63 > wrow_lo) {
                int grow0 = wrow_lo + r0;
                int grow1 = grow0 + 8;
#pragma unroll
                for (int nt = 0; nt < 8; nt++) {
                    int col = k0 + nt * 8 + (l & 3) * 2;
                    if (col > grow0)     s[nt][0] = MASKV;
                    if (col + 1 > grow0) s[nt][1] = MASKV;
                    if (col > grow1)     s[nt][2] = MASKV;
                    if (col + 1 > grow1) s[nt][3] = MASKV;
                }
            }

            float rm0 = MASKV, rm1 = MASKV;
#pragma unroll
            for (int nt = 0; nt < 8; nt++) {
                rm0 = fmaxf(rm0, fmaxf(s[nt][0], s[nt][1]));
                rm1 = fmaxf(rm1, fmaxf(s[nt][2], s[nt][3]));
            }
            rm0 = fmaxf(rm0, __shfl_xor_sync(0xffffffffu, rm0, 1));
            rm0 = fmaxf(rm0, __shfl_xor_sync(0xffffffffu, rm0, 2));
            rm1 = fmaxf(rm1, __shfl_xor_sync(0xffffffffu, rm1, 1));
            rm1 = fmaxf(rm1, __shfl_xor_sync(0xffffffffu, rm1, 2));

            float mn0 = fmaxf(mrow[0], rm0);
            float mn1 = fmaxf(mrow[1], rm1);
            float alpha0 = fexp(mrow[0] - mn0);
            float alpha1 = fexp(mrow[1] - mn1);
            mrow[0] = mn0; mrow[1] = mn1;

            float rs0 = 0.f, rs1 = 0.f;
#pragma unroll
            for (int nt = 0; nt < 8; nt++) {
                s[nt][0] = fexp(s[nt][0] - mn0);
                s[nt][1] = fexp(s[nt][1] - mn0);
                s[nt][2] = fexp(s[nt][2] - mn1);
                s[nt][3] = fexp(s[nt][3] - mn1);
                rs0 += s[nt][0] + s[nt][1];
                rs1 += s[nt][2] + s[nt][3];
            }
            rs0 += __shfl_xor_sync(0xffffffffu, rs0, 1);
            rs0 += __shfl_xor_sync(0xffffffffu, rs0, 2);
            rs1 += __shfl_xor_sync(0xffffffffu, rs1, 1);
            rs1 += __shfl_xor_sync(0xffffffffu, rs1, 2);
            lrow[0] = lrow[0] * alpha0 + rs0;
            lrow[1] = lrow[1] * alpha1 + rs1;

#pragma unroll
            for (int nt = 0; nt < 16; nt++) {
                o[nt][0] *= alpha0; o[nt][1] *= alpha0;
                o[nt][2] *= alpha1; o[nt][3] *= alpha1;
            }

#pragma unroll
            for (int ks = 0; ks < 4; ks++) {
                uint32_t pa[4];
                pa[0] = packh(s[2*ks][0],   s[2*ks][1]);
                pa[1] = packh(s[2*ks][2],   s[2*ks][3]);
                pa[2] = packh(s[2*ks+1][0], s[2*ks+1][1]);
                pa[3] = packh(s[2*ks+1][2], s[2*ks+1][3]);
#pragma unroll
                for (int dg = 0; dg < 8; dg++) {
                    uint32_t voff = (uint32_t)((ks * 16 + v_row) * FSTR + dg * 16 + v_cof) * 2;
                    uint32_t vf[4];
                    ldmx4t(vf, smem_u32(sV) + voff);
                    mma16816h(o[2*dg],   pa, &vf[0]);
                    mma16816h(o[2*dg+1], pa, &vf[2]);
                }
            }
        }
        __syncthreads();
    }

    float inv0 = 1.f / lrow[0];
    float inv1 = 1.f / lrow[1];
    size_t row0 = (size_t)b * S_ + q0 + 16 * w + r0;
    size_t row1 = row0 + 8;
    int colb = h * D_ + (l & 3) * 2;
#pragma unroll
    for (int nt = 0; nt < 16; nt++) {
        int col = colb + nt * 8;
        *(uint32_t*)(O16 + row0 * (H_*D_) + col) = packh(o[nt][0] * inv0, o[nt][1] * inv0);
        *(uint32_t*)(O16 + row1 * (H_*D_) + col) = packh(o[nt][2] * inv1, o[nt][3] * inv1);
    }
}

// ---------------- launcher ---------------------------------------------------
static void launch_split(const float* src, __nv_bfloat16* hi, __nv_bfloat16* lo, int n)
{
    int n4 = n / 4;
    split_bf16_kernel<<<(n4 + 255) / 256, 256>>>(src, hi, lo, n4);
}

extern "C" void kernel_launch(void* const* d_in, const int* in_sizes, int n_in,
                              void* d_out, int out_size)
{
    const float* hidden   = (const float*)d_in[0];
    const float* cosb     = (const float*)d_in[1];
    const float* sinb     = (const float*)d_in[2];
    const float* q_w      = (const float*)d_in[3];
    const float* k_w      = (const float*)d_in[4];
    const float* v_w      = (const float*)d_in[5];
    const float* o_w      = (const float*)d_in[6];
    const float* q_norm_w = (const float*)d_in[7];
    const float* k_norm_w = (const float*)d_in[8];
    float* out = (float*)d_out;

    float* pqkv;
    cudaGetSymbolAddress((void**)&pqkv, g_qkv);

    __nv_bfloat16 *hidh, *hidl, *wh, *wl;
    __half *ow16, *at16;
    cudaGetSymbolAddress((void**)&hidh, g_hid_h); cudaGetSymbolAddress((void**)&hidl, g_hid_l);
    cudaGetSymbolAddress((void**)&wh,   g_w_h);   cudaGetSymbolAddress((void**)&wl,   g_w_l);
    cudaGetSymbolAddress((void**)&ow16, g_ow16);
    cudaGetSymbolAddress((void**)&at16, g_at16);

    cudaFuncSetAttribute(gemm_mma,  cudaFuncAttributeMaxDynamicSharedMemorySize, GEMM_SMEM);
    cudaFuncSetAttribute(gemm_ff,   cudaFuncAttributeMaxDynamicSharedMemorySize, GEMM_SMEM2);
    cudaFuncSetAttribute(flash_mma, cudaFuncAttributeMaxDynamicSharedMemorySize, FLASH_SMEM);

    // 1) converts
    launch_split(hidden, hidh, hidl, MTOK * HID_);
    launch_split(q_w, wh,                     wl,                     H_*D_*HID_);
    launch_split(k_w, wh + (size_t)2048*HID_, wl + (size_t)2048*HID_, KV_*D_*HID_);
    launch_split(v_w, wh + (size_t)3072*HID_, wl + (size_t)3072*HID_, KV_*D_*HID_);
    conv_fp16_kernel<<<(HID_*H_*D_/4 + 255)/256, 256>>>(o_w, ow16, HID_*H_*D_/4);

    // 2) fused QKV projection (bf16x3, 2-stage pipe, 2 CTAs/SM)
    gemm_mma<<<dim3(NQKV/128, MTOK/128), 256, GEMM_SMEM>>>(hidh, hidl, wh, wl, pqkv, NQKV, HID_);

    // 3) RMSNorm + mrope -> single fp16 Q/K/V (Q pre-scaled by 1/sqrt(D))
    norm_rope_kernel<<<MTOK, 256>>>(cosb, sinb, q_norm_w, k_norm_w);

    // 4) flash attention: QK 1-mma, PV 1-mma, 2 CTAs/SM
    flash_mma<<<dim3(S_ / 128, H_, B_), 256, FLASH_SMEM>>>(at16);

    // 5) O-projection (plain fp16, 1-mma) -> d_out
    gemm_ff<<<dim3(HID_/128, MTOK/128), 256, GEMM_SMEM2>>>(at16, ow16, out, HID_, H_*D_);
}

// round 13
// speedup vs baseline: 2.0607x; 1.2250x over previous
#include <cuda_runtime.h>
#include <cuda_bf16.h>
#include <cuda_fp16.h>
#include <math.h>
#include <stdint.h>

// Problem constants
#define B_   2
#define S_   2048
#define HID_ 2048
#define H_   16
#define KV_  8
#define D_   128
#define MTOK (B_*S_)   // 4096 tokens
#define NQKV 4096

// ---------------- scratch (device globals) ----------------------------------
__device__ float g_qkv[MTOK * NQKV];   // fused QKV projection output

__device__ __half g_hid_h[MTOK*HID_], g_hid_l[MTOK*HID_];  // hidden fp16 hi/lo
__device__ __half g_w16 [NQKV*HID_];                        // q|k|v weights fp16
__device__ __half g_ow16[HID_*H_*D_];                       // o_w fp16

// roped/normed operands for flash (single fp16), [B,H|KV,S,D]
__device__ __half g_q16[B_*H_*S_*D_];
__device__ __half g_k16[B_*KV_*S_*D_];
__device__ __half g_v16[B_*KV_*S_*D_];
// attention output (single fp16), [B*S, H*D]
__device__ __half g_at16[MTOK*H_*D_];

// ======================= PTX helpers (sm_80-era) ===========================
__device__ __forceinline__ uint32_t smem_u32(const void* p) {
    return (uint32_t)__cvta_generic_to_shared(p);
}
__device__ __forceinline__ void cpasync16(uint32_t dst, const void* src) {
    asm volatile("cp.async.cg.shared.global [%0], [%1], 16;" :: "r"(dst), "l"(src));
}
#define CP_COMMIT() asm volatile("cp.async.commit_group;" ::: "memory")
#define CP_WAIT1()  asm volatile("cp.async.wait_group 1;" ::: "memory")
#define CP_WAIT0()  asm volatile("cp.async.wait_group 0;" ::: "memory")

__device__ __forceinline__ void ldmx4(uint32_t* r, uint32_t addr) {
    asm volatile("ldmatrix.sync.aligned.m8n8.x4.shared.b16 {%0,%1,%2,%3}, [%4];"
                 : "=r"(r[0]), "=r"(r[1]), "=r"(r[2]), "=r"(r[3]) : "r"(addr));
}
__device__ __forceinline__ void ldmx4t(uint32_t* r, uint32_t addr) {
    asm volatile("ldmatrix.sync.aligned.m8n8.x4.trans.shared.b16 {%0,%1,%2,%3}, [%4];"
                 : "=r"(r[0]), "=r"(r[1]), "=r"(r[2]), "=r"(r[3]) : "r"(addr));
}
// fp16 mma
__device__ __forceinline__ void mma16816h(float* d, const uint32_t* a, const uint32_t* b) {
    asm volatile("mma.sync.aligned.m16n8k16.row.col.f32.f16.f16.f32 "
                 "{%0,%1,%2,%3}, {%4,%5,%6,%7}, {%8,%9}, {%0,%1,%2,%3};"
                 : "+f"(d[0]), "+f"(d[1]), "+f"(d[2]), "+f"(d[3])
                 : "r"(a[0]), "r"(a[1]), "r"(a[2]), "r"(a[3]), "r"(b[0]), "r"(b[1]));
}
__device__ __forceinline__ uint32_t packh(float x, float y) {
    __half2 t; t.x = __float2half_rn(x); t.y = __float2half_rn(y);
    return *(uint32_t*)&t;
}
__device__ __forceinline__ float fexp(float x) {
    return __expf(fmaxf(x, -80.0f));
}

// ======================= fp32 -> fp16 hi/lo split ==========================
__global__ __launch_bounds__(256)
void split_fp16_kernel(const float* __restrict__ src,
                       __half* __restrict__ hi, __half* __restrict__ lo, int n4)
{
    int i = blockIdx.x * blockDim.x + threadIdx.x;
    if (i >= n4) return;
    float4 x = ((const float4*)src)[i];
    float xs[4] = {x.x, x.y, x.z, x.w};
    __half h[4], l[4];
#pragma unroll
    for (int j = 0; j < 4; j++) {
        h[j] = __float2half_rn(xs[j]);
        l[j] = __float2half_rn(xs[j] - __half2float(h[j]));
    }
    __half2 h0; h0.x = h[0]; h0.y = h[1];
    __half2 h1; h1.x = h[2]; h1.y = h[3];
    __half2 l0; l0.x = l[0]; l0.y = l[1];
    __half2 l1; l1.x = l[2]; l1.y = l[3];
    ((__half2*)hi)[i*2 + 0] = h0;
    ((__half2*)hi)[i*2 + 1] = h1;
    ((__half2*)lo)[i*2 + 0] = l0;
    ((__half2*)lo)[i*2 + 1] = l1;
}

// ======================= fp32 -> fp16 single convert =======================
__global__ __launch_bounds__(256)
void conv_fp16_kernel(const float* __restrict__ src, __half* __restrict__ dst, int n4)
{
    int i = blockIdx.x * blockDim.x + threadIdx.x;
    if (i >= n4) return;
    float4 x = ((const float4*)src)[i];
    __half2 a; a.x = __float2half_rn(x.x); a.y = __float2half_rn(x.y);
    __half2 b; b.x = __float2half_rn(x.z); b.y = __float2half_rn(x.w);
    ((__half2*)dst)[i*2 + 0] = a;
    ((__half2*)dst)[i*2 + 1] = b;
}

// ======================= fp16 asym GEMM (A hi/lo x B single, NT) ===========
// QKV projection: 2 MMAs per pair, 2-stage pipe, 2 CTAs/SM.
#define LDT   40
#define TILE_B (128*LDT*2)
#define STG_B3 (3*TILE_B)
#define GEMM_SMEM3 (2*STG_B3)   // 61440 -> 2 CTAs/SM

__device__ __forceinline__ void load_stage3(
    uint32_t sbase, int stg,
    const __half* __restrict__ Ah, const __half* __restrict__ Al,
    const __half* __restrict__ Bs,
    int m0, int n0, int K, int k0, int tid)
{
    uint32_t sd = sbase + stg * STG_B3;
#pragma unroll
    for (int i = 0; i < 6; i++) {
        int chunk = i * 256 + tid;
        int tile  = chunk >> 9;         // 0..2
        int idx   = chunk & 511;
        int row   = idx >> 2;
        int cseg  = idx & 3;
        const __half* g = (tile == 0) ? Ah : (tile == 1) ? Al : Bs;
        int grow = ((tile < 2) ? m0 : n0) + row;
        const char* src = (const char*)(g + (size_t)grow * K + k0) + cseg * 16;
        cpasync16(sd + tile * TILE_B + row * 80 + cseg * 16, src);
    }
}

__global__ __launch_bounds__(256, 2)
void gemm_asym(const __half* __restrict__ Ah, const __half* __restrict__ Al,
               const __half* __restrict__ Bs,
               float* __restrict__ C, int N, int K)
{
    extern __shared__ char dsm[];
    const uint32_t sb = smem_u32(dsm);
    const int tid = threadIdx.x;
    const int w = tid >> 5;
    const int l = tid & 31;
    const int wm = (w >> 2) * 64;
    const int wn = (w & 3) * 32;
    const int m0 = blockIdx.y * 128;
    const int n0 = blockIdx.x * 128;
    const int kiters = K / 32;

    load_stage3(sb, 0, Ah, Al, Bs, m0, n0, K, 0, tid);  CP_COMMIT();
    load_stage3(sb, 1, Ah, Al, Bs, m0, n0, K, 32, tid); CP_COMMIT();

    float acc[16][4];
#pragma unroll
    for (int i = 0; i < 16; i++)
#pragma unroll
        for (int j = 0; j < 4; j++) acc[i][j] = 0.f;

    const int a_row = (l & 15);
    const int a_kof = (l >> 4) * 8;
    const int b_row = (l & 7) + ((l >> 4) & 1) * 8;
    const int b_kof = ((l >> 3) & 1) * 8;

    for (int kt = 0; kt < kiters; kt++) {
        CP_WAIT1();
        __syncthreads();
        const uint32_t st = sb + (kt & 1) * STG_B3;
        const uint32_t sAh = st;
        const uint32_t sAl = st + TILE_B;
        const uint32_t sBs = st + 2 * TILE_B;

#pragma unroll
        for (int ks = 0; ks < 2; ks++) {
            const int kbase = ks * 16;
            uint32_t ah[4][4], al[4][4], bh[2][4];
#pragma unroll
            for (int mi = 0; mi < 4; mi++) {
                uint32_t off = (uint32_t)((wm + mi * 16 + a_row) * 80 + (kbase + a_kof) * 2);
                ldmx4(ah[mi], sAh + off);
                ldmx4(al[mi], sAl + off);
            }
#pragma unroll
            for (int ni2 = 0; ni2 < 2; ni2++) {
                uint32_t off = (uint32_t)((wn + ni2 * 16 + b_row) * 80 + (kbase + b_kof) * 2);
                ldmx4(bh[ni2], sBs + off);
            }
#pragma unroll
            for (int mi = 0; mi < 4; mi++) {
#pragma unroll
                for (int ni = 0; ni < 4; ni++) {
                    const uint32_t* bp = &bh[ni >> 1][(ni & 1) * 2];
                    mma16816h(acc[mi * 4 + ni], ah[mi], bp);
                    mma16816h(acc[mi * 4 + ni], al[mi], bp);
                }
            }
        }
        __syncthreads();
        if (kt + 2 < kiters)
            load_stage3(sb, kt & 1, Ah, Al, Bs, m0, n0, K, (kt + 2) * 32, tid);
        CP_COMMIT();
    }

#pragma unroll
    for (int mi = 0; mi < 4; mi++) {
#pragma unroll
        for (int ni = 0; ni < 4; ni++) {
            int row = m0 + wm + mi * 16 + (l >> 2);
            int col = n0 + wn + ni * 8 + (l & 3) * 2;
            float* c = C + (size_t)row * N + col;
            float2 v0; v0.x = acc[mi * 4 + ni][0]; v0.y = acc[mi * 4 + ni][1];
            float2 v1; v1.x = acc[mi * 4 + ni][2]; v1.y = acc[mi * 4 + ni][3];
            *(float2*)c = v0;
            *(float2*)(c + 8 * (size_t)N) = v1;
        }
    }
}

// ======================= plain fp16 GEMM (single x single) — O-proj ========
#define STG_B2 (2*TILE_B)
#define GEMM_SMEM2 (3*STG_B2)

__device__ __forceinline__ void load_stage2(
    uint32_t sbase, int stg,
    const __half* __restrict__ As, const __half* __restrict__ Bs,
    int m0, int n0, int K, int k0, int tid)
{
    uint32_t sd = sbase + stg * STG_B2;
#pragma unroll
    for (int i = 0; i < 4; i++) {
        int chunk = i * 256 + tid;
        int tile  = chunk >> 9;
        int idx   = chunk & 511;
        int row   = idx >> 2;
        int cseg  = idx & 3;
        const __half* g = (tile == 0) ? As : Bs;
        int grow = ((tile == 0) ? m0 : n0) + row;
        const char* src = (const char*)(g + (size_t)grow * K + k0) + cseg * 16;
        cpasync16(sd + tile * TILE_B + row * 80 + cseg * 16, src);
    }
}

__global__ __launch_bounds__(256, 2)
void gemm_ff(const __half* __restrict__ As, const __half* __restrict__ Bs,
             float* __restrict__ C, int N, int K)
{
    extern __shared__ char dsm[];
    const uint32_t sb = smem_u32(dsm);
    const int tid = threadIdx.x;
    const int w = tid >> 5;
    const int l = tid & 31;
    const int wm = (w >> 2) * 64;
    const int wn = (w & 3) * 32;
    const int m0 = blockIdx.y * 128;
    const int n0 = blockIdx.x * 128;
    const int kiters = K / 32;

    load_stage2(sb, 0, As, Bs, m0, n0, K, 0, tid);  CP_COMMIT();
    load_stage2(sb, 1, As, Bs, m0, n0, K, 32, tid); CP_COMMIT();

    float acc[16][4];
#pragma unroll
    for (int i = 0; i < 16; i++)
#pragma unroll
        for (int j = 0; j < 4; j++) acc[i][j] = 0.f;

    const int a_row = (l & 15);
    const int a_kof = (l >> 4) * 8;
    const int b_row = (l & 7) + ((l >> 4) & 1) * 8;
    const int b_kof = ((l >> 3) & 1) * 8;

    for (int kt = 0; kt < kiters; kt++) {
        CP_WAIT1();
        __syncthreads();
        const uint32_t st = sb + (kt % 3) * STG_B2;
        const uint32_t sA = st;
        const uint32_t sB = st + TILE_B;

#pragma unroll
        for (int ks = 0; ks < 2; ks++) {
            const int kbase = ks * 16;
            uint32_t af[4][4], bf[2][4];
#pragma unroll
            for (int mi = 0; mi < 4; mi++) {
                uint32_t off = (uint32_t)((wm + mi * 16 + a_row) * 80 + (kbase + a_kof) * 2);
                ldmx4(af[mi], sA + off);
            }
#pragma unroll
            for (int ni2 = 0; ni2 < 2; ni2++) {
                uint32_t off = (uint32_t)((wn + ni2 * 16 + b_row) * 80 + (kbase + b_kof) * 2);
                ldmx4(bf[ni2], sB + off);
            }
#pragma unroll
            for (int mi = 0; mi < 4; mi++) {
#pragma unroll
                for (int ni = 0; ni < 4; ni++) {
                    const uint32_t* bp = &bf[ni >> 1][(ni & 1) * 2];
                    mma16816h(acc[mi * 4 + ni], af[mi], bp);
                }
            }
        }
        __syncthreads();
        if (kt + 2 < kiters)
            load_stage2(sb, (kt + 2) % 3, As, Bs, m0, n0, K, (kt + 2) * 32, tid);
        CP_COMMIT();
    }

#pragma unroll
    for (int mi = 0; mi < 4; mi++) {
#pragma unroll
        for (int ni = 0; ni < 4; ni++) {
            int row = m0 + wm + mi * 16 + (l >> 2);
            int col = n0 + wn + ni * 8 + (l & 3) * 2;
            float* c = C + (size_t)row * N + col;
            float2 v0; v0.x = acc[mi * 4 + ni][0]; v0.y = acc[mi * 4 + ni][1];
            float2 v1; v1.x = acc[mi * 4 + ni][2]; v1.y = acc[mi * 4 + ni][3];
            *(float2*)c = v0;
            *(float2*)(c + 8 * (size_t)N) = v1;
        }
    }
}

// ---------------- RMSNorm + mrope -> single fp16 operands -------------------
__device__ __forceinline__ int mrope_axis(int d) {
    return d < 21 ? 0 : d < 42 ? 1 : d < 64 ? 2 : d < 85 ? 0 : d < 106 ? 1 : 2;
}

__global__ __launch_bounds__(256)
void norm_rope_kernel(const float* __restrict__ cosb, const float* __restrict__ sinb,
                      const float* __restrict__ qw,   const float* __restrict__ kw)
{
    const int m = blockIdx.x;
    const int b = m >> 11;
    const int s = m & (S_ - 1);
    const int warp = threadIdx.x >> 5;
    const int lane = threadIdx.x & 31;
    const float SC = 0.08838834764831845f;
    const float* tok = g_qkv + (size_t)m * NQKV;

#pragma unroll
    for (int it = 0; it < 4; it++) {
        int slot = warp + (it << 3);
        const float* src; const float* w; bool rope; float scale;
        __half* dh;
        if (slot < 16) {
            src = tok + slot * D_;
            dh = g_q16 + ((size_t)(b * H_ + slot) * S_ + s) * D_;
            w = qw; rope = true; scale = SC;
        } else if (slot < 24) {
            int hh = slot - 16;
            src = tok + 2048 + hh * D_;
            dh = g_k16 + ((size_t)(b * KV_ + hh) * S_ + s) * D_;
            w = kw; rope = true; scale = 1.f;
        } else {
            int hh = slot - 24;
            src = tok + 3072 + hh * D_;
            dh = g_v16 + ((size_t)(b * KV_ + hh) * S_ + s) * D_;
            w = nullptr; rope = false; scale = 1.f;
        }
        float4 x4 = *(const float4*)(src + lane * 4);
        float out[4] = {x4.x, x4.y, x4.z, x4.w};
        if (rope) {
            float x[4] = {out[0], out[1], out[2], out[3]};
            float ssum = x[0]*x[0] + x[1]*x[1] + x[2]*x[2] + x[3]*x[3];
#pragma unroll
            for (int o2 = 16; o2 > 0; o2 >>= 1)
                ssum += __shfl_xor_sync(0xffffffffu, ssum, o2);
            float r = rsqrtf(ssum * (1.0f / 128.0f) + 1e-6f);
            float4 w4 = *(const float4*)(w + lane * 4);
            float xn[4];
            xn[0] = x[0] * r * w4.x; xn[1] = x[1] * r * w4.y;
            xn[2] = x[2] * r * w4.z; xn[3] = x[3] * r * w4.w;
            float oth[4];
#pragma unroll
            for (int j = 0; j < 4; j++)
                oth[j] = __shfl_xor_sync(0xffffffffu, xn[j], 16);
            float sgn = (lane < 16) ? -1.f : 1.f;
            int dbase = lane * 4;
#pragma unroll
            for (int j = 0; j < 4; j++) {
                int d = dbase + j;
                int ax = mrope_axis(d);
                size_t ci = ((size_t)(ax * B_ + b) * S_ + s) * D_ + d;
                out[j] = (xn[j] * cosb[ci] + sgn * oth[j] * sinb[ci]) * scale;
            }
        }
        __half2* ph = (__half2*)(dh + lane * 4);
        __half2 t;
        t.x = __float2half_rn(out[0]); t.y = __float2half_rn(out[1]); ph[0] = t;
        t.x = __float2half_rn(out[2]); t.y = __float2half_rn(out[3]); ph[1] = t;
    }
}

// ---------------- causal GQA flash attention (fp16 single, 1-mma) -----------
#define FSTR 136
#define QTILE_E (128*FSTR)
#define KTILE_E (64*FSTR)
#define FLASH_SMEM ((QTILE_E + 4*KTILE_E)*2)   // 104448 bytes
#define MASKV (-30000.0f)

__device__ __forceinline__ void load_kv_stage(
    __half* fsb, int st, int k0,
    const __half* Kp, const __half* Vp, int tid)
{
    __half* kd = fsb + QTILE_E + st * 2 * KTILE_E;
    __half* vd = kd + KTILE_E;
#pragma unroll
    for (int i = 0; i < 4; i++) {
        int c = tid + i * 256;
        int r = c >> 4, cs = c & 15;
        size_t go = (size_t)(k0 + r) * D_ + cs * 8;
        uint32_t so = (uint32_t)(r * FSTR + cs * 8);
        cpasync16(smem_u32(kd + so), Kp + go);
        cpasync16(smem_u32(vd + so), Vp + go);
    }
}

__global__ __launch_bounds__(256, 2)
void flash_mma(__half* __restrict__ O16)
{
    extern __shared__ __half fsh[];
    __half* sQ = fsh;

    const int qt = (int)gridDim.x - 1 - (int)blockIdx.x;  // longest-first
    const int h = blockIdx.y, b = blockIdx.z;
    const int tid = threadIdx.x;
    const int w = tid >> 5;
    const int l = tid & 31;
    const int q0 = qt * 128;

    const __half* Qb = g_q16 + ((size_t)(b * H_ + h) * S_ + q0) * D_;
    const __half* Kb = g_k16 + (size_t)(b * KV_ + (h >> 1)) * S_ * D_;
    const __half* Vb = g_v16 + (size_t)(b * KV_ + (h >> 1)) * S_ * D_;

#pragma unroll
    for (int i = 0; i < 8; i++) {
        int c = tid + i * 256;
        int r = c >> 4, cs = c & 15;
        cpasync16(smem_u32(sQ + (uint32_t)(r * FSTR + cs * 8)), Qb + (size_t)r * D_ + cs * 8);
    }
    load_kv_stage(fsh, 0, 0, Kb, Vb, tid);
    CP_COMMIT();

    float o[16][4];
#pragma unroll
    for (int i = 0; i < 16; i++)
#pragma unroll
        for (int j = 0; j < 4; j++) o[i][j] = 0.f;
    float mrow[2] = {MASKV, MASKV};
    float lrow[2] = {0.f, 0.f};

    const int r0 = l >> 2;
    const int a_row = (l & 15);
    const int a_kof = (l >> 4) * 8;
    const int b_row = (l & 7) + ((l >> 4) & 1) * 8;
    const int b_kof = ((l >> 3) & 1) * 8;
    const int v_row = (l & 15);
    const int v_cof = (l >> 4) * 8;
    const int wrow_lo = q0 + 16 * w;
    const int ntiles = 2 * qt + 2;

    for (int t = 0; t < ntiles; t++) {
        const int k0 = t * 64;
        const int st = t & 1;
        if (t + 1 < ntiles) {
            load_kv_stage(fsh, st ^ 1, (t + 1) * 64, Kb, Vb, tid);
            CP_COMMIT();
            CP_WAIT1();
        } else {
            CP_WAIT0();
        }
        __syncthreads();

        if (k0 <= wrow_lo + 15) {
            __half* sK = fsh + QTILE_E + st * 2 * KTILE_E;
            __half* sV = sK + KTILE_E;

            float s[8][4];
#pragma unroll
            for (int i = 0; i < 8; i++)
#pragma unroll
                for (int j = 0; j < 4; j++) s[i][j] = 0.f;

#pragma unroll
            for (int ks = 0; ks < 8; ks++) {
                uint32_t aoff = (uint32_t)((16 * w + a_row) * FSTR + ks * 16 + a_kof) * 2;
                uint32_t qf[4];
                ldmx4(qf, smem_u32(sQ) + aoff);
#pragma unroll
                for (int ng = 0; ng < 4; ng++) {
                    uint32_t boff = (uint32_t)((16 * ng + b_row) * FSTR + ks * 16 + b_kof) * 2;
                    uint32_t kf[4];
                    ldmx4(kf, smem_u32(sK) + boff);
                    mma16816h(s[2*ng],   qf, &kf[0]);
                    mma16816h(s[2*ng+1], qf, &kf[2]);
                }
            }

            if (k0 + 63 > wrow_lo) {
                int grow0 = wrow_lo + r0;
                int grow1 = grow0 + 8;
#pragma unroll
                for (int nt = 0; nt < 8; nt++) {
                    int col = k0 + nt * 8 + (l & 3) * 2;
                    if (col > grow0)     s[nt][0] = MASKV;
                    if (col + 1 > grow0) s[nt][1] = MASKV;
                    if (col > grow1)     s[nt][2] = MASKV;
                    if (col + 1 > grow1) s[nt][3] = MASKV;
                }
            }

            float rm0 = MASKV, rm1 = MASKV;
#pragma unroll
            for (int nt = 0; nt < 8; nt++) {
                rm0 = fmaxf(rm0, fmaxf(s[nt][0], s[nt][1]));
                rm1 = fmaxf(rm1, fmaxf(s[nt][2], s[nt][3]));
            }
            rm0 = fmaxf(rm0, __shfl_xor_sync(0xffffffffu, rm0, 1));
            rm0 = fmaxf(rm0, __shfl_xor_sync(0xffffffffu, rm0, 2));
            rm1 = fmaxf(rm1, __shfl_xor_sync(0xffffffffu, rm1, 1));
            rm1 = fmaxf(rm1, __shfl_xor_sync(0xffffffffu, rm1, 2));

            float mn0 = fmaxf(mrow[0], rm0);
            float mn1 = fmaxf(mrow[1], rm1);
            float alpha0 = fexp(mrow[0] - mn0);
            float alpha1 = fexp(mrow[1] - mn1);
            mrow[0] = mn0; mrow[1] = mn1;

            float rs0 = 0.f, rs1 = 0.f;
#pragma unroll
            for (int nt = 0; nt < 8; nt++) {
                s[nt][0] = fexp(s[nt][0] - mn0);
                s[nt][1] = fexp(s[nt][1] - mn0);
                s[nt][2] = fexp(s[nt][2] - mn1);
                s[nt][3] = fexp(s[nt][3] - mn1);
                rs0 += s[nt][0] + s[nt][1];
                rs1 += s[nt][2] + s[nt][3];
            }
            rs0 += __shfl_xor_sync(0xffffffffu, rs0, 1);
            rs0 += __shfl_xor_sync(0xffffffffu, rs0, 2);
            rs1 += __shfl_xor_sync(0xffffffffu, rs1, 1);
            rs1 += __shfl_xor_sync(0xffffffffu, rs1, 2);
            lrow[0] = lrow[0] * alpha0 + rs0;
            lrow[1] = lrow[1] * alpha1 + rs1;

#pragma unroll
            for (int nt = 0; nt < 16; nt++) {
                o[nt][0] *= alpha0; o[nt][1] *= alpha0;
                o[nt][2] *= alpha1; o[nt][3] *= alpha1;
            }

#pragma unroll
            for (int ks = 0; ks < 4; ks++) {
                uint32_t pa[4];
                pa[0] = packh(s[2*ks][0],   s[2*ks][1]);
                pa[1] = packh(s[2*ks][2],   s[2*ks][3]);
                pa[2] = packh(s[2*ks+1][0], s[2*ks+1][1]);
                pa[3] = packh(s[2*ks+1][2], s[2*ks+1][3]);
#pragma unroll
                for (int dg = 0; dg < 8; dg++) {
                    uint32_t voff = (uint32_t)((ks * 16 + v_row) * FSTR + dg * 16 + v_cof) * 2;
                    uint32_t vf[4];
                    ldmx4t(vf, smem_u32(sV) + voff);
                    mma16816h(o[2*dg],   pa, &vf[0]);
                    mma16816h(o[2*dg+1], pa, &vf[2]);
                }
            }
        }
        __syncthreads();
    }

    float inv0 = 1.f / lrow[0];
    float inv1 = 1.f / lrow[1];
    size_t row0 = (size_t)b * S_ + q0 + 16 * w + r0;
    size_t row1 = row0 + 8;
    int colb = h * D_ + (l & 3) * 2;
#pragma unroll
    for (int nt = 0; nt < 16; nt++) {
        int col = colb + nt * 8;
        *(uint32_t*)(O16 + row0 * (H_*D_) + col) = packh(o[nt][0] * inv0, o[nt][1] * inv0);
        *(uint32_t*)(O16 + row1 * (H_*D_) + col) = packh(o[nt][2] * inv1, o[nt][3] * inv1);
    }
}

// ---------------- launcher ---------------------------------------------------
extern "C" void kernel_launch(void* const* d_in, const int* in_sizes, int n_in,
                              void* d_out, int out_size)
{
    const float* hidden   = (const float*)d_in[0];
    const float* cosb     = (const float*)d_in[1];
    const float* sinb     = (const float*)d_in[2];
    const float* q_w      = (const float*)d_in[3];
    const float* k_w      = (const float*)d_in[4];
    const float* v_w      = (const float*)d_in[5];
    const float* o_w      = (const float*)d_in[6];
    const float* q_norm_w = (const float*)d_in[7];
    const float* k_norm_w = (const float*)d_in[8];
    float* out = (float*)d_out;

    float* pqkv;
    cudaGetSymbolAddress((void**)&pqkv, g_qkv);

    __half *hidh, *hidl, *w16, *ow16, *at16;
    cudaGetSymbolAddress((void**)&hidh, g_hid_h);
    cudaGetSymbolAddress((void**)&hidl, g_hid_l);
    cudaGetSymbolAddress((void**)&w16,  g_w16);
    cudaGetSymbolAddress((void**)&ow16, g_ow16);
    cudaGetSymbolAddress((void**)&at16, g_at16);

    cudaFuncSetAttribute(gemm_asym, cudaFuncAttributeMaxDynamicSharedMemorySize, GEMM_SMEM3);
    cudaFuncSetAttribute(gemm_ff,   cudaFuncAttributeMaxDynamicSharedMemorySize, GEMM_SMEM2);
    cudaFuncSetAttribute(flash_mma, cudaFuncAttributeMaxDynamicSharedMemorySize, FLASH_SMEM);

    // 1) converts: hidden -> fp16 hi/lo; weights -> single fp16
    {
        int n4 = MTOK * HID_ / 4;
        split_fp16_kernel<<<(n4 + 255) / 256, 256>>>(hidden, hidh, hidl, n4);
    }
    conv_fp16_kernel<<<(H_*D_*HID_/4 + 255)/256, 256>>>(q_w, w16,                      H_*D_*HID_/4);
    conv_fp16_kernel<<<(KV_*D_*HID_/4 + 255)/256, 256>>>(k_w, w16 + (size_t)2048*HID_, KV_*D_*HID_/4);
    conv_fp16_kernel<<<(KV_*D_*HID_/4 + 255)/256, 256>>>(v_w, w16 + (size_t)3072*HID_, KV_*D_*HID_/4);
    conv_fp16_kernel<<<(HID_*H_*D_/4 + 255)/256, 256>>>(o_w, ow16, HID_*H_*D_/4);

    // 2) fused QKV projection (fp16 asym, 2-mma, 2-stage, 2 CTAs/SM)
    gemm_asym<<<dim3(NQKV/128, MTOK/128), 256, GEMM_SMEM3>>>(hidh, hidl, w16, pqkv, NQKV, HID_);

    // 3) RMSNorm + mrope -> single fp16 Q/K/V (Q pre-scaled by 1/sqrt(D))
    norm_rope_kernel<<<MTOK, 256>>>(cosb, sinb, q_norm_w, k_norm_w);

    // 4) flash attention: QK 1-mma, PV 1-mma, 2 CTAs/SM
    flash_mma<<<dim3(S_ / 128, H_, B_), 256, FLASH_SMEM>>>(at16);

    // 5) O-projection (plain fp16, 1-mma) -> d_out
    gemm_ff<<<dim3(HID_/128, MTOK/128), 256, GEMM_SMEM2>>>(at16, ow16, out, HID_, H_*D_);
}

// round 14
// speedup vs baseline: 2.1779x; 1.0569x over previous
#include <cuda_runtime.h>
#include <cuda_fp16.h>
#include <math.h>
#include <stdint.h>

// Problem constants
#define B_   2
#define S_   2048
#define HID_ 2048
#define H_   16
#define KV_  8
#define D_   128
#define MTOK (B_*S_)   // 4096 tokens
#define NQKV 4096

// ---------------- scratch (device globals) ----------------------------------
__device__ __half g_hid_h[MTOK*HID_], g_hid_l[MTOK*HID_];  // hidden fp16 hi/lo
__device__ __half g_w16 [NQKV*HID_];                        // q|k|v weights fp16
__device__ __half g_ow16[HID_*H_*D_];                       // o_w fp16

// roped/normed operands for flash (single fp16), [B,H|KV,S,D]
__device__ __half g_q16[B_*H_*S_*D_];
__device__ __half g_k16[B_*KV_*S_*D_];
__device__ __half g_v16[B_*KV_*S_*D_];
// attention output (single fp16), [B*S, H*D]
__device__ __half g_at16[MTOK*H_*D_];

// ======================= PTX helpers (sm_80-era) ===========================
__device__ __forceinline__ uint32_t smem_u32(const void* p) {
    return (uint32_t)__cvta_generic_to_shared(p);
}
__device__ __forceinline__ void cpasync16(uint32_t dst, const void* src) {
    asm volatile("cp.async.cg.shared.global [%0], [%1], 16;" :: "r"(dst), "l"(src));
}
#define CP_COMMIT() asm volatile("cp.async.commit_group;" ::: "memory")
#define CP_WAIT1()  asm volatile("cp.async.wait_group 1;" ::: "memory")
#define CP_WAIT0()  asm volatile("cp.async.wait_group 0;" ::: "memory")

__device__ __forceinline__ void ldmx4(uint32_t* r, uint32_t addr) {
    asm volatile("ldmatrix.sync.aligned.m8n8.x4.shared.b16 {%0,%1,%2,%3}, [%4];"
                 : "=r"(r[0]), "=r"(r[1]), "=r"(r[2]), "=r"(r[3]) : "r"(addr));
}
__device__ __forceinline__ void ldmx4t(uint32_t* r, uint32_t addr) {
    asm volatile("ldmatrix.sync.aligned.m8n8.x4.trans.shared.b16 {%0,%1,%2,%3}, [%4];"
                 : "=r"(r[0]), "=r"(r[1]), "=r"(r[2]), "=r"(r[3]) : "r"(addr));
}
__device__ __forceinline__ void mma16816h(float* d, const uint32_t* a, const uint32_t* b) {
    asm volatile("mma.sync.aligned.m16n8k16.row.col.f32.f16.f16.f32 "
                 "{%0,%1,%2,%3}, {%4,%5,%6,%7}, {%8,%9}, {%0,%1,%2,%3};"
                 : "+f"(d[0]), "+f"(d[1]), "+f"(d[2]), "+f"(d[3])
                 : "r"(a[0]), "r"(a[1]), "r"(a[2]), "r"(a[3]), "r"(b[0]), "r"(b[1]));
}
__device__ __forceinline__ uint32_t packh(float x, float y) {
    __half2 t; t.x = __float2half_rn(x); t.y = __float2half_rn(y);
    return *(uint32_t*)&t;
}
__device__ __forceinline__ float fexp(float x) {
    return __expf(fmaxf(x, -80.0f));
}

// ======================= fp32 -> fp16 hi/lo split ==========================
__global__ __launch_bounds__(256)
void split_fp16_kernel(const float* __restrict__ src,
                       __half* __restrict__ hi, __half* __restrict__ lo, int n4)
{
    int i = blockIdx.x * blockDim.x + threadIdx.x;
    if (i >= n4) return;
    float4 x = ((const float4*)src)[i];
    float xs[4] = {x.x, x.y, x.z, x.w};
    __half h[4], l[4];
#pragma unroll
    for (int j = 0; j < 4; j++) {
        h[j] = __float2half_rn(xs[j]);
        l[j] = __float2half_rn(xs[j] - __half2float(h[j]));
    }
    __half2 h0; h0.x = h[0]; h0.y = h[1];
    __half2 h1; h1.x = h[2]; h1.y = h[3];
    __half2 l0; l0.x = l[0]; l0.y = l[1];
    __half2 l1; l1.x = l[2]; l1.y = l[3];
    ((__half2*)hi)[i*2 + 0] = h0;
    ((__half2*)hi)[i*2 + 1] = h1;
    ((__half2*)lo)[i*2 + 0] = l0;
    ((__half2*)lo)[i*2 + 1] = l1;
}

// ======================= merged weight convert (q|k|v -> w16, o -> ow16) ===
#define QW4 (H_*D_*HID_/4)
#define KW4 (KV_*D_*HID_/4)
#define OW4 (HID_*H_*D_/4)
#define NW4 (QW4 + 2*KW4 + OW4)

__global__ __launch_bounds__(256)
void conv_weights_kernel(const float* __restrict__ qw, const float* __restrict__ kw,
                         const float* __restrict__ vw, const float* __restrict__ ow,
                         __half* __restrict__ w16, __half* __restrict__ ow16)
{
    int i = blockIdx.x * blockDim.x + threadIdx.x;
    if (i >= NW4) return;
    const float* src; __half* dst; int li;
    if (i < QW4)                 { src = qw; dst = w16;                       li = i; }
    else if (i < QW4 + KW4)      { src = kw; dst = w16 + 4*(size_t)QW4;      li = i - QW4; }
    else if (i < QW4 + 2*KW4)    { src = vw; dst = w16 + 4*(size_t)(QW4+KW4); li = i - QW4 - KW4; }
    else                         { src = ow; dst = ow16;                      li = i - QW4 - 2*KW4; }
    float4 x = ((const float4*)src)[li];
    ((__half2*)dst)[li*2 + 0] = *(__half2*)&(uint32_t){packh(x.x, x.y)};
    ((__half2*)dst)[li*2 + 1] = *(__half2*)&(uint32_t){packh(x.z, x.w)};
}

// ======================= fp16 asym GEMM + fused norm/rope epilogue =========
// QKV projection: A=hidden hi/lo, B=weights single. 2-stage pipe, 2 CTAs/SM.
// Epilogue: RMSNorm (+mrope for q/k) per output tile (128 tokens x 1 head),
// writes fp16 directly to g_q16/g_k16/g_v16.
#define LDT   40
#define TILE_B (128*LDT*2)
#define STG_B3 (3*TILE_B)
#define GEMM_SMEM3 (2*STG_B3)   // 61440 -> 2 CTAs/SM
#define FT_LD 132               // fp32 staging tile stride

__device__ __forceinline__ int mrope_axis(int d) {
    return d < 21 ? 0 : d < 42 ? 1 : d < 64 ? 2 : d < 85 ? 0 : d < 106 ? 1 : 2;
}

__device__ __forceinline__ void load_stage3(
    uint32_t sbase, int stg,
    const __half* __restrict__ Ah, const __half* __restrict__ Al,
    const __half* __restrict__ Bs,
    int m0, int n0, int K, int k0, int tid)
{
    uint32_t sd = sbase + stg * STG_B3;
#pragma unroll
    for (int i = 0; i < 6; i++) {
        int chunk = i * 256 + tid;
        int tile  = chunk >> 9;
        int idx   = chunk & 511;
        int row   = idx >> 2;
        int cseg  = idx & 3;
        const __half* g = (tile == 0) ? Ah : (tile == 1) ? Al : Bs;
        int grow = ((tile < 2) ? m0 : n0) + row;
        const char* src = (const char*)(g + (size_t)grow * K + k0) + cseg * 16;
        cpasync16(sd + tile * TILE_B + row * 80 + cseg * 16, src);
    }
}

__global__ __launch_bounds__(256, 2)
void gemm_qkv(const __half* __restrict__ Ah, const __half* __restrict__ Al,
              const __half* __restrict__ Bs,
              const float* __restrict__ cosb, const float* __restrict__ sinb,
              const float* __restrict__ qnw,  const float* __restrict__ knw)
{
    extern __shared__ char dsm[];
    const uint32_t sb = smem_u32(dsm);
    const int tid = threadIdx.x;
    const int w = tid >> 5;
    const int l = tid & 31;
    const int wm = (w >> 2) * 64;
    const int wn = (w & 3) * 32;
    const int m0 = blockIdx.y * 128;
    const int n0 = blockIdx.x * 128;
    const int K = HID_;
    const int kiters = K / 32;

    load_stage3(sb, 0, Ah, Al, Bs, m0, n0, K, 0, tid);  CP_COMMIT();
    load_stage3(sb, 1, Ah, Al, Bs, m0, n0, K, 32, tid); CP_COMMIT();

    float acc[16][4];
#pragma unroll
    for (int i = 0; i < 16; i++)
#pragma unroll
        for (int j = 0; j < 4; j++) acc[i][j] = 0.f;

    const int a_row = (l & 15);
    const int a_kof = (l >> 4) * 8;
    const int b_row = (l & 7) + ((l >> 4) & 1) * 8;
    const int b_kof = ((l >> 3) & 1) * 8;

    for (int kt = 0; kt < kiters; kt++) {
        CP_WAIT1();
        __syncthreads();
        const uint32_t st = sb + (kt & 1) * STG_B3;
        const uint32_t sAh = st;
        const uint32_t sAl = st + TILE_B;
        const uint32_t sBs = st + 2 * TILE_B;

#pragma unroll
        for (int ks = 0; ks < 2; ks++) {
            const int kbase = ks * 16;
            uint32_t ah[4][4], al[4][4], bh[2][4];
#pragma unroll
            for (int mi = 0; mi < 4; mi++) {
                uint32_t off = (uint32_t)((wm + mi * 16 + a_row) * 80 + (kbase + a_kof) * 2);
                ldmx4(ah[mi], sAh + off);
                ldmx4(al[mi], sAl + off);
            }
#pragma unroll
            for (int ni2 = 0; ni2 < 2; ni2++) {
                uint32_t off = (uint32_t)((wn + ni2 * 16 + b_row) * 80 + (kbase + b_kof) * 2);
                ldmx4(bh[ni2], sBs + off);
            }
#pragma unroll
            for (int mi = 0; mi < 4; mi++) {
#pragma unroll
                for (int ni = 0; ni < 4; ni++) {
                    const uint32_t* bp = &bh[ni >> 1][(ni & 1) * 2];
                    mma16816h(acc[mi * 4 + ni], ah[mi], bp);
                    mma16816h(acc[mi * 4 + ni], al[mi], bp);
                }
            }
        }
        __syncthreads();
        if (kt + 2 < kiters)
            load_stage3(sb, kt & 1, Ah, Al, Bs, m0, n0, K, (kt + 2) * 32, tid);
        CP_COMMIT();
    }

    // ---- fused epilogue: stage acc in smem, rmsnorm+rope, write fp16 ----
    float* ftile = (float*)dsm;   // [64][FT_LD]
    const float SC = 0.08838834764831845f;
    const int r0 = l >> 2;

    // head routing for this tile
    __half* dbase; const float* nw; bool rope; float scale;
    if (n0 < 2048)      { dbase = g_q16 + (size_t)(n0 >> 7) * S_ * D_;          nw = qnw; rope = true;  scale = SC;  }
    else if (n0 < 3072) { dbase = g_k16 + (size_t)((n0 - 2048) >> 7) * S_ * D_; nw = knw; rope = true;  scale = 1.f; }
    else                { dbase = g_v16 + (size_t)((n0 - 3072) >> 7) * S_ * D_; nw = nullptr; rope = false; scale = 1.f; }
    const int nheads = (n0 < 2048) ? H_ : KV_;

    float4 w4 = make_float4(1.f, 1.f, 1.f, 1.f);
    if (rope) w4 = *(const float4*)(nw + l * 4);

#pragma unroll
    for (int half = 0; half < 2; half++) {
        if ((wm >> 6) == half) {
#pragma unroll
            for (int mi = 0; mi < 4; mi++)
#pragma unroll
                for (int ni = 0; ni < 4; ni++) {
                    int rl = mi * 16 + r0;
                    int cc = wn + ni * 8 + (l & 3) * 2;
                    ftile[rl * FT_LD + cc]       = acc[mi*4+ni][0];
                    ftile[rl * FT_LD + cc + 1]   = acc[mi*4+ni][1];
                    ftile[(rl+8) * FT_LD + cc]   = acc[mi*4+ni][2];
                    ftile[(rl+8) * FT_LD + cc+1] = acc[mi*4+ni][3];
                }
        }
        __syncthreads();

#pragma unroll
        for (int rr = 0; rr < 8; rr++) {
            int row  = w * 8 + rr;
            int mtok = m0 + half * 64 + row;
            int bb = mtok >> 11, ss = mtok & (S_ - 1);
            float4 x4 = *(float4*)&ftile[row * FT_LD + l * 4];
            float out[4] = {x4.x, x4.y, x4.z, x4.w};
            if (rope) {
                float ssum = out[0]*out[0] + out[1]*out[1] + out[2]*out[2] + out[3]*out[3];
#pragma unroll
                for (int o2 = 16; o2 > 0; o2 >>= 1)
                    ssum += __shfl_xor_sync(0xffffffffu, ssum, o2);
                float r = rsqrtf(ssum * (1.0f / 128.0f) + 1e-6f);
                float xn[4];
                xn[0] = out[0]*r*w4.x; xn[1] = out[1]*r*w4.y;
                xn[2] = out[2]*r*w4.z; xn[3] = out[3]*r*w4.w;
                float oth[4];
#pragma unroll
                for (int j = 0; j < 4; j++)
                    oth[j] = __shfl_xor_sync(0xffffffffu, xn[j], 16);
                float sgn = (l < 16) ? -1.f : 1.f;
                int dbidx = l * 4;
#pragma unroll
                for (int j = 0; j < 4; j++) {
                    int d = dbidx + j;
                    int ax = mrope_axis(d);
                    size_t ci = ((size_t)(ax * B_ + bb) * S_ + ss) * D_ + d;
                    out[j] = (xn[j] * cosb[ci] + sgn * oth[j] * sinb[ci]) * scale;
                }
            }
            __half* dst = dbase + ((size_t)bb * nheads * S_ + ss) * D_ + l * 4;
            *(uint32_t*)(dst)     = packh(out[0], out[1]);
            *(uint32_t*)(dst + 2) = packh(out[2], out[3]);
        }
        __syncthreads();
    }
}

// ======================= plain fp16 GEMM (single x single) — O-proj ========
#define STG_B2 (2*TILE_B)
#define GEMM_SMEM2 (3*STG_B2)

__device__ __forceinline__ void load_stage2(
    uint32_t sbase, int stg,
    const __half* __restrict__ As, const __half* __restrict__ Bs,
    int m0, int n0, int K, int k0, int tid)
{
    uint32_t sd = sbase + stg * STG_B2;
#pragma unroll
    for (int i = 0; i < 4; i++) {
        int chunk = i * 256 + tid;
        int tile  = chunk >> 9;
        int idx   = chunk & 511;
        int row   = idx >> 2;
        int cseg  = idx & 3;
        const __half* g = (tile == 0) ? As : Bs;
        int grow = ((tile == 0) ? m0 : n0) + row;
        const char* src = (const char*)(g + (size_t)grow * K + k0) + cseg * 16;
        cpasync16(sd + tile * TILE_B + row * 80 + cseg * 16, src);
    }
}

__global__ __launch_bounds__(256, 2)
void gemm_ff(const __half* __restrict__ As, const __half* __restrict__ Bs,
             float* __restrict__ C, int N, int K)
{
    extern __shared__ char dsm[];
    const uint32_t sb = smem_u32(dsm);
    const int tid = threadIdx.x;
    const int w = tid >> 5;
    const int l = tid & 31;
    const int wm = (w >> 2) * 64;
    const int wn = (w & 3) * 32;
    const int m0 = blockIdx.y * 128;
    const int n0 = blockIdx.x * 128;
    const int kiters = K / 32;

    load_stage2(sb, 0, As, Bs, m0, n0, K, 0, tid);  CP_COMMIT();
    load_stage2(sb, 1, As, Bs, m0, n0, K, 32, tid); CP_COMMIT();

    float acc[16][4];
#pragma unroll
    for (int i = 0; i < 16; i++)
#pragma unroll
        for (int j = 0; j < 4; j++) acc[i][j] = 0.f;

    const int a_row = (l & 15);
    const int a_kof = (l >> 4) * 8;
    const int b_row = (l & 7) + ((l >> 4) & 1) * 8;
    const int b_kof = ((l >> 3) & 1) * 8;

    for (int kt = 0; kt < kiters; kt++) {
        CP_WAIT1();
        __syncthreads();
        const uint32_t st = sb + (kt % 3) * STG_B2;
        const uint32_t sA = st;
        const uint32_t sB = st + TILE_B;

#pragma unroll
        for (int ks = 0; ks < 2; ks++) {
            const int kbase = ks * 16;
            uint32_t af[4][4], bf[2][4];
#pragma unroll
            for (int mi = 0; mi < 4; mi++) {
                uint32_t off = (uint32_t)((wm + mi * 16 + a_row) * 80 + (kbase + a_kof) * 2);
                ldmx4(af[mi], sA + off);
            }
#pragma unroll
            for (int ni2 = 0; ni2 < 2; ni2++) {
                uint32_t off = (uint32_t)((wn + ni2 * 16 + b_row) * 80 + (kbase + b_kof) * 2);
                ldmx4(bf[ni2], sB + off);
            }
#pragma unroll
            for (int mi = 0; mi < 4; mi++) {
#pragma unroll
                for (int ni = 0; ni < 4; ni++) {
                    const uint32_t* bp = &bf[ni >> 1][(ni & 1) * 2];
                    mma16816h(acc[mi * 4 + ni], af[mi], bp);
                }
            }
        }
        __syncthreads();
        if (kt + 2 < kiters)
            load_stage2(sb, (kt + 2) % 3, As, Bs, m0, n0, K, (kt + 2) * 32, tid);
        CP_COMMIT();
    }

#pragma unroll
    for (int mi = 0; mi < 4; mi++) {
#pragma unroll
        for (int ni = 0; ni < 4; ni++) {
            int row = m0 + wm + mi * 16 + (l >> 2);
            int col = n0 + wn + ni * 8 + (l & 3) * 2;
            float* c = C + (size_t)row * N + col;
            float2 v0; v0.x = acc[mi * 4 + ni][0]; v0.y = acc[mi * 4 + ni][1];
            float2 v1; v1.x = acc[mi * 4 + ni][2]; v1.y = acc[mi * 4 + ni][3];
            *(float2*)c = v0;
            *(float2*)(c + 8 * (size_t)N) = v1;
        }
    }
}

// ---------------- causal GQA flash attention (fp16 single, 1-mma) -----------
#define FSTR 136
#define QTILE_E (128*FSTR)
#define KTILE_E (64*FSTR)
#define FLASH_SMEM ((QTILE_E + 4*KTILE_E)*2)   // 104448 bytes
#define MASKV (-30000.0f)

__device__ __forceinline__ void load_kv_stage(
    __half* fsb, int st, int k0,
    const __half* Kp, const __half* Vp, int tid)
{
    __half* kd = fsb + QTILE_E + st * 2 * KTILE_E;
    __half* vd = kd + KTILE_E;
#pragma unroll
    for (int i = 0; i < 4; i++) {
        int c = tid + i * 256;
        int r = c >> 4, cs = c & 15;
        size_t go = (size_t)(k0 + r) * D_ + cs * 8;
        uint32_t so = (uint32_t)(r * FSTR + cs * 8);
        cpasync16(smem_u32(kd + so), Kp + go);
        cpasync16(smem_u32(vd + so), Vp + go);
    }
}

__global__ __launch_bounds__(256, 2)
void flash_mma(__half* __restrict__ O16)
{
    extern __shared__ __half fsh[];
    __half* sQ = fsh;

    const int qt = (int)gridDim.x - 1 - (int)blockIdx.x;  // longest-first
    const int h = blockIdx.y, b = blockIdx.z;
    const int tid = threadIdx.x;
    const int w = tid >> 5;
    const int l = tid & 31;
    const int q0 = qt * 128;

    const __half* Qb = g_q16 + ((size_t)(b * H_ + h) * S_ + q0) * D_;
    const __half* Kb = g_k16 + (size_t)(b * KV_ + (h >> 1)) * S_ * D_;
    const __half* Vb = g_v16 + (size_t)(b * KV_ + (h >> 1)) * S_ * D_;

#pragma unroll
    for (int i = 0; i < 8; i++) {
        int c = tid + i * 256;
        int r = c >> 4, cs = c & 15;
        cpasync16(smem_u32(sQ + (uint32_t)(r * FSTR + cs * 8)), Qb + (size_t)r * D_ + cs * 8);
    }
    load_kv_stage(fsh, 0, 0, Kb, Vb, tid);
    CP_COMMIT();

    float o[16][4];
#pragma unroll
    for (int i = 0; i < 16; i++)
#pragma unroll
        for (int j = 0; j < 4; j++) o[i][j] = 0.f;
    float mrow[2] = {MASKV, MASKV};
    float lrow[2] = {0.f, 0.f};

    const int r0 = l >> 2;
    const int a_row = (l & 15);
    const int a_kof = (l >> 4) * 8;
    const int b_row = (l & 7) + ((l >> 4) & 1) * 8;
    const int b_kof = ((l >> 3) & 1) * 8;
    const int v_row = (l & 15);
    const int v_cof = (l >> 4) * 8;
    const int wrow_lo = q0 + 16 * w;
    const int ntiles = 2 * qt + 2;

    for (int t = 0; t < ntiles; t++) {
        const int k0 = t * 64;
        const int st = t & 1;
        if (t + 1 < ntiles) {
            load_kv_stage(fsh, st ^ 1, (t + 1) * 64, Kb, Vb, tid);
            CP_COMMIT();
            CP_WAIT1();
        } else {
            CP_WAIT0();
        }
        __syncthreads();

        if (k0 <= wrow_lo + 15) {
            __half* sK = fsh + QTILE_E + st * 2 * KTILE_E;
            __half* sV = sK + KTILE_E;

            float s[8][4];
#pragma unroll
            for (int i = 0; i < 8; i++)
#pragma unroll
                for (int j = 0; j < 4; j++) s[i][j] = 0.f;

#pragma unroll
            for (int ks = 0; ks < 8; ks++) {
                uint32_t aoff = (uint32_t)((16 * w + a_row) * FSTR + ks * 16 + a_kof) * 2;
                uint32_t qf[4];
                ldmx4(qf, smem_u32(sQ) + aoff);
#pragma unroll
                for (int ng = 0; ng < 4; ng++) {
                    uint32_t boff = (uint32_t)((16 * ng + b_row) * FSTR + ks * 16 + b_kof) * 2;
                    uint32_t kf[4];
                    ldmx4(kf, smem_u32(sK) + boff);
                    mma16816h(s[2*ng],   qf, &kf[0]);
                    mma16816h(s[2*ng+1], qf, &kf[2]);
                }
            }

            if (k0 + 63 > wrow_lo) {
                int grow0 = wrow_lo + r0;
                int grow1 = grow0 + 8;
#pragma unroll
                for (int nt = 0; nt < 8; nt++) {
                    int col = k0 + nt * 8 + (l & 3) * 2;
                    if (col > grow0)     s[nt][0] = MASKV;
                    if (col + 1 > grow0) s[nt][1] = MASKV;
                    if (col > grow1)     s[nt][2] = MASKV;
                    if (col + 1 > grow1) s[nt][3] = MASKV;
                }
            }

            float rm0 = MASKV, rm1 = MASKV;
#pragma unroll
            for (int nt = 0; nt < 8; nt++) {
                rm0 = fmaxf(rm0, fmaxf(s[nt][0], s[nt][1]));
                rm1 = fmaxf(rm1, fmaxf(s[nt][2], s[nt][3]));
            }
            rm0 = fmaxf(rm0, __shfl_xor_sync(0xffffffffu, rm0, 1));
            rm0 = fmaxf(rm0, __shfl_xor_sync(0xffffffffu, rm0, 2));
            rm1 = fmaxf(rm1, __shfl_xor_sync(0xffffffffu, rm1, 1));
            rm1 = fmaxf(rm1, __shfl_xor_sync(0xffffffffu, rm1, 2));

            float mn0 = fmaxf(mrow[0], rm0);
            float mn1 = fmaxf(mrow[1], rm1);
            float alpha0 = fexp(mrow[0] - mn0);
            float alpha1 = fexp(mrow[1] - mn1);
            mrow[0] = mn0; mrow[1] = mn1;

            float rs0 = 0.f, rs1 = 0.f;
#pragma unroll
            for (int nt = 0; nt < 8; nt++) {
                s[nt][0] = fexp(s[nt][0] - mn0);
                s[nt][1] = fexp(s[nt][1] - mn0);
                s[nt][2] = fexp(s[nt][2] - mn1);
                s[nt][3] = fexp(s[nt][3] - mn1);
                rs0 += s[nt][0] + s[nt][1];
                rs1 += s[nt][2] + s[nt][3];
            }
            rs0 += __shfl_xor_sync(0xffffffffu, rs0, 1);
            rs0 += __shfl_xor_sync(0xffffffffu, rs0, 2);
            rs1 += __shfl_xor_sync(0xffffffffu, rs1, 1);
            rs1 += __shfl_xor_sync(0xffffffffu, rs1, 2);
            lrow[0] = lrow[0] * alpha0 + rs0;
            lrow[1] = lrow[1] * alpha1 + rs1;

#pragma unroll
            for (int nt = 0; nt < 16; nt++) {
                o[nt][0] *= alpha0; o[nt][1] *= alpha0;
                o[nt][2] *= alpha1; o[nt][3] *= alpha1;
            }

#pragma unroll
            for (int ks = 0; ks < 4; ks++) {
                uint32_t pa[4];
                pa[0] = packh(s[2*ks][0],   s[2*ks][1]);
                pa[1] = packh(s[2*ks][2],   s[2*ks][3]);
                pa[2] = packh(s[2*ks+1][0], s[2*ks+1][1]);
                pa[3] = packh(s[2*ks+1][2], s[2*ks+1][3]);
#pragma unroll
                for (int dg = 0; dg < 8; dg++) {
                    uint32_t voff = (uint32_t)((ks * 16 + v_row) * FSTR + dg * 16 + v_cof) * 2;
                    uint32_t vf[4];
                    ldmx4t(vf, smem_u32(sV) + voff);
                    mma16816h(o[2*dg],   pa, &vf[0]);
                    mma16816h(o[2*dg+1], pa, &vf[2]);
                }
            }
        }
        __syncthreads();
    }

    float inv0 = 1.f / lrow[0];
    float inv1 = 1.f / lrow[1];
    size_t row0 = (size_t)b * S_ + q0 + 16 * w + r0;
    size_t row1 = row0 + 8;
    int colb = h * D_ + (l & 3) * 2;
#pragma unroll
    for (int nt = 0; nt < 16; nt++) {
        int col = colb + nt * 8;
        *(uint32_t*)(O16 + row0 * (H_*D_) + col) = packh(o[nt][0] * inv0, o[nt][1] * inv0);
        *(uint32_t*)(O16 + row1 * (H_*D_) + col) = packh(o[nt][2] * inv1, o[nt][3] * inv1);
    }
}

// ---------------- launcher ---------------------------------------------------
extern "C" void kernel_launch(void* const* d_in, const int* in_sizes, int n_in,
                              void* d_out, int out_size)
{
    const float* hidden   = (const float*)d_in[0];
    const float* cosb     = (const float*)d_in[1];
    const float* sinb     = (const float*)d_in[2];
    const float* q_w      = (const float*)d_in[3];
    const float* k_w      = (const float*)d_in[4];
    const float* v_w      = (const float*)d_in[5];
    const float* o_w      = (const float*)d_in[6];
    const float* q_norm_w = (const float*)d_in[7];
    const float* k_norm_w = (const float*)d_in[8];
    float* out = (float*)d_out;

    __half *hidh, *hidl, *w16, *ow16, *at16;
    cudaGetSymbolAddress((void**)&hidh, g_hid_h);
    cudaGetSymbolAddress((void**)&hidl, g_hid_l);
    cudaGetSymbolAddress((void**)&w16,  g_w16);
    cudaGetSymbolAddress((void**)&ow16, g_ow16);
    cudaGetSymbolAddress((void**)&at16, g_at16);

    cudaFuncSetAttribute(gemm_qkv, cudaFuncAttributeMaxDynamicSharedMemorySize, GEMM_SMEM3);
    cudaFuncSetAttribute(gemm_ff,  cudaFuncAttributeMaxDynamicSharedMemorySize, GEMM_SMEM2);
    cudaFuncSetAttribute(flash_mma, cudaFuncAttributeMaxDynamicSharedMemorySize, FLASH_SMEM);

    // 1) converts (2 launches)
    {
        int n4 = MTOK * HID_ / 4;
        split_fp16_kernel<<<(n4 + 255) / 256, 256>>>(hidden, hidh, hidl, n4);
    }
    conv_weights_kernel<<<(NW4 + 255) / 256, 256>>>(q_w, k_w, v_w, o_w, w16, ow16);

    // 2) fused QKV projection + RMSNorm + mrope -> fp16 Q/K/V directly
    gemm_qkv<<<dim3(NQKV/128, MTOK/128), 256, GEMM_SMEM3>>>(
        hidh, hidl, w16, cosb, sinb, q_norm_w, k_norm_w);

    // 3) flash attention: QK 1-mma, PV 1-mma, 2 CTAs/SM
    flash_mma<<<dim3(S_ / 128, H_, B_), 256, FLASH_SMEM>>>(at16);

    // 4) O-projection (plain fp16, 1-mma) -> d_out
    gemm_ff<<<dim3(HID_/128, MTOK/128), 256, GEMM_SMEM2>>>(at16, ow16, out, HID_, H_*D_);
}

// round 15
// speedup vs baseline: 2.1978x; 1.0092x over previous
#include <cuda_runtime.h>
#include <cuda_fp16.h>
#include <math.h>
#include <stdint.h>

// Problem constants
#define B_   2
#define S_   2048
#define HID_ 2048
#define H_   16
#define KV_  8
#define D_   128
#define MTOK (B_*S_)   // 4096 tokens
#define NQKV 4096

// ---------------- scratch (device globals) ----------------------------------
__device__ __half g_hid_h[MTOK*HID_], g_hid_l[MTOK*HID_];  // hidden fp16 hi/lo
__device__ __half g_w16 [NQKV*HID_];                        // q|k|v weights fp16
__device__ __half g_ow16[HID_*H_*D_];                       // o_w fp16

// roped/normed operands for flash (single fp16), [B,H|KV,S,D]
__device__ __half g_q16[B_*H_*S_*D_];
__device__ __half g_k16[B_*KV_*S_*D_];
__device__ __half g_v16[B_*KV_*S_*D_];
// attention output (single fp16), [B*S, H*D]
__device__ __half g_at16[MTOK*H_*D_];

// ======================= PTX helpers (sm_80-era) ===========================
__device__ __forceinline__ uint32_t smem_u32(const void* p) {
    return (uint32_t)__cvta_generic_to_shared(p);
}
__device__ __forceinline__ void cpasync16(uint32_t dst, const void* src) {
    asm volatile("cp.async.cg.shared.global [%0], [%1], 16;" :: "r"(dst), "l"(src));
}
#define CP_COMMIT() asm volatile("cp.async.commit_group;" ::: "memory")
#define CP_WAIT1()  asm volatile("cp.async.wait_group 1;" ::: "memory")
#define CP_WAIT0()  asm volatile("cp.async.wait_group 0;" ::: "memory")

__device__ __forceinline__ void ldmx4(uint32_t* r, uint32_t addr) {
    asm volatile("ldmatrix.sync.aligned.m8n8.x4.shared.b16 {%0,%1,%2,%3}, [%4];"
                 : "=r"(r[0]), "=r"(r[1]), "=r"(r[2]), "=r"(r[3]) : "r"(addr));
}
__device__ __forceinline__ void ldmx4t(uint32_t* r, uint32_t addr) {
    asm volatile("ldmatrix.sync.aligned.m8n8.x4.trans.shared.b16 {%0,%1,%2,%3}, [%4];"
                 : "=r"(r[0]), "=r"(r[1]), "=r"(r[2]), "=r"(r[3]) : "r"(addr));
}
__device__ __forceinline__ void ldmx2t(uint32_t* r, uint32_t addr) {
    asm volatile("ldmatrix.sync.aligned.m8n8.x2.trans.shared.b16 {%0,%1}, [%2];"
                 : "=r"(r[0]), "=r"(r[1]) : "r"(addr));
}
__device__ __forceinline__ void mma16816h(float* d, const uint32_t* a, const uint32_t* b) {
    asm volatile("mma.sync.aligned.m16n8k16.row.col.f32.f16.f16.f32 "
                 "{%0,%1,%2,%3}, {%4,%5,%6,%7}, {%8,%9}, {%0,%1,%2,%3};"
                 : "+f"(d[0]), "+f"(d[1]), "+f"(d[2]), "+f"(d[3])
                 : "r"(a[0]), "r"(a[1]), "r"(a[2]), "r"(a[3]), "r"(b[0]), "r"(b[1]));
}
__device__ __forceinline__ uint32_t packh(float x, float y) {
    __half2 t; t.x = __float2half_rn(x); t.y = __float2half_rn(y);
    return *(uint32_t*)&t;
}
__device__ __forceinline__ uint32_t h2exp2_(uint32_t x) {
    uint32_t y;
    asm volatile("ex2.approx.f16x2 %0, %1;" : "=r"(y) : "r"(x));
    return y;
}

// ======================= merged prep: hidden split + weight converts =======
#define HID4 (MTOK*HID_/4)
#define QW4 (H_*D_*HID_/4)
#define KW4 (KV_*D_*HID_/4)
#define OW4 (HID_*H_*D_/4)
#define NW4 (QW4 + 2*KW4 + OW4)
#define PREP4 (HID4 + NW4)

__global__ __launch_bounds__(256)
void prep_kernel(const float* __restrict__ hid,
                 const float* __restrict__ qw, const float* __restrict__ kw,
                 const float* __restrict__ vw, const float* __restrict__ ow,
                 __half* __restrict__ hidh, __half* __restrict__ hidl,
                 __half* __restrict__ w16,  __half* __restrict__ ow16)
{
    int i = blockIdx.x * blockDim.x + threadIdx.x;
    if (i >= PREP4) return;
    if (i < HID4) {
        float4 x = ((const float4*)hid)[i];
        float xs[4] = {x.x, x.y, x.z, x.w};
        __half h[4], l[4];
#pragma unroll
        for (int j = 0; j < 4; j++) {
            h[j] = __float2half_rn(xs[j]);
            l[j] = __float2half_rn(xs[j] - __half2float(h[j]));
        }
        __half2 t;
        t.x = h[0]; t.y = h[1]; ((__half2*)hidh)[i*2 + 0] = t;
        t.x = h[2]; t.y = h[3]; ((__half2*)hidh)[i*2 + 1] = t;
        t.x = l[0]; t.y = l[1]; ((__half2*)hidl)[i*2 + 0] = t;
        t.x = l[2]; t.y = l[3]; ((__half2*)hidl)[i*2 + 1] = t;
    } else {
        int j = i - HID4;
        const float* src; __half* dst; int li;
        if (j < QW4)              { src = qw; dst = w16;                        li = j; }
        else if (j < QW4 + KW4)   { src = kw; dst = w16 + 4*(size_t)QW4;       li = j - QW4; }
        else if (j < QW4 + 2*KW4) { src = vw; dst = w16 + 4*(size_t)(QW4+KW4); li = j - QW4 - KW4; }
        else                      { src = ow; dst = ow16;                       li = j - QW4 - 2*KW4; }
        float4 x = ((const float4*)src)[li];
        uint32_t p0 = packh(x.x, x.y);
        uint32_t p1 = packh(x.z, x.w);
        ((uint32_t*)dst)[li*2 + 0] = p0;
        ((uint32_t*)dst)[li*2 + 1] = p1;
    }
}

// ======================= fp16 asym GEMM + fused norm/rope epilogue =========
#define LDT   40
#define TILE_B (128*LDT*2)
#define STG_B3 (3*TILE_B)
#define GEMM_SMEM3 (2*STG_B3)   // 61440 -> 2 CTAs/SM
#define FT_LD 132

__device__ __forceinline__ int mrope_axis(int d) {
    return d < 21 ? 0 : d < 42 ? 1 : d < 64 ? 2 : d < 85 ? 0 : d < 106 ? 1 : 2;
}

__device__ __forceinline__ void load_stage3(
    uint32_t sbase, int stg,
    const __half* __restrict__ Ah, const __half* __restrict__ Al,
    const __half* __restrict__ Bs,
    int m0, int n0, int K, int k0, int tid)
{
    uint32_t sd = sbase + stg * STG_B3;
#pragma unroll
    for (int i = 0; i < 6; i++) {
        int chunk = i * 256 + tid;
        int tile  = chunk >> 9;
        int idx   = chunk & 511;
        int row   = idx >> 2;
        int cseg  = idx & 3;
        const __half* g = (tile == 0) ? Ah : (tile == 1) ? Al : Bs;
        int grow = ((tile < 2) ? m0 : n0) + row;
        const char* src = (const char*)(g + (size_t)grow * K + k0) + cseg * 16;
        cpasync16(sd + tile * TILE_B + row * 80 + cseg * 16, src);
    }
}

__global__ __launch_bounds__(256, 2)
void gemm_qkv(const __half* __restrict__ Ah, const __half* __restrict__ Al,
              const __half* __restrict__ Bs,
              const float* __restrict__ cosb, const float* __restrict__ sinb,
              const float* __restrict__ qnw,  const float* __restrict__ knw)
{
    extern __shared__ char dsm[];
    const uint32_t sb = smem_u32(dsm);
    const int tid = threadIdx.x;
    const int w = tid >> 5;
    const int l = tid & 31;
    const int wm = (w >> 2) * 64;
    const int wn = (w & 3) * 32;
    const int m0 = blockIdx.y * 128;
    const int n0 = blockIdx.x * 128;
    const int K = HID_;
    const int kiters = K / 32;

    load_stage3(sb, 0, Ah, Al, Bs, m0, n0, K, 0, tid);  CP_COMMIT();
    load_stage3(sb, 1, Ah, Al, Bs, m0, n0, K, 32, tid); CP_COMMIT();

    float acc[16][4];
#pragma unroll
    for (int i = 0; i < 16; i++)
#pragma unroll
        for (int j = 0; j < 4; j++) acc[i][j] = 0.f;

    const int a_row = (l & 15);
    const int a_kof = (l >> 4) * 8;
    const int b_row = (l & 7) + ((l >> 4) & 1) * 8;
    const int b_kof = ((l >> 3) & 1) * 8;

    for (int kt = 0; kt < kiters; kt++) {
        CP_WAIT1();
        __syncthreads();
        const uint32_t st = sb + (kt & 1) * STG_B3;
        const uint32_t sAh = st;
        const uint32_t sAl = st + TILE_B;
        const uint32_t sBs = st + 2 * TILE_B;

#pragma unroll
        for (int ks = 0; ks < 2; ks++) {
            const int kbase = ks * 16;
            uint32_t ah[4][4], al[4][4], bh[2][4];
#pragma unroll
            for (int mi = 0; mi < 4; mi++) {
                uint32_t off = (uint32_t)((wm + mi * 16 + a_row) * 80 + (kbase + a_kof) * 2);
                ldmx4(ah[mi], sAh + off);
                ldmx4(al[mi], sAl + off);
            }
#pragma unroll
            for (int ni2 = 0; ni2 < 2; ni2++) {
                uint32_t off = (uint32_t)((wn + ni2 * 16 + b_row) * 80 + (kbase + b_kof) * 2);
                ldmx4(bh[ni2], sBs + off);
            }
#pragma unroll
            for (int mi = 0; mi < 4; mi++) {
#pragma unroll
                for (int ni = 0; ni < 4; ni++) {
                    const uint32_t* bp = &bh[ni >> 1][(ni & 1) * 2];
                    mma16816h(acc[mi * 4 + ni], ah[mi], bp);
                    mma16816h(acc[mi * 4 + ni], al[mi], bp);
                }
            }
        }
        __syncthreads();
        if (kt + 2 < kiters)
            load_stage3(sb, kt & 1, Ah, Al, Bs, m0, n0, K, (kt + 2) * 32, tid);
        CP_COMMIT();
    }

    // ---- fused epilogue: stage acc in smem, rmsnorm+rope, write fp16 ----
    float* ftile = (float*)dsm;
    const float SC = 0.08838834764831845f;
    const int r0 = l >> 2;

    __half* dbase; const float* nw; bool rope; float scale;
    if (n0 < 2048)      { dbase = g_q16 + (size_t)(n0 >> 7) * S_ * D_;          nw = qnw; rope = true;  scale = SC;  }
    else if (n0 < 3072) { dbase = g_k16 + (size_t)((n0 - 2048) >> 7) * S_ * D_; nw = knw; rope = true;  scale = 1.f; }
    else                { dbase = g_v16 + (size_t)((n0 - 3072) >> 7) * S_ * D_; nw = nullptr; rope = false; scale = 1.f; }
    const int nheads = (n0 < 2048) ? H_ : KV_;

    float4 w4 = make_float4(1.f, 1.f, 1.f, 1.f);
    if (rope) w4 = *(const float4*)(nw + l * 4);

#pragma unroll
    for (int half = 0; half < 2; half++) {
        if ((wm >> 6) == half) {
#pragma unroll
            for (int mi = 0; mi < 4; mi++)
#pragma unroll
                for (int ni = 0; ni < 4; ni++) {
                    int rl = mi * 16 + r0;
                    int cc = wn + ni * 8 + (l & 3) * 2;
                    ftile[rl * FT_LD + cc]       = acc[mi*4+ni][0];
                    ftile[rl * FT_LD + cc + 1]   = acc[mi*4+ni][1];
                    ftile[(rl+8) * FT_LD + cc]   = acc[mi*4+ni][2];
                    ftile[(rl+8) * FT_LD + cc+1] = acc[mi*4+ni][3];
                }
        }
        __syncthreads();

#pragma unroll
        for (int rr = 0; rr < 8; rr++) {
            int row  = w * 8 + rr;
            int mtok = m0 + half * 64 + row;
            int bb = mtok >> 11, ss = mtok & (S_ - 1);
            float4 x4 = *(float4*)&ftile[row * FT_LD + l * 4];
            float out[4] = {x4.x, x4.y, x4.z, x4.w};
            if (rope) {
                float ssum = out[0]*out[0] + out[1]*out[1] + out[2]*out[2] + out[3]*out[3];
#pragma unroll
                for (int o2 = 16; o2 > 0; o2 >>= 1)
                    ssum += __shfl_xor_sync(0xffffffffu, ssum, o2);
                float r = rsqrtf(ssum * (1.0f / 128.0f) + 1e-6f);
                float xn[4];
                xn[0] = out[0]*r*w4.x; xn[1] = out[1]*r*w4.y;
                xn[2] = out[2]*r*w4.z; xn[3] = out[3]*r*w4.w;
                float oth[4];
#pragma unroll
                for (int j = 0; j < 4; j++)
                    oth[j] = __shfl_xor_sync(0xffffffffu, xn[j], 16);
                float sgn = (l < 16) ? -1.f : 1.f;
                int dbidx = l * 4;
#pragma unroll
                for (int j = 0; j < 4; j++) {
                    int d = dbidx + j;
                    int ax = mrope_axis(d);
                    size_t ci = ((size_t)(ax * B_ + bb) * S_ + ss) * D_ + d;
                    out[j] = (xn[j] * cosb[ci] + sgn * oth[j] * sinb[ci]) * scale;
                }
            }
            __half* dst = dbase + ((size_t)bb * nheads * S_ + ss) * D_ + l * 4;
            *(uint32_t*)(dst)     = packh(out[0], out[1]);
            *(uint32_t*)(dst + 2) = packh(out[2], out[3]);
        }
        __syncthreads();
    }
}

// ======================= plain fp16 GEMM (single x single) — O-proj ========
#define STG_B2 (2*TILE_B)
#define GEMM_SMEM2 (3*STG_B2)

__device__ __forceinline__ void load_stage2(
    uint32_t sbase, int stg,
    const __half* __restrict__ As, const __half* __restrict__ Bs,
    int m0, int n0, int K, int k0, int tid)
{
    uint32_t sd = sbase + stg * STG_B2;
#pragma unroll
    for (int i = 0; i < 4; i++) {
        int chunk = i * 256 + tid;
        int tile  = chunk >> 9;
        int idx   = chunk & 511;
        int row   = idx >> 2;
        int cseg  = idx & 3;
        const __half* g = (tile == 0) ? As : Bs;
        int grow = ((tile == 0) ? m0 : n0) + row;
        const char* src = (const char*)(g + (size_t)grow * K + k0) + cseg * 16;
        cpasync16(sd + tile * TILE_B + row * 80 + cseg * 16, src);
    }
}

__global__ __launch_bounds__(256, 2)
void gemm_ff(const __half* __restrict__ As, const __half* __restrict__ Bs,
             float* __restrict__ C, int N, int K)
{
    extern __shared__ char dsm[];
    const uint32_t sb = smem_u32(dsm);
    const int tid = threadIdx.x;
    const int w = tid >> 5;
    const int l = tid & 31;
    const int wm = (w >> 2) * 64;
    const int wn = (w & 3) * 32;
    const int m0 = blockIdx.y * 128;
    const int n0 = blockIdx.x * 128;
    const int kiters = K / 32;

    load_stage2(sb, 0, As, Bs, m0, n0, K, 0, tid);  CP_COMMIT();
    load_stage2(sb, 1, As, Bs, m0, n0, K, 32, tid); CP_COMMIT();

    float acc[16][4];
#pragma unroll
    for (int i = 0; i < 16; i++)
#pragma unroll
        for (int j = 0; j < 4; j++) acc[i][j] = 0.f;

    const int a_row = (l & 15);
    const int a_kof = (l >> 4) * 8;
    const int b_row = (l & 7) + ((l >> 4) & 1) * 8;
    const int b_kof = ((l >> 3) & 1) * 8;

    for (int kt = 0; kt < kiters; kt++) {
        CP_WAIT1();
        __syncthreads();
        const uint32_t st = sb + (kt % 3) * STG_B2;
        const uint32_t sA = st;
        const uint32_t sB = st + TILE_B;

#pragma unroll
        for (int ks = 0; ks < 2; ks++) {
            const int kbase = ks * 16;
            uint32_t af[4][4], bf[2][4];
#pragma unroll
            for (int mi = 0; mi < 4; mi++) {
                uint32_t off = (uint32_t)((wm + mi * 16 + a_row) * 80 + (kbase + a_kof) * 2);
                ldmx4(af[mi], sA + off);
            }
#pragma unroll
            for (int ni2 = 0; ni2 < 2; ni2++) {
                uint32_t off = (uint32_t)((wn + ni2 * 16 + b_row) * 80 + (kbase + b_kof) * 2);
                ldmx4(bf[ni2], sB + off);
            }
#pragma unroll
            for (int mi = 0; mi < 4; mi++) {
#pragma unroll
                for (int ni = 0; ni < 4; ni++) {
                    const uint32_t* bp = &bf[ni >> 1][(ni & 1) * 2];
                    mma16816h(acc[mi * 4 + ni], af[mi], bp);
                }
            }
        }
        __syncthreads();
        if (kt + 2 < kiters)
            load_stage2(sb, (kt + 2) % 3, As, Bs, m0, n0, K, (kt + 2) * 32, tid);
        CP_COMMIT();
    }

#pragma unroll
    for (int mi = 0; mi < 4; mi++) {
#pragma unroll
        for (int ni = 0; ni < 4; ni++) {
            int row = m0 + wm + mi * 16 + (l >> 2);
            int col = n0 + wn + ni * 8 + (l & 3) * 2;
            float* c = C + (size_t)row * N + col;
            float2 v0; v0.x = acc[mi * 4 + ni][0]; v0.y = acc[mi * 4 + ni][1];
            float2 v1; v1.x = acc[mi * 4 + ni][2]; v1.y = acc[mi * 4 + ni][3];
            *(float2*)c = v0;
            *(float2*)(c + 8 * (size_t)N) = v1;
        }
    }
}

// ---------------- causal GQA flash attention (fp16, mma row-sum) ------------
#define FSTR 136
#define QTILE_E (128*FSTR)
#define KTILE_E (64*FSTR)
#define FLASH_SMEM ((QTILE_E + 4*KTILE_E)*2)   // 104448 bytes
#define MASKV (-30000.0f)
#define L2E 1.44269504f

__device__ __forceinline__ void load_kv_stage(
    __half* fsb, int st, int k0,
    const __half* Kp, const __half* Vp, int tid)
{
    __half* kd = fsb + QTILE_E + st * 2 * KTILE_E;
    __half* vd = kd + KTILE_E;
#pragma unroll
    for (int i = 0; i < 4; i++) {
        int c = tid + i * 256;
        int r = c >> 4, cs = c & 15;
        size_t go = (size_t)(k0 + r) * D_ + cs * 8;
        uint32_t so = (uint32_t)(r * FSTR + cs * 8);
        cpasync16(smem_u32(kd + so), Kp + go);
        cpasync16(smem_u32(vd + so), Vp + go);
    }
}

__global__ __launch_bounds__(256, 2)
void flash_mma(__half* __restrict__ O16)
{
    extern __shared__ __half fsh[];
    __half* sQ = fsh;

    const int qt = (int)gridDim.x - 1 - (int)blockIdx.x;  // longest-first
    const int h = blockIdx.y, b = blockIdx.z;
    const int tid = threadIdx.x;
    const int w = tid >> 5;
    const int l = tid & 31;
    const int q0 = qt * 128;

    const __half* Qb = g_q16 + ((size_t)(b * H_ + h) * S_ + q0) * D_;
    const __half* Kb = g_k16 + (size_t)(b * KV_ + (h >> 1)) * S_ * D_;
    const __half* Vb = g_v16 + (size_t)(b * KV_ + (h >> 1)) * S_ * D_;

    // prologue: Q loads; V padding cols 128..135 = {1,0,...,0} for BOTH stages
    // (cp.async only ever writes cols 0..127, so this persists across tiles)
#pragma unroll
    for (int i = 0; i < 8; i++) {
        int c = tid + i * 256;
        int r = c >> 4, cs = c & 15;
        cpasync16(smem_u32(sQ + (uint32_t)(r * FSTR + cs * 8)), Qb + (size_t)r * D_ + cs * 8);
    }
    if (tid < 128) {
        int st2 = tid >> 6, r = tid & 63;
        __half* vd = fsh + QTILE_E + st2 * 2 * KTILE_E + KTILE_E;
        *(uint4*)(vd + r * FSTR + 128) = make_uint4(0x00003C00u, 0u, 0u, 0u);
    }
    load_kv_stage(fsh, 0, 0, Kb, Vb, tid);
    CP_COMMIT();

    float o[16][4];
#pragma unroll
    for (int i = 0; i < 16; i++)
#pragma unroll
        for (int j = 0; j < 4; j++) o[i][j] = 0.f;
    float ls[4] = {0.f, 0.f, 0.f, 0.f};     // row-sum accumulator (tensor-core)
    float mrow[2] = {MASKV, MASKV};

    const int r0 = l >> 2;
    const int a_row = (l & 15);
    const int a_kof = (l >> 4) * 8;
    const int b_row = (l & 7) + ((l >> 4) & 1) * 8;
    const int b_kof = ((l >> 3) & 1) * 8;
    const int v_row = (l & 15);
    const int v_cof = (l >> 4) * 8;
    const int wrow_lo = q0 + 16 * w;
    const int ntiles = 2 * qt + 2;

    for (int t = 0; t < ntiles; t++) {
        const int k0 = t * 64;
        const int st = t & 1;
        if (t + 1 < ntiles) {
            load_kv_stage(fsh, st ^ 1, (t + 1) * 64, Kb, Vb, tid);
            CP_COMMIT();
            CP_WAIT1();
        } else {
            CP_WAIT0();
        }
        __syncthreads();

        if (k0 <= wrow_lo + 15) {
            __half* sK = fsh + QTILE_E + st * 2 * KTILE_E;
            __half* sV = sK + KTILE_E;

            // ---- S = Q K^T ----
            float s[8][4];
#pragma unroll
            for (int i = 0; i < 8; i++)
#pragma unroll
                for (int j = 0; j < 4; j++) s[i][j] = 0.f;

#pragma unroll
            for (int ks = 0; ks < 8; ks++) {
                uint32_t aoff = (uint32_t)((16 * w + a_row) * FSTR + ks * 16 + a_kof) * 2;
                uint32_t qf[4];
                ldmx4(qf, smem_u32(sQ) + aoff);
#pragma unroll
                for (int ng = 0; ng < 4; ng++) {
                    uint32_t boff = (uint32_t)((16 * ng + b_row) * FSTR + ks * 16 + b_kof) * 2;
                    uint32_t kf[4];
                    ldmx4(kf, smem_u32(sK) + boff);
                    mma16816h(s[2*ng],   qf, &kf[0]);
                    mma16816h(s[2*ng+1], qf, &kf[2]);
                }
            }

            // ---- causal mask (boundary tiles) ----
            if (k0 + 63 > wrow_lo) {
                int grow0 = wrow_lo + r0;
                int grow1 = grow0 + 8;
#pragma unroll
                for (int nt = 0; nt < 8; nt++) {
                    int col = k0 + nt * 8 + (l & 3) * 2;
                    if (col > grow0)     s[nt][0] = MASKV;
                    if (col + 1 > grow0) s[nt][1] = MASKV;
                    if (col > grow1)     s[nt][2] = MASKV;
                    if (col + 1 > grow1) s[nt][3] = MASKV;
                }
            }

            // ---- row max + rescale (row-sum handled by tensor core) ----
            float rm0 = MASKV, rm1 = MASKV;
#pragma unroll
            for (int nt = 0; nt < 8; nt++) {
                rm0 = fmaxf(rm0, fmaxf(s[nt][0], s[nt][1]));
                rm1 = fmaxf(rm1, fmaxf(s[nt][2], s[nt][3]));
            }
            rm0 = fmaxf(rm0, __shfl_xor_sync(0xffffffffu, rm0, 1));
            rm0 = fmaxf(rm0, __shfl_xor_sync(0xffffffffu, rm0, 2));
            rm1 = fmaxf(rm1, __shfl_xor_sync(0xffffffffu, rm1, 1));
            rm1 = fmaxf(rm1, __shfl_xor_sync(0xffffffffu, rm1, 2));

            float mn0 = fmaxf(mrow[0], rm0);
            float mn1 = fmaxf(mrow[1], rm1);
            float alpha0 = __expf(mrow[0] - mn0);
            float alpha1 = __expf(mrow[1] - mn1);
            mrow[0] = mn0; mrow[1] = mn1;

#pragma unroll
            for (int nt = 0; nt < 16; nt++) {
                o[nt][0] *= alpha0; o[nt][1] *= alpha0;
                o[nt][2] *= alpha1; o[nt][3] *= alpha1;
            }
            ls[0] *= alpha0; ls[2] *= alpha1;

            // ---- P = exp(S-mn) via f16x2 ex2; PV + row-sum mma ----
            float mnL0 = mn0 * L2E, mnL1 = mn1 * L2E;
#pragma unroll
            for (int ks = 0; ks < 4; ks++) {
                uint32_t pa[4];
                pa[0] = h2exp2_(packh(fmaf(s[2*ks][0],   L2E, -mnL0),
                                      fmaf(s[2*ks][1],   L2E, -mnL0)));
                pa[1] = h2exp2_(packh(fmaf(s[2*ks][2],   L2E, -mnL1),
                                      fmaf(s[2*ks][3],   L2E, -mnL1)));
                pa[2] = h2exp2_(packh(fmaf(s[2*ks+1][0], L2E, -mnL0),
                                      fmaf(s[2*ks+1][1], L2E, -mnL0)));
                pa[3] = h2exp2_(packh(fmaf(s[2*ks+1][2], L2E, -mnL1),
                                      fmaf(s[2*ks+1][3], L2E, -mnL1)));
                // row-sum via ones-column (cols 128..135 of V)
                uint32_t vs2[2];
                ldmx2t(vs2, smem_u32(sV) + (uint32_t)((ks * 16 + v_row) * FSTR + 128) * 2);
                mma16816h(ls, pa, vs2);
#pragma unroll
                for (int dg = 0; dg < 8; dg++) {
                    uint32_t voff = (uint32_t)((ks * 16 + v_row) * FSTR + dg * 16 + v_cof) * 2;
                    uint32_t vf[4];
                    ldmx4t(vf, smem_u32(sV) + voff);
                    mma16816h(o[2*dg],   pa, &vf[0]);
                    mma16816h(o[2*dg+1], pa, &vf[2]);
                }
            }
        }
        __syncthreads();
    }

    // ---- epilogue: fetch row-sums from quad-lane 0, normalize, write fp16 ----
    float lr0 = __shfl_sync(0xffffffffu, ls[0], l & 28);
    float lr1 = __shfl_sync(0xffffffffu, ls[2], l & 28);
    float inv0 = 1.f / lr0;
    float inv1 = 1.f / lr1;
    size_t row0 = (size_t)b * S_ + q0 + 16 * w + r0;
    size_t row1 = row0 + 8;
    int colb = h * D_ + (l & 3) * 2;
#pragma unroll
    for (int nt = 0; nt < 16; nt++) {
        int col = colb + nt * 8;
        *(uint32_t*)(O16 + row0 * (H_*D_) + col) = packh(o[nt][0] * inv0, o[nt][1] * inv0);
        *(uint32_t*)(O16 + row1 * (H_*D_) + col) = packh(o[nt][2] * inv1, o[nt][3] * inv1);
    }
}

// ---------------- launcher ---------------------------------------------------
extern "C" void kernel_launch(void* const* d_in, const int* in_sizes, int n_in,
                              void* d_out, int out_size)
{
    const float* hidden   = (const float*)d_in[0];
    const float* cosb     = (const float*)d_in[1];
    const float* sinb     = (const float*)d_in[2];
    const float* q_w      = (const float*)d_in[3];
    const float* k_w      = (const float*)d_in[4];
    const float* v_w      = (const float*)d_in[5];
    const float* o_w      = (const float*)d_in[6];
    const float* q_norm_w = (const float*)d_in[7];
    const float* k_norm_w = (const float*)d_in[8];
    float* out = (float*)d_out;

    __half *hidh, *hidl, *w16, *ow16, *at16;
    cudaGetSymbolAddress((void**)&hidh, g_hid_h);
    cudaGetSymbolAddress((void**)&hidl, g_hid_l);
    cudaGetSymbolAddress((void**)&w16,  g_w16);
    cudaGetSymbolAddress((void**)&ow16, g_ow16);
    cudaGetSymbolAddress((void**)&at16, g_at16);

    cudaFuncSetAttribute(gemm_qkv, cudaFuncAttributeMaxDynamicSharedMemorySize, GEMM_SMEM3);
    cudaFuncSetAttribute(gemm_ff,  cudaFuncAttributeMaxDynamicSharedMemorySize, GEMM_SMEM2);
    cudaFuncSetAttribute(flash_mma, cudaFuncAttributeMaxDynamicSharedMemorySize, FLASH_SMEM);

    // 1) merged prep: hidden split + all weight converts (one launch)
    prep_kernel<<<(PREP4 + 255) / 256, 256>>>(hidden, q_w, k_w, v_w, o_w,
                                              hidh, hidl, w16, ow16);

    // 2) fused QKV projection + RMSNorm + mrope -> fp16 Q/K/V directly
    gemm_qkv<<<dim3(NQKV/128, MTOK/128), 256, GEMM_SMEM3>>>(
        hidh, hidl, w16, cosb, sinb, q_norm_w, k_norm_w);

    // 3) flash attention: QK 1-mma, PV 1-mma, mma row-sum, f16x2 exp
    flash_mma<<<dim3(S_ / 128, H_, B_), 256, FLASH_SMEM>>>(at16);

    // 4) O-projection (plain fp16, 1-mma) -> d_out
    gemm_ff<<<dim3(HID_/128, MTOK/128), 256, GEMM_SMEM2>>>(at16, ow16, out, HID_, H_*D_);
}

// round 16
// speedup vs baseline: 2.6657x; 1.2129x over previous
#include <cuda_runtime.h>
#include <cuda_fp16.h>
#include <math.h>
#include <stdint.h>

// Problem constants
#define B_   2
#define S_   2048
#define HID_ 2048
#define H_   16
#define KV_  8
#define D_   128
#define MTOK (B_*S_)   // 4096 tokens
#define NQKV 4096

// ---------------- scratch (device globals) ----------------------------------
__device__ __half g_hid16[MTOK*HID_];     // hidden fp16 (single)
__device__ __half g_w16 [NQKV*HID_];      // q|k|v weights fp16
__device__ __half g_ow16[HID_*H_*D_];     // o_w fp16

// roped/normed operands for flash (single fp16), [B,H|KV,S,D]
__device__ __half g_q16[B_*H_*S_*D_];
__device__ __half g_k16[B_*KV_*S_*D_];
__device__ __half g_v16[B_*KV_*S_*D_];
// attention output (single fp16), [B*S, H*D]
__device__ __half g_at16[MTOK*H_*D_];

// ======================= PTX helpers (sm_80-era) ===========================
__device__ __forceinline__ uint32_t smem_u32(const void* p) {
    return (uint32_t)__cvta_generic_to_shared(p);
}
__device__ __forceinline__ void cpasync16(uint32_t dst, const void* src) {
    asm volatile("cp.async.cg.shared.global [%0], [%1], 16;" :: "r"(dst), "l"(src));
}
#define CP_COMMIT() asm volatile("cp.async.commit_group;" ::: "memory")
#define CP_WAIT1()  asm volatile("cp.async.wait_group 1;" ::: "memory")
#define CP_WAIT0()  asm volatile("cp.async.wait_group 0;" ::: "memory")

__device__ __forceinline__ void ldmx4(uint32_t* r, uint32_t addr) {
    asm volatile("ldmatrix.sync.aligned.m8n8.x4.shared.b16 {%0,%1,%2,%3}, [%4];"
                 : "=r"(r[0]), "=r"(r[1]), "=r"(r[2]), "=r"(r[3]) : "r"(addr));
}
__device__ __forceinline__ void ldmx4t(uint32_t* r, uint32_t addr) {
    asm volatile("ldmatrix.sync.aligned.m8n8.x4.trans.shared.b16 {%0,%1,%2,%3}, [%4];"
                 : "=r"(r[0]), "=r"(r[1]), "=r"(r[2]), "=r"(r[3]) : "r"(addr));
}
__device__ __forceinline__ void ldmx2t(uint32_t* r, uint32_t addr) {
    asm volatile("ldmatrix.sync.aligned.m8n8.x2.trans.shared.b16 {%0,%1}, [%2];"
                 : "=r"(r[0]), "=r"(r[1]) : "r"(addr));
}
__device__ __forceinline__ void mma16816h(float* d, const uint32_t* a, const uint32_t* b) {
    asm volatile("mma.sync.aligned.m16n8k16.row.col.f32.f16.f16.f32 "
                 "{%0,%1,%2,%3}, {%4,%5,%6,%7}, {%8,%9}, {%0,%1,%2,%3};"
                 : "+f"(d[0]), "+f"(d[1]), "+f"(d[2]), "+f"(d[3])
                 : "r"(a[0]), "r"(a[1]), "r"(a[2]), "r"(a[3]), "r"(b[0]), "r"(b[1]));
}
__device__ __forceinline__ uint32_t packh(float x, float y) {
    __half2 t; t.x = __float2half_rn(x); t.y = __float2half_rn(y);
    return *(uint32_t*)&t;
}
__device__ __forceinline__ uint32_t h2exp2_(uint32_t x) {
    uint32_t y;
    asm volatile("ex2.approx.f16x2 %0, %1;" : "=r"(y) : "r"(x));
    return y;
}

// ======================= merged prep: all fp32 -> fp16 converts ============
#define HID4 (MTOK*HID_/4)
#define QW4 (H_*D_*HID_/4)
#define KW4 (KV_*D_*HID_/4)
#define OW4 (HID_*H_*D_/4)
#define PREP4 (HID4 + QW4 + 2*KW4 + OW4)

__global__ __launch_bounds__(256)
void prep_kernel(const float* __restrict__ hid,
                 const float* __restrict__ qw, const float* __restrict__ kw,
                 const float* __restrict__ vw, const float* __restrict__ ow,
                 __half* __restrict__ hid16, __half* __restrict__ w16,
                 __half* __restrict__ ow16)
{
    int i = blockIdx.x * blockDim.x + threadIdx.x;
    if (i >= PREP4) return;
    const float* src; __half* dst; int li;
    if (i < HID4)                        { src = hid; dst = hid16;                     li = i; }
    else if (i < HID4 + QW4)             { src = qw;  dst = w16;                       li = i - HID4; }
    else if (i < HID4 + QW4 + KW4)       { src = kw;  dst = w16 + 4*(size_t)QW4;      li = i - HID4 - QW4; }
    else if (i < HID4 + QW4 + 2*KW4)     { src = vw;  dst = w16 + 4*(size_t)(QW4+KW4); li = i - HID4 - QW4 - KW4; }
    else                                 { src = ow;  dst = ow16;                      li = i - HID4 - QW4 - 2*KW4; }
    float4 x = ((const float4*)src)[li];
    ((uint32_t*)dst)[li*2 + 0] = packh(x.x, x.y);
    ((uint32_t*)dst)[li*2 + 1] = packh(x.z, x.w);
}

// ======================= fp16 GEMM + fused norm/rope epilogue — QKV ========
// A=hidden single, B=weights single: 1 MMA per pair. 2-stage, 2 CTAs/SM.
#define LDT   40
#define TILE_B (128*LDT*2)
#define STG_B2 (2*TILE_B)
#define GEMM_SMEMQ (2*STG_B2)   // 40960
#define FT_LD 132

__device__ __forceinline__ int mrope_axis(int d) {
    return d < 21 ? 0 : d < 42 ? 1 : d < 64 ? 2 : d < 85 ? 0 : d < 106 ? 1 : 2;
}

__device__ __forceinline__ void load_stage2g(
    uint32_t sbase, uint32_t stg_off, int stg,
    const __half* __restrict__ As, const __half* __restrict__ Bs,
    int m0, int n0, int K, int k0, int tid)
{
    uint32_t sd = sbase + stg * stg_off;
#pragma unroll
    for (int i = 0; i < 4; i++) {
        int chunk = i * 256 + tid;
        int tile  = chunk >> 9;
        int idx   = chunk & 511;
        int row   = idx >> 2;
        int cseg  = idx & 3;
        const __half* g = (tile == 0) ? As : Bs;
        int grow = ((tile == 0) ? m0 : n0) + row;
        const char* src = (const char*)(g + (size_t)grow * K + k0) + cseg * 16;
        cpasync16(sd + tile * TILE_B + row * 80 + cseg * 16, src);
    }
}

__global__ __launch_bounds__(256, 2)
void gemm_qkv(const __half* __restrict__ As, const __half* __restrict__ Bs,
              const float* __restrict__ cosb, const float* __restrict__ sinb,
              const float* __restrict__ qnw,  const float* __restrict__ knw)
{
    extern __shared__ char dsm[];
    const uint32_t sb = smem_u32(dsm);
    const int tid = threadIdx.x;
    const int w = tid >> 5;
    const int l = tid & 31;
    const int wm = (w >> 2) * 64;
    const int wn = (w & 3) * 32;
    const int m0 = blockIdx.y * 128;
    const int n0 = blockIdx.x * 128;
    const int K = HID_;
    const int kiters = K / 32;

    load_stage2g(sb, STG_B2, 0, As, Bs, m0, n0, K, 0, tid);  CP_COMMIT();
    load_stage2g(sb, STG_B2, 1, As, Bs, m0, n0, K, 32, tid); CP_COMMIT();

    float acc[16][4];
#pragma unroll
    for (int i = 0; i < 16; i++)
#pragma unroll
        for (int j = 0; j < 4; j++) acc[i][j] = 0.f;

    const int a_row = (l & 15);
    const int a_kof = (l >> 4) * 8;
    const int b_row = (l & 7) + ((l >> 4) & 1) * 8;
    const int b_kof = ((l >> 3) & 1) * 8;

    for (int kt = 0; kt < kiters; kt++) {
        CP_WAIT1();
        __syncthreads();
        const uint32_t st = sb + (kt & 1) * STG_B2;
        const uint32_t sA = st;
        const uint32_t sB = st + TILE_B;

#pragma unroll
        for (int ks = 0; ks < 2; ks++) {
            const int kbase = ks * 16;
            uint32_t af[4][4], bf[2][4];
#pragma unroll
            for (int mi = 0; mi < 4; mi++) {
                uint32_t off = (uint32_t)((wm + mi * 16 + a_row) * 80 + (kbase + a_kof) * 2);
                ldmx4(af[mi], sA + off);
            }
#pragma unroll
            for (int ni2 = 0; ni2 < 2; ni2++) {
                uint32_t off = (uint32_t)((wn + ni2 * 16 + b_row) * 80 + (kbase + b_kof) * 2);
                ldmx4(bf[ni2], sB + off);
            }
#pragma unroll
            for (int mi = 0; mi < 4; mi++) {
#pragma unroll
                for (int ni = 0; ni < 4; ni++) {
                    const uint32_t* bp = &bf[ni >> 1][(ni & 1) * 2];
                    mma16816h(acc[mi * 4 + ni], af[mi], bp);
                }
            }
        }
        __syncthreads();
        if (kt + 2 < kiters)
            load_stage2g(sb, STG_B2, kt & 1, As, Bs, m0, n0, K, (kt + 2) * 32, tid);
        CP_COMMIT();
    }

    // ---- fused epilogue: stage acc in smem, rmsnorm+rope, write fp16 ----
    float* ftile = (float*)dsm;
    const float SC = 0.08838834764831845f;
    const int r0 = l >> 2;

    __half* dbase; const float* nw; bool rope; float scale;
    if (n0 < 2048)      { dbase = g_q16 + (size_t)(n0 >> 7) * S_ * D_;          nw = qnw; rope = true;  scale = SC;  }
    else if (n0 < 3072) { dbase = g_k16 + (size_t)((n0 - 2048) >> 7) * S_ * D_; nw = knw; rope = true;  scale = 1.f; }
    else                { dbase = g_v16 + (size_t)((n0 - 3072) >> 7) * S_ * D_; nw = nullptr; rope = false; scale = 1.f; }
    const int nheads = (n0 < 2048) ? H_ : KV_;

    float4 w4 = make_float4(1.f, 1.f, 1.f, 1.f);
    if (rope) w4 = *(const float4*)(nw + l * 4);

#pragma unroll
    for (int half = 0; half < 2; half++) {
        if ((wm >> 6) == half) {
#pragma unroll
            for (int mi = 0; mi < 4; mi++)
#pragma unroll
                for (int ni = 0; ni < 4; ni++) {
                    int rl = mi * 16 + r0;
                    int cc = wn + ni * 8 + (l & 3) * 2;
                    ftile[rl * FT_LD + cc]       = acc[mi*4+ni][0];
                    ftile[rl * FT_LD + cc + 1]   = acc[mi*4+ni][1];
                    ftile[(rl+8) * FT_LD + cc]   = acc[mi*4+ni][2];
                    ftile[(rl+8) * FT_LD + cc+1] = acc[mi*4+ni][3];
                }
        }
        __syncthreads();

#pragma unroll
        for (int rr = 0; rr < 8; rr++) {
            int row  = w * 8 + rr;
            int mtok = m0 + half * 64 + row;
            int bb = mtok >> 11, ss = mtok & (S_ - 1);
            float4 x4 = *(float4*)&ftile[row * FT_LD + l * 4];
            float out[4] = {x4.x, x4.y, x4.z, x4.w};
            if (rope) {
                float ssum = out[0]*out[0] + out[1]*out[1] + out[2]*out[2] + out[3]*out[3];
#pragma unroll
                for (int o2 = 16; o2 > 0; o2 >>= 1)
                    ssum += __shfl_xor_sync(0xffffffffu, ssum, o2);
                float r = rsqrtf(ssum * (1.0f / 128.0f) + 1e-6f);
                float xn[4];
                xn[0] = out[0]*r*w4.x; xn[1] = out[1]*r*w4.y;
                xn[2] = out[2]*r*w4.z; xn[3] = out[3]*r*w4.w;
                float oth[4];
#pragma unroll
                for (int j = 0; j < 4; j++)
                    oth[j] = __shfl_xor_sync(0xffffffffu, xn[j], 16);
                float sgn = (l < 16) ? -1.f : 1.f;
                int dbidx = l * 4;
#pragma unroll
                for (int j = 0; j < 4; j++) {
                    int d = dbidx + j;
                    int ax = mrope_axis(d);
                    size_t ci = ((size_t)(ax * B_ + bb) * S_ + ss) * D_ + d;
                    out[j] = (xn[j] * cosb[ci] + sgn * oth[j] * sinb[ci]) * scale;
                }
            }
            __half* dst = dbase + ((size_t)bb * nheads * S_ + ss) * D_ + l * 4;
            *(uint32_t*)(dst)     = packh(out[0], out[1]);
            *(uint32_t*)(dst + 2) = packh(out[2], out[3]);
        }
        __syncthreads();
    }
}

// ======================= plain fp16 GEMM — O-proj ==========================
#define GEMM_SMEM2 (3*STG_B2)

__global__ __launch_bounds__(256, 2)
void gemm_ff(const __half* __restrict__ As, const __half* __restrict__ Bs,
             float* __restrict__ C, int N, int K)
{
    extern __shared__ char dsm[];
    const uint32_t sb = smem_u32(dsm);
    const int tid = threadIdx.x;
    const int w = tid >> 5;
    const int l = tid & 31;
    const int wm = (w >> 2) * 64;
    const int wn = (w & 3) * 32;
    const int m0 = blockIdx.y * 128;
    const int n0 = blockIdx.x * 128;
    const int kiters = K / 32;

    load_stage2g(sb, STG_B2, 0, As, Bs, m0, n0, K, 0, tid);  CP_COMMIT();
    load_stage2g(sb, STG_B2, 1, As, Bs, m0, n0, K, 32, tid); CP_COMMIT();

    float acc[16][4];
#pragma unroll
    for (int i = 0; i < 16; i++)
#pragma unroll
        for (int j = 0; j < 4; j++) acc[i][j] = 0.f;

    const int a_row = (l & 15);
    const int a_kof = (l >> 4) * 8;
    const int b_row = (l & 7) + ((l >> 4) & 1) * 8;
    const int b_kof = ((l >> 3) & 1) * 8;

    for (int kt = 0; kt < kiters; kt++) {
        CP_WAIT1();
        __syncthreads();
        const uint32_t st = sb + ((kt % 3) % 2 == kt % 3 ? 0 : 0) * 0 + (kt % 3) * STG_B2;
        const uint32_t sA = st;
        const uint32_t sB = st + TILE_B;

#pragma unroll
        for (int ks = 0; ks < 2; ks++) {
            const int kbase = ks * 16;
            uint32_t af[4][4], bf[2][4];
#pragma unroll
            for (int mi = 0; mi < 4; mi++) {
                uint32_t off = (uint32_t)((wm + mi * 16 + a_row) * 80 + (kbase + a_kof) * 2);
                ldmx4(af[mi], sA + off);
            }
#pragma unroll
            for (int ni2 = 0; ni2 < 2; ni2++) {
                uint32_t off = (uint32_t)((wn + ni2 * 16 + b_row) * 80 + (kbase + b_kof) * 2);
                ldmx4(bf[ni2], sB + off);
            }
#pragma unroll
            for (int mi = 0; mi < 4; mi++) {
#pragma unroll
                for (int ni = 0; ni < 4; ni++) {
                    const uint32_t* bp = &bf[ni >> 1][(ni & 1) * 2];
                    mma16816h(acc[mi * 4 + ni], af[mi], bp);
                }
            }
        }
        __syncthreads();
        if (kt + 2 < kiters)
            load_stage2g(sb, STG_B2, (kt + 2) % 3, As, Bs, m0, n0, K, (kt + 2) * 32, tid);
        CP_COMMIT();
    }

#pragma unroll
    for (int mi = 0; mi < 4; mi++) {
#pragma unroll
        for (int ni = 0; ni < 4; ni++) {
            int row = m0 + wm + mi * 16 + (l >> 2);
            int col = n0 + wn + ni * 8 + (l & 3) * 2;
            float* c = C + (size_t)row * N + col;
            float2 v0; v0.x = acc[mi * 4 + ni][0]; v0.y = acc[mi * 4 + ni][1];
            float2 v1; v1.x = acc[mi * 4 + ni][2]; v1.y = acc[mi * 4 + ni][3];
            *(float2*)c = v0;
            *(float2*)(c + 8 * (size_t)N) = v1;
        }
    }
}

// ---------------- causal GQA flash attention (fp16, mma row-sum) ------------
#define FSTR 136
#define QTILE_E (128*FSTR)
#define KTILE_E (64*FSTR)
#define FLASH_SMEM ((QTILE_E + 4*KTILE_E)*2)   // 104448 bytes
#define MASKV (-30000.0f)
#define L2E 1.44269504f

__device__ __forceinline__ void load_kv_stage(
    __half* fsb, int st, int k0,
    const __half* Kp, const __half* Vp, int tid)
{
    __half* kd = fsb + QTILE_E + st * 2 * KTILE_E;
    __half* vd = kd + KTILE_E;
#pragma unroll
    for (int i = 0; i < 4; i++) {
        int c = tid + i * 256;
        int r = c >> 4, cs = c & 15;
        size_t go = (size_t)(k0 + r) * D_ + cs * 8;
        uint32_t so = (uint32_t)(r * FSTR + cs * 8);
        cpasync16(smem_u32(kd + so), Kp + go);
        cpasync16(smem_u32(vd + so), Vp + go);
    }
}

__global__ __launch_bounds__(256, 2)
void flash_mma(__half* __restrict__ O16)
{
    extern __shared__ __half fsh[];
    __half* sQ = fsh;

    const int qt = (int)gridDim.x - 1 - (int)blockIdx.x;  // longest-first
    const int h = blockIdx.y, b = blockIdx.z;
    const int tid = threadIdx.x;
    const int w = tid >> 5;
    const int l = tid & 31;
    const int q0 = qt * 128;

    const __half* Qb = g_q16 + ((size_t)(b * H_ + h) * S_ + q0) * D_;
    const __half* Kb = g_k16 + (size_t)(b * KV_ + (h >> 1)) * S_ * D_;
    const __half* Vb = g_v16 + (size_t)(b * KV_ + (h >> 1)) * S_ * D_;

#pragma unroll
    for (int i = 0; i < 8; i++) {
        int c = tid + i * 256;
        int r = c >> 4, cs = c & 15;
        cpasync16(smem_u32(sQ + (uint32_t)(r * FSTR + cs * 8)), Qb + (size_t)r * D_ + cs * 8);
    }
    if (tid < 128) {
        int st2 = tid >> 6, r = tid & 63;
        __half* vd = fsh + QTILE_E + st2 * 2 * KTILE_E + KTILE_E;
        *(uint4*)(vd + r * FSTR + 128) = make_uint4(0x00003C00u, 0u, 0u, 0u);
    }
    load_kv_stage(fsh, 0, 0, Kb, Vb, tid);
    CP_COMMIT();

    float o[16][4];
#pragma unroll
    for (int i = 0; i < 16; i++)
#pragma unroll
        for (int j = 0; j < 4; j++) o[i][j] = 0.f;
    float ls[4] = {0.f, 0.f, 0.f, 0.f};
    float mrow[2] = {MASKV, MASKV};

    const int r0 = l >> 2;
    const int a_row = (l & 15);
    const int a_kof = (l >> 4) * 8;
    const int b_row = (l & 7) + ((l >> 4) & 1) * 8;
    const int b_kof = ((l >> 3) & 1) * 8;
    const int v_row = (l & 15);
    const int v_cof = (l >> 4) * 8;
    const int wrow_lo = q0 + 16 * w;
    const int ntiles = 2 * qt + 2;

    for (int t = 0; t < ntiles; t++) {
        const int k0 = t * 64;
        const int st = t & 1;
        if (t + 1 < ntiles) {
            load_kv_stage(fsh, st ^ 1, (t + 1) * 64, Kb, Vb, tid);
            CP_COMMIT();
            CP_WAIT1();
        } else {
            CP_WAIT0();
        }
        __syncthreads();

        if (k0 <= wrow_lo + 15) {
            __half* sK = fsh + QTILE_E + st * 2 * KTILE_E;
            __half* sV = sK + KTILE_E;

            float s[8][4];
#pragma unroll
            for (int i = 0; i < 8; i++)
#pragma unroll
                for (int j = 0; j < 4; j++) s[i][j] = 0.f;

#pragma unroll
            for (int ks = 0; ks < 8; ks++) {
                uint32_t aoff = (uint32_t)((16 * w + a_row) * FSTR + ks * 16 + a_kof) * 2;
                uint32_t qf[4];
                ldmx4(qf, smem_u32(sQ) + aoff);
#pragma unroll
                for (int ng = 0; ng < 4; ng++) {
                    uint32_t boff = (uint32_t)((16 * ng + b_row) * FSTR + ks * 16 + b_kof) * 2;
                    uint32_t kf[4];
                    ldmx4(kf, smem_u32(sK) + boff);
                    mma16816h(s[2*ng],   qf, &kf[0]);
                    mma16816h(s[2*ng+1], qf, &kf[2]);
                }
            }

            if (k0 + 63 > wrow_lo) {
                int grow0 = wrow_lo + r0;
                int grow1 = grow0 + 8;
#pragma unroll
                for (int nt = 0; nt < 8; nt++) {
                    int col = k0 + nt * 8 + (l & 3) * 2;
                    if (col > grow0)     s[nt][0] = MASKV;
                    if (col + 1 > grow0) s[nt][1] = MASKV;
                    if (col > grow1)     s[nt][2] = MASKV;
                    if (col + 1 > grow1) s[nt][3] = MASKV;
                }
            }

            float rm0 = MASKV, rm1 = MASKV;
#pragma unroll
            for (int nt = 0; nt < 8; nt++) {
                rm0 = fmaxf(rm0, fmaxf(s[nt][0], s[nt][1]));
                rm1 = fmaxf(rm1, fmaxf(s[nt][2], s[nt][3]));
            }
            rm0 = fmaxf(rm0, __shfl_xor_sync(0xffffffffu, rm0, 1));
            rm0 = fmaxf(rm0, __shfl_xor_sync(0xffffffffu, rm0, 2));
            rm1 = fmaxf(rm1, __shfl_xor_sync(0xffffffffu, rm1, 1));
            rm1 = fmaxf(rm1, __shfl_xor_sync(0xffffffffu, rm1, 2));

            float mn0 = fmaxf(mrow[0], rm0);
            float mn1 = fmaxf(mrow[1], rm1);
            float alpha0 = __expf(mrow[0] - mn0);
            float alpha1 = __expf(mrow[1] - mn1);
            mrow[0] = mn0; mrow[1] = mn1;

#pragma unroll
            for (int nt = 0; nt < 16; nt++) {
                o[nt][0] *= alpha0; o[nt][1] *= alpha0;
                o[nt][2] *= alpha1; o[nt][3] *= alpha1;
            }
            ls[0] *= alpha0; ls[2] *= alpha1;

            float mnL0 = mn0 * L2E, mnL1 = mn1 * L2E;
#pragma unroll
            for (int ks = 0; ks < 4; ks++) {
                uint32_t pa[4];
                pa[0] = h2exp2_(packh(fmaf(s[2*ks][0],   L2E, -mnL0),
                                      fmaf(s[2*ks][1],   L2E, -mnL0)));
                pa[1] = h2exp2_(packh(fmaf(s[2*ks][2],   L2E, -mnL1),
                                      fmaf(s[2*ks][3],   L2E, -mnL1)));
                pa[2] = h2exp2_(packh(fmaf(s[2*ks+1][0], L2E, -mnL0),
                                      fmaf(s[2*ks+1][1], L2E, -mnL0)));
                pa[3] = h2exp2_(packh(fmaf(s[2*ks+1][2], L2E, -mnL1),
                                      fmaf(s[2*ks+1][3], L2E, -mnL1)));
                uint32_t vs2[2];
                ldmx2t(vs2, smem_u32(sV) + (uint32_t)((ks * 16 + v_row) * FSTR + 128) * 2);
                mma16816h(ls, pa, vs2);
#pragma unroll
                for (int dg = 0; dg < 8; dg++) {
                    uint32_t voff = (uint32_t)((ks * 16 + v_row) * FSTR + dg * 16 + v_cof) * 2;
                    uint32_t vf[4];
                    ldmx4t(vf, smem_u32(sV) + voff);
                    mma16816h(o[2*dg],   pa, &vf[0]);
                    mma16816h(o[2*dg+1], pa, &vf[2]);
                }
            }
        }
        __syncthreads();
    }

    float lr0 = __shfl_sync(0xffffffffu, ls[0], l & 28);
    float lr1 = __shfl_sync(0xffffffffu, ls[2], l & 28);
    float inv0 = 1.f / lr0;
    float inv1 = 1.f / lr1;
    size_t row0 = (size_t)b * S_ + q0 + 16 * w + r0;
    size_t row1 = row0 + 8;
    int colb = h * D_ + (l & 3) * 2;
#pragma unroll
    for (int nt = 0; nt < 16; nt++) {
        int col = colb + nt * 8;
        *(uint32_t*)(O16 + row0 * (H_*D_) + col) = packh(o[nt][0] * inv0, o[nt][1] * inv0);
        *(uint32_t*)(O16 + row1 * (H_*D_) + col) = packh(o[nt][2] * inv1, o[nt][3] * inv1);
    }
}

// ---------------- launcher ---------------------------------------------------
extern "C" void kernel_launch(void* const* d_in, const int* in_sizes, int n_in,
                              void* d_out, int out_size)
{
    const float* hidden   = (const float*)d_in[0];
    const float* cosb     = (const float*)d_in[1];
    const float* sinb     = (const float*)d_in[2];
    const float* q_w      = (const float*)d_in[3];
    const float* k_w      = (const float*)d_in[4];
    const float* v_w      = (const float*)d_in[5];
    const float* o_w      = (const float*)d_in[6];
    const float* q_norm_w = (const float*)d_in[7];
    const float* k_norm_w = (const float*)d_in[8];
    float* out = (float*)d_out;

    __half *hid16, *w16, *ow16, *at16;
    cudaGetSymbolAddress((void**)&hid16, g_hid16);
    cudaGetSymbolAddress((void**)&w16,   g_w16);
    cudaGetSymbolAddress((void**)&ow16,  g_ow16);
    cudaGetSymbolAddress((void**)&at16,  g_at16);

    cudaFuncSetAttribute(gemm_qkv, cudaFuncAttributeMaxDynamicSharedMemorySize, GEMM_SMEMQ);
    cudaFuncSetAttribute(gemm_ff,  cudaFuncAttributeMaxDynamicSharedMemorySize, GEMM_SMEM2);
    cudaFuncSetAttribute(flash_mma, cudaFuncAttributeMaxDynamicSharedMemorySize, FLASH_SMEM);

    // 1) merged prep: all fp32 -> fp16 converts (one launch)
    prep_kernel<<<(PREP4 + 255) / 256, 256>>>(hidden, q_w, k_w, v_w, o_w,
                                              hid16, w16, ow16);

    // 2) fused QKV projection (1-mma) + RMSNorm + mrope -> fp16 Q/K/V
    gemm_qkv<<<dim3(NQKV/128, MTOK/128), 256, GEMM_SMEMQ>>>(
        hid16, w16, cosb, sinb, q_norm_w, k_norm_w);

    // 3) flash attention
    flash_mma<<<dim3(S_ / 128, H_, B_), 256, FLASH_SMEM>>>(at16);

    // 4) O-projection -> d_out
    gemm_ff<<<dim3(HID_/128, MTOK/128), 256, GEMM_SMEM2>>>(at16, ow16, out, HID_, H_*D_);
}

// round 17
// speedup vs baseline: 2.7737x; 1.0405x over previous
#include <cuda_runtime.h>
#include <cuda_fp16.h>
#include <math.h>
#include <stdint.h>

// Problem constants
#define B_   2
#define S_   2048
#define HID_ 2048
#define H_   16
#define KV_  8
#define D_   128
#define MTOK (B_*S_)   // 4096 tokens
#define NQKV 4096

// ---------------- scratch (device globals) ----------------------------------
__device__ __half g_hid16[MTOK*HID_];     // hidden fp16 (single)
__device__ __half g_w16 [NQKV*HID_];      // q|k|v weights fp16
__device__ __half g_ow16[HID_*H_*D_];     // o_w fp16

// roped/normed operands for flash (single fp16), [B,H|KV,S,D]
__device__ __half g_q16[B_*H_*S_*D_];
__device__ __half g_k16[B_*KV_*S_*D_];
__device__ __half g_v16[B_*KV_*S_*D_];
// attention output (single fp16), [B*S, H*D]
__device__ __half g_at16[MTOK*H_*D_];

// ======================= PTX helpers (sm_80-era) ===========================
__device__ __forceinline__ uint32_t smem_u32(const void* p) {
    return (uint32_t)__cvta_generic_to_shared(p);
}
__device__ __forceinline__ void cpasync16(uint32_t dst, const void* src) {
    asm volatile("cp.async.cg.shared.global [%0], [%1], 16;" :: "r"(dst), "l"(src));
}
#define CP_COMMIT() asm volatile("cp.async.commit_group;" ::: "memory")
#define CP_WAIT1()  asm volatile("cp.async.wait_group 1;" ::: "memory")
#define CP_WAIT0()  asm volatile("cp.async.wait_group 0;" ::: "memory")

__device__ __forceinline__ void ldmx4(uint32_t* r, uint32_t addr) {
    asm volatile("ldmatrix.sync.aligned.m8n8.x4.shared.b16 {%0,%1,%2,%3}, [%4];"
                 : "=r"(r[0]), "=r"(r[1]), "=r"(r[2]), "=r"(r[3]) : "r"(addr));
}
__device__ __forceinline__ void ldmx4t(uint32_t* r, uint32_t addr) {
    asm volatile("ldmatrix.sync.aligned.m8n8.x4.trans.shared.b16 {%0,%1,%2,%3}, [%4];"
                 : "=r"(r[0]), "=r"(r[1]), "=r"(r[2]), "=r"(r[3]) : "r"(addr));
}
__device__ __forceinline__ void ldmx2t(uint32_t* r, uint32_t addr) {
    asm volatile("ldmatrix.sync.aligned.m8n8.x2.trans.shared.b16 {%0,%1}, [%2];"
                 : "=r"(r[0]), "=r"(r[1]) : "r"(addr));
}
__device__ __forceinline__ void mma16816h(float* d, const uint32_t* a, const uint32_t* b) {
    asm volatile("mma.sync.aligned.m16n8k16.row.col.f32.f16.f16.f32 "
                 "{%0,%1,%2,%3}, {%4,%5,%6,%7}, {%8,%9}, {%0,%1,%2,%3};"
                 : "+f"(d[0]), "+f"(d[1]), "+f"(d[2]), "+f"(d[3])
                 : "r"(a[0]), "r"(a[1]), "r"(a[2]), "r"(a[3]), "r"(b[0]), "r"(b[1]));
}
__device__ __forceinline__ uint32_t packh(float x, float y) {
    __half2 t; t.x = __float2half_rn(x); t.y = __float2half_rn(y);
    return *(uint32_t*)&t;
}
__device__ __forceinline__ uint32_t h2exp2_(uint32_t x) {
    uint32_t y;
    asm volatile("ex2.approx.f16x2 %0, %1;" : "=r"(y) : "r"(x));
    return y;
}

// ======================= merged prep: all fp32 -> fp16 converts ============
#define HID4 (MTOK*HID_/4)
#define QW4 (H_*D_*HID_/4)
#define KW4 (KV_*D_*HID_/4)
#define OW4 (HID_*H_*D_/4)
#define PREP4 (HID4 + QW4 + 2*KW4 + OW4)

__global__ __launch_bounds__(256)
void prep_kernel(const float* __restrict__ hid,
                 const float* __restrict__ qw, const float* __restrict__ kw,
                 const float* __restrict__ vw, const float* __restrict__ ow,
                 __half* __restrict__ hid16, __half* __restrict__ w16,
                 __half* __restrict__ ow16)
{
    int i = blockIdx.x * blockDim.x + threadIdx.x;
    if (i >= PREP4) return;
    const float* src; __half* dst; int li;
    if (i < HID4)                        { src = hid; dst = hid16;                     li = i; }
    else if (i < HID4 + QW4)             { src = qw;  dst = w16;                       li = i - HID4; }
    else if (i < HID4 + QW4 + KW4)       { src = kw;  dst = w16 + 4*(size_t)QW4;      li = i - HID4 - QW4; }
    else if (i < HID4 + QW4 + 2*KW4)     { src = vw;  dst = w16 + 4*(size_t)(QW4+KW4); li = i - HID4 - QW4 - KW4; }
    else                                 { src = ow;  dst = ow16;                      li = i - HID4 - QW4 - 2*KW4; }
    float4 x = ((const float4*)src)[li];
    ((uint32_t*)dst)[li*2 + 0] = packh(x.x, x.y);
    ((uint32_t*)dst)[li*2 + 1] = packh(x.z, x.w);
}

// ======================= fp16 GEMM + fused norm/rope epilogue — QKV ========
// 3-stage pipeline, ONE barrier per k-iteration, 2 CTAs/SM.
#define LDT   40
#define TILE_B (128*LDT*2)
#define STG_B2 (2*TILE_B)
#define GEMM_SMEMQ (3*STG_B2)   // 61440
#define FT_LD 132

__device__ __forceinline__ int mrope_axis(int d) {
    return d < 21 ? 0 : d < 42 ? 1 : d < 64 ? 2 : d < 85 ? 0 : d < 106 ? 1 : 2;
}

__device__ __forceinline__ void load_stage2g(
    uint32_t sbase, int stg,
    const __half* __restrict__ As, const __half* __restrict__ Bs,
    int m0, int n0, int K, int k0, int tid)
{
    uint32_t sd = sbase + stg * STG_B2;
#pragma unroll
    for (int i = 0; i < 4; i++) {
        int chunk = i * 256 + tid;
        int tile  = chunk >> 9;
        int idx   = chunk & 511;
        int row   = idx >> 2;
        int cseg  = idx & 3;
        const __half* g = (tile == 0) ? As : Bs;
        int grow = ((tile == 0) ? m0 : n0) + row;
        const char* src = (const char*)(g + (size_t)grow * K + k0) + cseg * 16;
        cpasync16(sd + tile * TILE_B + row * 80 + cseg * 16, src);
    }
}

// shared 3-stage single-barrier mainloop body (compute stage kt%3)
#define GEMM_MAINLOOP(SBASE, AS, BS, M0, N0, KK, KITERS, TIDV)                  \
    for (int kt = 0; kt < (KITERS); kt++) {                                     \
        CP_WAIT1();                                                             \
        __syncthreads();                                                        \
        const uint32_t st = (SBASE) + (kt % 3) * STG_B2;                        \
        const uint32_t sA = st;                                                 \
        const uint32_t sB = st + TILE_B;                                        \
        _Pragma("unroll")                                                       \
        for (int ks = 0; ks < 2; ks++) {                                        \
            const int kbase = ks * 16;                                          \
            uint32_t af[4][4], bf[2][4];                                        \
            _Pragma("unroll")                                                   \
            for (int mi = 0; mi < 4; mi++) {                                    \
                uint32_t off = (uint32_t)((wm + mi * 16 + a_row) * 80 + (kbase + a_kof) * 2); \
                ldmx4(af[mi], sA + off);                                        \
            }                                                                   \
            _Pragma("unroll")                                                   \
            for (int ni2 = 0; ni2 < 2; ni2++) {                                 \
                uint32_t off = (uint32_t)((wn + ni2 * 16 + b_row) * 80 + (kbase + b_kof) * 2); \
                ldmx4(bf[ni2], sB + off);                                       \
            }                                                                   \
            _Pragma("unroll")                                                   \
            for (int mi = 0; mi < 4; mi++) {                                    \
                _Pragma("unroll")                                               \
                for (int ni = 0; ni < 4; ni++) {                                \
                    const uint32_t* bp = &bf[ni >> 1][(ni & 1) * 2];            \
                    mma16816h(acc[mi * 4 + ni], af[mi], bp);                    \
                }                                                               \
            }                                                                   \
        }                                                                       \
        if (kt + 2 < (KITERS))                                                  \
            load_stage2g((SBASE), (kt + 2) % 3, (AS), (BS), (M0), (N0), (KK), (kt + 2) * 32, (TIDV)); \
        CP_COMMIT();                                                            \
    }

__global__ __launch_bounds__(256, 2)
void gemm_qkv(const __half* __restrict__ As, const __half* __restrict__ Bs,
              const float* __restrict__ cosb, const float* __restrict__ sinb,
              const float* __restrict__ qnw,  const float* __restrict__ knw)
{
    extern __shared__ char dsm[];
    const uint32_t sb = smem_u32(dsm);
    const int tid = threadIdx.x;
    const int w = tid >> 5;
    const int l = tid & 31;
    const int wm = (w >> 2) * 64;
    const int wn = (w & 3) * 32;
    const int m0 = blockIdx.y * 128;
    const int n0 = blockIdx.x * 128;
    const int K = HID_;
    const int kiters = K / 32;

    load_stage2g(sb, 0, As, Bs, m0, n0, K, 0, tid);  CP_COMMIT();
    load_stage2g(sb, 1, As, Bs, m0, n0, K, 32, tid); CP_COMMIT();

    float acc[16][4];
#pragma unroll
    for (int i = 0; i < 16; i++)
#pragma unroll
        for (int j = 0; j < 4; j++) acc[i][j] = 0.f;

    const int a_row = (l & 15);
    const int a_kof = (l >> 4) * 8;
    const int b_row = (l & 7) + ((l >> 4) & 1) * 8;
    const int b_kof = ((l >> 3) & 1) * 8;

    GEMM_MAINLOOP(sb, As, Bs, m0, n0, K, kiters, tid)

    // all warps must finish compute before ftile aliases stage smem
    CP_WAIT0();
    __syncthreads();

    // ---- fused epilogue: stage acc in smem, rmsnorm+rope, write fp16 ----
    float* ftile = (float*)dsm;
    const float SC = 0.08838834764831845f;
    const int r0 = l >> 2;

    __half* dbase; const float* nw; bool rope; float scale;
    if (n0 < 2048)      { dbase = g_q16 + (size_t)(n0 >> 7) * S_ * D_;          nw = qnw; rope = true;  scale = SC;  }
    else if (n0 < 3072) { dbase = g_k16 + (size_t)((n0 - 2048) >> 7) * S_ * D_; nw = knw; rope = true;  scale = 1.f; }
    else                { dbase = g_v16 + (size_t)((n0 - 3072) >> 7) * S_ * D_; nw = nullptr; rope = false; scale = 1.f; }
    const int nheads = (n0 < 2048) ? H_ : KV_;

    float4 w4 = make_float4(1.f, 1.f, 1.f, 1.f);
    if (rope) w4 = *(const float4*)(nw + l * 4);

#pragma unroll
    for (int half = 0; half < 2; half++) {
        if ((wm >> 6) == half) {
#pragma unroll
            for (int mi = 0; mi < 4; mi++)
#pragma unroll
                for (int ni = 0; ni < 4; ni++) {
                    int rl = mi * 16 + r0;
                    int cc = wn + ni * 8 + (l & 3) * 2;
                    ftile[rl * FT_LD + cc]       = acc[mi*4+ni][0];
                    ftile[rl * FT_LD + cc + 1]   = acc[mi*4+ni][1];
                    ftile[(rl+8) * FT_LD + cc]   = acc[mi*4+ni][2];
                    ftile[(rl+8) * FT_LD + cc+1] = acc[mi*4+ni][3];
                }
        }
        __syncthreads();

#pragma unroll
        for (int rr = 0; rr < 8; rr++) {
            int row  = w * 8 + rr;
            int mtok = m0 + half * 64 + row;
            int bb = mtok >> 11, ss = mtok & (S_ - 1);
            float4 x4 = *(float4*)&ftile[row * FT_LD + l * 4];
            float out[4] = {x4.x, x4.y, x4.z, x4.w};
            if (rope) {
                float ssum = out[0]*out[0] + out[1]*out[1] + out[2]*out[2] + out[3]*out[3];
#pragma unroll
                for (int o2 = 16; o2 > 0; o2 >>= 1)
                    ssum += __shfl_xor_sync(0xffffffffu, ssum, o2);
                float r = rsqrtf(ssum * (1.0f / 128.0f) + 1e-6f);
                float xn[4];
                xn[0] = out[0]*r*w4.x; xn[1] = out[1]*r*w4.y;
                xn[2] = out[2]*r*w4.z; xn[3] = out[3]*r*w4.w;
                float oth[4];
#pragma unroll
                for (int j = 0; j < 4; j++)
                    oth[j] = __shfl_xor_sync(0xffffffffu, xn[j], 16);
                float sgn = (l < 16) ? -1.f : 1.f;
                int dbidx = l * 4;
#pragma unroll
                for (int j = 0; j < 4; j++) {
                    int d = dbidx + j;
                    int ax = mrope_axis(d);
                    size_t ci = ((size_t)(ax * B_ + bb) * S_ + ss) * D_ + d;
                    out[j] = (xn[j] * cosb[ci] + sgn * oth[j] * sinb[ci]) * scale;
                }
            }
            __half* dst = dbase + ((size_t)bb * nheads * S_ + ss) * D_ + l * 4;
            *(uint32_t*)(dst)     = packh(out[0], out[1]);
            *(uint32_t*)(dst + 2) = packh(out[2], out[3]);
        }
        __syncthreads();
    }
}

// ======================= plain fp16 GEMM — O-proj ==========================
#define GEMM_SMEM2 (3*STG_B2)

__global__ __launch_bounds__(256, 2)
void gemm_ff(const __half* __restrict__ As, const __half* __restrict__ Bs,
             float* __restrict__ C, int N, int K)
{
    extern __shared__ char dsm[];
    const uint32_t sb = smem_u32(dsm);
    const int tid = threadIdx.x;
    const int w = tid >> 5;
    const int l = tid & 31;
    const int wm = (w >> 2) * 64;
    const int wn = (w & 3) * 32;
    const int m0 = blockIdx.y * 128;
    const int n0 = blockIdx.x * 128;
    const int kiters = K / 32;

    load_stage2g(sb, 0, As, Bs, m0, n0, K, 0, tid);  CP_COMMIT();
    load_stage2g(sb, 1, As, Bs, m0, n0, K, 32, tid); CP_COMMIT();

    float acc[16][4];
#pragma unroll
    for (int i = 0; i < 16; i++)
#pragma unroll
        for (int j = 0; j < 4; j++) acc[i][j] = 0.f;

    const int a_row = (l & 15);
    const int a_kof = (l >> 4) * 8;
    const int b_row = (l & 7) + ((l >> 4) & 1) * 8;
    const int b_kof = ((l >> 3) & 1) * 8;

    GEMM_MAINLOOP(sb, As, Bs, m0, n0, K, kiters, tid)

#pragma unroll
    for (int mi = 0; mi < 4; mi++) {
#pragma unroll
        for (int ni = 0; ni < 4; ni++) {
            int row = m0 + wm + mi * 16 + (l >> 2);
            int col = n0 + wn + ni * 8 + (l & 3) * 2;
            float* c = C + (size_t)row * N + col;
            float2 v0; v0.x = acc[mi * 4 + ni][0]; v0.y = acc[mi * 4 + ni][1];
            float2 v1; v1.x = acc[mi * 4 + ni][2]; v1.y = acc[mi * 4 + ni][3];
            *(float2*)c = v0;
            *(float2*)(c + 8 * (size_t)N) = v1;
        }
    }
}

// ---------------- causal GQA flash attention (fp16, mma row-sum) ------------
#define FSTR 136
#define QTILE_E (128*FSTR)
#define KTILE_E (64*FSTR)
#define FLASH_SMEM ((QTILE_E + 4*KTILE_E)*2)   // 104448 bytes
#define MASKV (-30000.0f)
#define L2E 1.44269504f

__device__ __forceinline__ void load_kv_stage(
    __half* fsb, int st, int k0,
    const __half* Kp, const __half* Vp, int tid)
{
    __half* kd = fsb + QTILE_E + st * 2 * KTILE_E;
    __half* vd = kd + KTILE_E;
#pragma unroll
    for (int i = 0; i < 4; i++) {
        int c = tid + i * 256;
        int r = c >> 4, cs = c & 15;
        size_t go = (size_t)(k0 + r) * D_ + cs * 8;
        uint32_t so = (uint32_t)(r * FSTR + cs * 8);
        cpasync16(smem_u32(kd + so), Kp + go);
        cpasync16(smem_u32(vd + so), Vp + go);
    }
}

__global__ __launch_bounds__(256, 2)
void flash_mma(__half* __restrict__ O16)
{
    extern __shared__ __half fsh[];
    __half* sQ = fsh;

    const int qt = (int)gridDim.x - 1 - (int)blockIdx.x;  // longest-first
    const int h = blockIdx.y, b = blockIdx.z;
    const int tid = threadIdx.x;
    const int w = tid >> 5;
    const int l = tid & 31;
    const int q0 = qt * 128;

    const __half* Qb = g_q16 + ((size_t)(b * H_ + h) * S_ + q0) * D_;
    const __half* Kb = g_k16 + (size_t)(b * KV_ + (h >> 1)) * S_ * D_;
    const __half* Vb = g_v16 + (size_t)(b * KV_ + (h >> 1)) * S_ * D_;

#pragma unroll
    for (int i = 0; i < 8; i++) {
        int c = tid + i * 256;
        int r = c >> 4, cs = c & 15;
        cpasync16(smem_u32(sQ + (uint32_t)(r * FSTR + cs * 8)), Qb + (size_t)r * D_ + cs * 8);
    }
    if (tid < 128) {
        int st2 = tid >> 6, r = tid & 63;
        __half* vd = fsh + QTILE_E + st2 * 2 * KTILE_E + KTILE_E;
        *(uint4*)(vd + r * FSTR + 128) = make_uint4(0x00003C00u, 0u, 0u, 0u);
    }
    load_kv_stage(fsh, 0, 0, Kb, Vb, tid);
    CP_COMMIT();

    float o[16][4];
#pragma unroll
    for (int i = 0; i < 16; i++)
#pragma unroll
        for (int j = 0; j < 4; j++) o[i][j] = 0.f;
    float ls[4] = {0.f, 0.f, 0.f, 0.f};
    float mrow[2] = {MASKV, MASKV};

    const int r0 = l >> 2;
    const int a_row = (l & 15);
    const int a_kof = (l >> 4) * 8;
    const int b_row = (l & 7) + ((l >> 4) & 1) * 8;
    const int b_kof = ((l >> 3) & 1) * 8;
    const int v_row = (l & 15);
    const int v_cof = (l >> 4) * 8;
    const int wrow_lo = q0 + 16 * w;
    const int ntiles = 2 * qt + 2;

    for (int t = 0; t < ntiles; t++) {
        const int k0 = t * 64;
        const int st = t & 1;
        if (t + 1 < ntiles) {
            load_kv_stage(fsh, st ^ 1, (t + 1) * 64, Kb, Vb, tid);
            CP_COMMIT();
            CP_WAIT1();
        } else {
            CP_WAIT0();
        }
        __syncthreads();

        if (k0 <= wrow_lo + 15) {
            __half* sK = fsh + QTILE_E + st * 2 * KTILE_E;
            __half* sV = sK + KTILE_E;

            float s[8][4];
#pragma unroll
            for (int i = 0; i < 8; i++)
#pragma unroll
                for (int j = 0; j < 4; j++) s[i][j] = 0.f;

#pragma unroll
            for (int ks = 0; ks < 8; ks++) {
                uint32_t aoff = (uint32_t)((16 * w + a_row) * FSTR + ks * 16 + a_kof) * 2;
                uint32_t qf[4];
                ldmx4(qf, smem_u32(sQ) + aoff);
#pragma unroll
                for (int ng = 0; ng < 4; ng++) {
                    uint32_t boff = (uint32_t)((16 * ng + b_row) * FSTR + ks * 16 + b_kof) * 2;
                    uint32_t kf[4];
                    ldmx4(kf, smem_u32(sK) + boff);
                    mma16816h(s[2*ng],   qf, &kf[0]);
                    mma16816h(s[2*ng+1], qf, &kf[2]);
                }
            }

            if (k0 + 63 > wrow_lo) {
                int grow0 = wrow_lo + r0;
                int grow1 = grow0 + 8;
#pragma unroll
                for (int nt = 0; nt < 8; nt++) {
                    int col = k0 + nt * 8 + (l & 3) * 2;
                    if (col > grow0)     s[nt][0] = MASKV;
                    if (col + 1 > grow0) s[nt][1] = MASKV;
                    if (col > grow1)     s[nt][2] = MASKV;
                    if (col + 1 > grow1) s[nt][3] = MASKV;
                }
            }

            float rm0 = MASKV, rm1 = MASKV;
#pragma unroll
            for (int nt = 0; nt < 8; nt++) {
                rm0 = fmaxf(rm0, fmaxf(s[nt][0], s[nt][1]));
                rm1 = fmaxf(rm1, fmaxf(s[nt][2], s[nt][3]));
            }
            rm0 = fmaxf(rm0, __shfl_xor_sync(0xffffffffu, rm0, 1));
            rm0 = fmaxf(rm0, __shfl_xor_sync(0xffffffffu, rm0, 2));
            rm1 = fmaxf(rm1, __shfl_xor_sync(0xffffffffu, rm1, 1));
            rm1 = fmaxf(rm1, __shfl_xor_sync(0xffffffffu, rm1, 2));

            float mn0 = fmaxf(mrow[0], rm0);
            float mn1 = fmaxf(mrow[1], rm1);
            float alpha0 = __expf(mrow[0] - mn0);
            float alpha1 = __expf(mrow[1] - mn1);
            mrow[0] = mn0; mrow[1] = mn1;

#pragma unroll
            for (int nt = 0; nt < 16; nt++) {
                o[nt][0] *= alpha0; o[nt][1] *= alpha0;
                o[nt][2] *= alpha1; o[nt][3] *= alpha1;
            }
            ls[0] *= alpha0; ls[2] *= alpha1;

            float mnL0 = mn0 * L2E, mnL1 = mn1 * L2E;
#pragma unroll
            for (int ks = 0; ks < 4; ks++) {
                uint32_t pa[4];
                pa[0] = h2exp2_(packh(fmaf(s[2*ks][0],   L2E, -mnL0),
                                      fmaf(s[2*ks][1],   L2E, -mnL0)));
                pa[1] = h2exp2_(packh(fmaf(s[2*ks][2],   L2E, -mnL1),
                                      fmaf(s[2*ks][3],   L2E, -mnL1)));
                pa[2] = h2exp2_(packh(fmaf(s[2*ks+1][0], L2E, -mnL0),
                                      fmaf(s[2*ks+1][1], L2E, -mnL0)));
                pa[3] = h2exp2_(packh(fmaf(s[2*ks+1][2], L2E, -mnL1),
                                      fmaf(s[2*ks+1][3], L2E, -mnL1)));
                uint32_t vs2[2];
                ldmx2t(vs2, smem_u32(sV) + (uint32_t)((ks * 16 + v_row) * FSTR + 128) * 2);
                mma16816h(ls, pa, vs2);
#pragma unroll
                for (int dg = 0; dg < 8; dg++) {
                    uint32_t voff = (uint32_t)((ks * 16 + v_row) * FSTR + dg * 16 + v_cof) * 2;
                    uint32_t vf[4];
                    ldmx4t(vf, smem_u32(sV) + voff);
                    mma16816h(o[2*dg],   pa, &vf[0]);
                    mma16816h(o[2*dg+1], pa, &vf[2]);
                }
            }
        }
        __syncthreads();
    }

    float lr0 = __shfl_sync(0xffffffffu, ls[0], l & 28);
    float lr1 = __shfl_sync(0xffffffffu, ls[2], l & 28);
    float inv0 = 1.f / lr0;
    float inv1 = 1.f / lr1;
    size_t row0 = (size_t)b * S_ + q0 + 16 * w + r0;
    size_t row1 = row0 + 8;
    int colb = h * D_ + (l & 3) * 2;
#pragma unroll
    for (int nt = 0; nt < 16; nt++) {
        int col = colb + nt * 8;
        *(uint32_t*)(O16 + row0 * (H_*D_) + col) = packh(o[nt][0] * inv0, o[nt][1] * inv0);
        *(uint32_t*)(O16 + row1 * (H_*D_) + col) = packh(o[nt][2] * inv1, o[nt][3] * inv1);
    }
}

// ---------------- launcher ---------------------------------------------------
extern "C" void kernel_launch(void* const* d_in, const int* in_sizes, int n_in,
                              void* d_out, int out_size)
{
    const float* hidden   = (const float*)d_in[0];
    const float* cosb     = (const float*)d_in[1];
    const float* sinb     = (const float*)d_in[2];
    const float* q_w      = (const float*)d_in[3];
    const float* k_w      = (const float*)d_in[4];
    const float* v_w      = (const float*)d_in[5];
    const float* o_w      = (const float*)d_in[6];
    const float* q_norm_w = (const float*)d_in[7];
    const float* k_norm_w = (const float*)d_in[8];
    float* out = (float*)d_out;

    __half *hid16, *w16, *ow16, *at16;
    cudaGetSymbolAddress((void**)&hid16, g_hid16);
    cudaGetSymbolAddress((void**)&w16,   g_w16);
    cudaGetSymbolAddress((void**)&ow16,  g_ow16);
    cudaGetSymbolAddress((void**)&at16,  g_at16);

    cudaFuncSetAttribute(gemm_qkv, cudaFuncAttributeMaxDynamicSharedMemorySize, GEMM_SMEMQ);
    cudaFuncSetAttribute(gemm_ff,  cudaFuncAttributeMaxDynamicSharedMemorySize, GEMM_SMEM2);
    cudaFuncSetAttribute(flash_mma, cudaFuncAttributeMaxDynamicSharedMemorySize, FLASH_SMEM);

    // 1) merged prep: all fp32 -> fp16 converts (one launch)
    prep_kernel<<<(PREP4 + 255) / 256, 256>>>(hidden, q_w, k_w, v_w, o_w,
                                              hid16, w16, ow16);

    // 2) fused QKV projection (1-mma) + RMSNorm + mrope -> fp16 Q/K/V
    gemm_qkv<<<dim3(NQKV/128, MTOK/128), 256, GEMM_SMEMQ>>>(
        hid16, w16, cosb, sinb, q_norm_w, k_norm_w);

    // 3) flash attention
    flash_mma<<<dim3(S_ / 128, H_, B_), 256, FLASH_SMEM>>>(at16);

    // 4) O-projection -> d_out
    gemm_ff<<<dim3(HID_/128, MTOK/128), 256, GEMM_SMEM2>>>(at16, ow16, out, HID_, H_*D_);
}